// round 3
// baseline (speedup 1.0000x reference)
#include <cuda_runtime.h>
#include <cstdint>
#include <math.h>

// ---------------- problem constants ----------------
#define Bn    8
#define Cn    512
#define Hn    64
#define Wn    64
#define HWn   4096          // 64*64
#define NTOK  32768         // 4096*8 tokens
#define NKV   2048          // 256*8
#define C1n   358
#define C2n   154

// ---------------- scratch (static device, no allocs) ----------------
__device__ float  g_qh_in[NTOK * Cn];
__device__ float  g_kv_in[NKV * Cn];
__device__ float  g_xv_in[NTOK * Cn];
__device__ float  g_qh   [NTOK * Cn];
__device__ float  g_kvh  [NKV * 2 * Cn];
__device__ float  g_qkvv [(size_t)NTOK * 3 * Cn];
__device__ float  g_oh   [NTOK * Cn];
__device__ float  g_ov   [NTOK * Cn];
__device__ float  g_ha   [(size_t)NTOK * C1n];
__device__ float  g_va   [(size_t)NTOK * C2n];
__device__ double g_stats[16];
__device__ float  g_mu[8];
__device__ float  g_rstd[8];

// ---------------- transpose x(b,c,h,w) -> token rows [row, C] ----------------
__global__ void transpose_kernel(const float* __restrict__ x,
                                 float* __restrict__ out, int mode)
{
    __shared__ float tile[32][33];
    int bb = blockIdx.z;
    int l0 = blockIdx.x * 32, c0 = blockIdx.y * 32;
    int tx = threadIdx.x, ty = threadIdx.y;   // (32, 8)
#pragma unroll
    for (int j = 0; j < 4; j++) {
        int c = c0 + ty + j * 8;
        tile[ty + j * 8][tx] = x[((size_t)(bb * Cn + c)) * HWn + l0 + tx];
    }
    __syncthreads();
#pragma unroll
    for (int j = 0; j < 4; j++) {
        int l = l0 + ty + j * 8;
        int row;
        if (mode == 0) {
            row = l * Bn + bb;
        } else {
            int xx = l & 63, y = l >> 6;
            int wd = xx & 3, nwi = xx >> 2;
            row = y * 512 + wd * 128 + bb * 16 + nwi;
        }
        out[(size_t)row * Cn + c0 + tx] = tile[tx][ty + j * 8];
    }
}

// ---------------- 4x4 avg pool -> kv token rows [lk*8+b, C] ----------------
__global__ void pool_kernel(const float* __restrict__ x, float* __restrict__ out)
{
    int idx = blockIdx.x * 256 + threadIdx.x;
    if (idx >= Bn * Cn * 256) return;
    int px = idx & 15, py = (idx >> 4) & 15, c = (idx >> 8) & 511, bb = idx >> 17;
    const float* base = x + (((size_t)(bb * Cn + c)) * Hn + py * 4) * Wn + px * 4;
    float s = 0.f;
#pragma unroll
    for (int i = 0; i < 4; i++)
#pragma unroll
        for (int j = 0; j < 4; j++) s += base[i * Wn + j];
    out[((size_t)((py * 16 + px) * Bn + bb)) * Cn + c] = s * 0.0625f;
}

// ---------------- tf32 helpers ----------------
__device__ __forceinline__ unsigned f2tf(float f) {
    unsigned r;
    asm("cvt.rna.tf32.f32 %0, %1;" : "=r"(r) : "f"(f));
    return r;
}

__device__ __forceinline__ void mma_tf32(float acc[4], const unsigned a[4], const unsigned b[2]) {
    asm volatile(
        "mma.sync.aligned.m16n8k8.row.col.f32.tf32.tf32.f32 "
        "{%0,%1,%2,%3}, {%4,%5,%6,%7}, {%8,%9}, {%0,%1,%2,%3};\n"
        : "+f"(acc[0]), "+f"(acc[1]), "+f"(acc[2]), "+f"(acc[3])
        : "r"(a[0]), "r"(a[1]), "r"(a[2]), "r"(a[3]), "r"(b[0]), "r"(b[1]));
}

// ---------------- tf32 tensor-core GEMM:  C[orow(m), n] = A[m,:]·B[n,:] + bias[n] ----
// A row-major [M,K], B row-major [N,K]. M % 128 == 0, K % 32 == 0.
// CTA tile 128x64, 8 warps in 4(m) x 2(n), warp tile 32x32, K-chunk 32.
// Smem k-layout permuted within 8-groups: phys = (k%4)*2 + k/4, so the mma
// fragment pair (t, t+4) is one LDS.64. Register-prefetch double buffering.
__global__ __launch_bounds__(256) void sgemm_tf32(
    const float* __restrict__ A, const float* __restrict__ Bm,
    const float* __restrict__ bias, float* __restrict__ Cc,
    int M, int N, int K, int ldc, int mode)
{
    __shared__ unsigned As[128][36];   // [m][k_phys], pad 4
    __shared__ unsigned Bs[64][36];    // [n][k_phys]

    int tid  = threadIdx.x;
    int warp = tid >> 5, lane = tid & 31;
    int wm = warp & 3, wn = warp >> 2;        // 4 x 2 warps
    int g = lane >> 2, t = lane & 3;
    int m0 = blockIdx.y * 128, n0 = blockIdx.x * 64;

    float acc[2][4][4];
#pragma unroll
    for (int mi = 0; mi < 2; mi++)
#pragma unroll
        for (int ni = 0; ni < 4; ni++)
#pragma unroll
            for (int j = 0; j < 4; j++) acc[mi][ni][j] = 0.f;

    int arow = tid >> 3;             // 0..31
    int ac   = (tid & 7) * 4;        // float4 col base within 32
    int agrp = ac & ~7;
    int asub = (ac & 4) ? 1 : 0;
    int brow = tid >> 2;             // 0..63
    int bc0  = (tid & 3) * 4;        // two float4s at bc0 and bc0+16

    float4 pa[4], pb[2];
    // prefetch first K-tile
#pragma unroll
    for (int i = 0; i < 4; i++)
        pa[i] = *(const float4*)(A + (size_t)(m0 + arow + i * 32) * K + ac);
#pragma unroll
    for (int i = 0; i < 2; i++) {
        pb[i] = make_float4(0.f, 0.f, 0.f, 0.f);
        if (n0 + brow < N)
            pb[i] = *(const float4*)(Bm + (size_t)(n0 + brow) * K + bc0 + i * 16);
    }

    for (int k0 = 0; k0 < K; k0 += 32) {
        // store staged registers -> smem (tf32, permuted columns)
#pragma unroll
        for (int i = 0; i < 4; i++) {
            int r = arow + i * 32;
            As[r][agrp + asub + 0] = f2tf(pa[i].x);
            As[r][agrp + asub + 2] = f2tf(pa[i].y);
            As[r][agrp + asub + 4] = f2tf(pa[i].z);
            As[r][agrp + asub + 6] = f2tf(pa[i].w);
        }
#pragma unroll
        for (int i = 0; i < 2; i++) {
            int c = bc0 + i * 16;
            int grp = c & ~7, sub = (c & 4) ? 1 : 0;
            Bs[brow][grp + sub + 0] = f2tf(pb[i].x);
            Bs[brow][grp + sub + 2] = f2tf(pb[i].y);
            Bs[brow][grp + sub + 4] = f2tf(pb[i].z);
            Bs[brow][grp + sub + 6] = f2tf(pb[i].w);
        }
        __syncthreads();

        // prefetch next K-tile while computing this one
        if (k0 + 32 < K) {
#pragma unroll
            for (int i = 0; i < 4; i++)
                pa[i] = *(const float4*)(A + (size_t)(m0 + arow + i * 32) * K + k0 + 32 + ac);
#pragma unroll
            for (int i = 0; i < 2; i++) {
                pb[i] = make_float4(0.f, 0.f, 0.f, 0.f);
                if (n0 + brow < N)
                    pb[i] = *(const float4*)(Bm + (size_t)(n0 + brow) * K + k0 + 32 + bc0 + i * 16);
            }
        }

#pragma unroll
        for (int kk = 0; kk < 32; kk += 8) {
            unsigned af[2][4], bf[4][2];
#pragma unroll
            for (int mi = 0; mi < 2; mi++) {
                int rm = wm * 32 + mi * 16 + g;
                uint2 lo = *(const uint2*)&As[rm    ][kk + 2 * t];
                uint2 hi = *(const uint2*)&As[rm + 8][kk + 2 * t];
                af[mi][0] = lo.x; af[mi][2] = lo.y;
                af[mi][1] = hi.x; af[mi][3] = hi.y;
            }
#pragma unroll
            for (int ni = 0; ni < 4; ni++) {
                int rn = wn * 32 + ni * 8 + g;
                uint2 bv = *(const uint2*)&Bs[rn][kk + 2 * t];
                bf[ni][0] = bv.x; bf[ni][1] = bv.y;
            }
#pragma unroll
            for (int mi = 0; mi < 2; mi++)
#pragma unroll
                for (int ni = 0; ni < 4; ni++)
                    mma_tf32(acc[mi][ni], af[mi], bf[ni]);
        }
        __syncthreads();
    }

    // epilogue: C row = g (+8), col = ni*8 + 2t + {0,1}
#pragma unroll
    for (int mi = 0; mi < 2; mi++) {
#pragma unroll
        for (int half = 0; half < 2; half++) {
            int m = m0 + wm * 32 + mi * 16 + g + half * 8;
            int orow;
            if (mode == 0) {
                orow = m;
            } else {
                int nwi = m & 15, bb = (m >> 4) & 7, wd = (m >> 7) & 3, y = m >> 9;
                orow = ((y << 6) + (nwi << 2) + wd) * Bn + bb;
            }
            float* cr = Cc + (size_t)orow * ldc;
#pragma unroll
            for (int ni = 0; ni < 4; ni++) {
                int n = n0 + wn * 32 + ni * 8 + t * 2;
                if (n < N) {
                    cr[n]     = acc[mi][ni][half * 2 + 0] + bias[n];
                    cr[n + 1] = acc[mi][ni][half * 2 + 1] + bias[n + 1];
                }
            }
        }
    }
}

// ---------------- attention: split-D, 2 threads per query, K/V in smem -------
// 512 threads = 256 queries/block. thread pair (2i, 2i+1) lane-adjacent:
// each owns 32 of the 64 head dims; shfl_xor(1) combines the dot product.
__global__ __launch_bounds__(512, 1) void attn_kernel(
    const float* __restrict__ qb, const float* __restrict__ kb,
    const float* __restrict__ vb, float* __restrict__ ob,
    int Lq, int Lk, int Bt, int qld, int kld, int oldd)
{
    extern __shared__ float sm[];
    int tid = threadIdx.x;
    int hd = blockIdx.y, bb = blockIdx.z;
    float4* Ks = (float4*)sm;
    float4* Vs = Ks + Lk * 16;
    for (int idx = tid; idx < Lk * 16; idx += 512) {
        int r = idx >> 4, cc = idx & 15;
        Ks[idx] = *(const float4*)(kb + (size_t)(r * Bt + bb) * kld + hd * 64 + cc * 4);
        Vs[idx] = *(const float4*)(vb + (size_t)(r * Bt + bb) * kld + hd * 64 + cc * 4);
    }
    __syncthreads();

    int qi   = blockIdx.x * 256 + (tid >> 1);
    int half = tid & 1;
    if (qi >= Lq) return;
    const float* qrow = qb + (size_t)(qi * Bt + bb) * qld + hd * 64 + half * 32;
    float4 q4[8], acc[8];
#pragma unroll
    for (int i = 0; i < 8; i++) {
        q4[i]  = ((const float4*)qrow)[i];
        acc[i] = make_float4(0.f, 0.f, 0.f, 0.f);
    }
    float mmax = -1e30f, lsum = 0.f;
    for (int k = 0; k < Lk; k++) {
        const float4* kr = Ks + k * 16 + half * 8;
        float s = 0.f;
#pragma unroll
        for (int i = 0; i < 8; i++) {
            float4 kv = kr[i];
            s += q4[i].x * kv.x + q4[i].y * kv.y + q4[i].z * kv.z + q4[i].w * kv.w;
        }
        s += __shfl_xor_sync(0xffffffffu, s, 1);   // combine the two halves
        s *= 0.125f;                               // 1/sqrt(64)
        float p;
        if (s > mmax) {
            float corr = __expf(mmax - s);
            mmax = s;
            lsum *= corr;
#pragma unroll
            for (int i = 0; i < 8; i++) {
                acc[i].x *= corr; acc[i].y *= corr; acc[i].z *= corr; acc[i].w *= corr;
            }
            p = 1.f;
        } else {
            p = __expf(s - mmax);
        }
        lsum += p;
        const float4* vr = Vs + k * 16 + half * 8;
#pragma unroll
        for (int i = 0; i < 8; i++) {
            float4 vv = vr[i];
            acc[i].x += p * vv.x; acc[i].y += p * vv.y;
            acc[i].z += p * vv.z; acc[i].w += p * vv.w;
        }
    }
    float inv = 1.f / lsum;
    float* orw = ob + (size_t)(qi * Bt + bb) * oldd + hd * 64 + half * 32;
#pragma unroll
    for (int i = 0; i < 8; i++) {
        float4 o = acc[i];
        o.x *= inv; o.y *= inv; o.z *= inv; o.w *= inv;
        ((float4*)orw)[i] = o;
    }
}

// ---------------- stats / concat / normalize ----------------
__global__ void zero_stats_kernel()
{
    if (threadIdx.x < 16) g_stats[threadIdx.x] = 0.0;
}

__global__ void concat_stats_kernel(const float* __restrict__ x, float* __restrict__ attn_out)
{
    __shared__ float tile[32][33];
    int bb = blockIdx.z;
    int l0 = blockIdx.x * 32, c0 = blockIdx.y * 32;
    int tx = threadIdx.x, ty = threadIdx.y;   // (32, 8)
#pragma unroll
    for (int j = 0; j < 4; j++) {
        int c = c0 + tx;
        int l = l0 + ty + j * 8;
        int row = l * Bn + bb;
        float v = (c < C1n) ? g_ha[(size_t)row * C1n + c]
                            : g_va[(size_t)row * C2n + (c - C1n)];
        tile[ty + j * 8][tx] = v;
    }
    __syncthreads();
    float lsum = 0.f, lsq = 0.f;
#pragma unroll
    for (int j = 0; j < 4; j++) {
        int c = c0 + ty + j * 8;
        int l = l0 + tx;
        float av = tile[tx][ty + j * 8];
        size_t gi = ((size_t)(bb * Cn + c)) * HWn + l;
        attn_out[gi] = av;
        float r = av + x[gi];
        lsum += r; lsq += r * r;
    }
#pragma unroll
    for (int off = 16; off > 0; off >>= 1) {
        lsum += __shfl_xor_sync(0xffffffffu, lsum, off);
        lsq  += __shfl_xor_sync(0xffffffffu, lsq,  off);
    }
    if (tx == 0) {
        atomicAdd(&g_stats[bb * 2 + 0], (double)lsum);
        atomicAdd(&g_stats[bb * 2 + 1], (double)lsq);
    }
}

__global__ void finalize_stats_kernel()
{
    int b = threadIdx.x;
    if (b < 8) {
        const double N = (double)Cn * HWn;
        double mu  = g_stats[2 * b + 0] / N;
        double var = g_stats[2 * b + 1] / N - mu * mu;
        g_mu[b]   = (float)mu;
        g_rstd[b] = (float)(1.0 / sqrt(var + 1e-5));
    }
}

__global__ void norm_kernel(const float* __restrict__ attn,
                            const float* __restrict__ x,
                            float* __restrict__ out)
{
    int i = blockIdx.x * 256 + threadIdx.x;
    int bb = i >> 21;
    float r = attn[i] + x[i];
    out[i] = (r - g_mu[bb]) * g_rstd[bb];
}

// ---------------- host launcher ----------------
extern "C" void kernel_launch(void* const* d_in, const int* in_sizes, int n_in,
                              void* d_out, int out_size)
{
    const float* x       = (const float*)d_in[0];
    const float* h_in_w  = (const float*)d_in[1];
    const float* h_in_b  = (const float*)d_in[2];
    const float* h_out_w = (const float*)d_in[3];
    const float* h_out_b = (const float*)d_in[4];
    const float* v_in_w  = (const float*)d_in[5];
    const float* v_in_b  = (const float*)d_in[6];
    const float* v_out_w = (const float*)d_in[7];
    const float* v_out_b = (const float*)d_in[8];
    const float* hfc_w   = (const float*)d_in[9];
    const float* hfc_b   = (const float*)d_in[10];
    const float* vfc_w   = (const float*)d_in[11];
    const float* vfc_b   = (const float*)d_in[12];

    float* out      = (float*)d_out;
    float* out_res  = out;                                   // result   [b,C,h,w]
    float* out_hax  = out + (size_t)NTOK * Cn;               // ha_x     [h,w,b,c]
    float* out_vax  = out + 2 * (size_t)NTOK * Cn;           // va_x     [h,w,b,c]
    float* out_attn = out + 3 * (size_t)NTOK * Cn;           // attn     [b,C,h,w]

    float *p_qh_in, *p_kv_in, *p_xv_in, *p_qh, *p_kvh, *p_qkvv, *p_oh, *p_ov, *p_ha, *p_va;
    cudaGetSymbolAddress((void**)&p_qh_in, g_qh_in);
    cudaGetSymbolAddress((void**)&p_kv_in, g_kv_in);
    cudaGetSymbolAddress((void**)&p_xv_in, g_xv_in);
    cudaGetSymbolAddress((void**)&p_qh,    g_qh);
    cudaGetSymbolAddress((void**)&p_kvh,   g_kvh);
    cudaGetSymbolAddress((void**)&p_qkvv,  g_qkvv);
    cudaGetSymbolAddress((void**)&p_oh,    g_oh);
    cudaGetSymbolAddress((void**)&p_ov,    g_ov);
    cudaGetSymbolAddress((void**)&p_ha,    g_ha);
    cudaGetSymbolAddress((void**)&p_va,    g_va);

    dim3 tb(32, 8);

    // 1) layout transforms
    transpose_kernel<<<dim3(128, 16, 8), tb>>>(x, p_qh_in, 0);
    transpose_kernel<<<dim3(128, 16, 8), tb>>>(x, p_xv_in, 1);
    pool_kernel<<<(Bn * Cn * 256 + 255) / 256, 256>>>(x, p_kv_in);

    // 2) input projections (tf32 tensor cores)
    sgemm_tf32<<<dim3(8, 256), 256>>>(p_qh_in, h_in_w,           h_in_b,       p_qh,   NTOK, 512,  512, 512,  0);
    sgemm_tf32<<<dim3(16, 16), 256>>>(p_kv_in, h_in_w + 512*512, h_in_b + 512, p_kvh,  NKV,  1024, 512, 1024, 0);
    sgemm_tf32<<<dim3(24, 256), 256>>>(p_xv_in, v_in_w,          v_in_b,       p_qkvv, NTOK, 1536, 512, 1536, 0);

    // 3) attention (split-D, 512 threads, 256 queries/block)
    int smem = 2 * 256 * 64 * (int)sizeof(float);   // 128 KB K+V
    cudaFuncSetAttribute(attn_kernel, cudaFuncAttributeMaxDynamicSharedMemorySize, smem);
    attn_kernel<<<dim3(16, 8, 8),  512, smem>>>(p_qh,   p_kvh,        p_kvh + 512,   p_oh, 4096, 256, 8,   512,  1024, 512);
    attn_kernel<<<dim3(1, 8, 128), 512, smem>>>(p_qkvv, p_qkvv + 512, p_qkvv + 1024, p_ov, 256,  256, 128, 1536, 1536, 512);

    // 4) output projections
    sgemm_tf32<<<dim3(8, 256), 256>>>(p_oh, h_out_w, h_out_b, out_hax, NTOK, 512, 512, 512, 0);
    sgemm_tf32<<<dim3(8, 256), 256>>>(p_ov, v_out_w, v_out_b, out_vax, NTOK, 512, 512, 512, 1);

    // 5) fc heads
    sgemm_tf32<<<dim3(6, 256), 256>>>(out_hax, hfc_w, hfc_b, p_ha, NTOK, C1n, 512, C1n, 0);
    sgemm_tf32<<<dim3(3, 256), 256>>>(out_vax, vfc_w, vfc_b, p_va, NTOK, C2n, 512, C2n, 0);

    // 6) concat + residual stats + layernorm
    zero_stats_kernel<<<1, 32>>>();
    concat_stats_kernel<<<dim3(128, 16, 8), tb>>>(x, out_attn);
    finalize_stats_kernel<<<1, 32>>>();
    norm_kernel<<<NTOK * Cn / 256, 256>>>(out_attn, x, out_res);
}

// round 5
// speedup vs baseline: 1.3034x; 1.3034x over previous
#include <cuda_runtime.h>
#include <cstdint>
#include <math.h>

// ---------------- problem constants ----------------
#define Bn    8
#define Cn    512
#define Hn    64
#define Wn    64
#define HWn   4096          // 64*64
#define NTOK  32768         // 4096*8 tokens
#define NKV   2048          // 256*8
#define C1n   358
#define C2n   154

// ---------------- scratch (static device, no allocs) ----------------
// buffers holding tf32 bit patterns are declared float; GEMM casts to unsigned.
__device__ float  g_qh_in[NTOK * Cn];           // tf32 bits
__device__ float  g_kv_in[NKV * Cn];            // tf32 bits
__device__ float  g_xv_in[NTOK * Cn];           // tf32 bits
__device__ float  g_qh   [NTOK * Cn];           // fp32
__device__ float  g_kvh  [NKV * 2 * Cn];        // fp32
__device__ float  g_qkvv [(size_t)NTOK * 3 * Cn]; // fp32
__device__ float  g_oh   [NTOK * Cn];           // tf32 bits (attn out -> GEMM)
__device__ float  g_ov   [NTOK * Cn];           // tf32 bits
__device__ float  g_hax_t32[NTOK * Cn];         // tf32 bits (fc-h input)
__device__ float  g_vax_t32[NTOK * Cn];         // tf32 bits (fc-v input)
__device__ float  g_wt  [2359296];              // tf32 bits of all weights
__device__ float  g_ha  [(size_t)NTOK * C1n];
__device__ float  g_va  [(size_t)NTOK * C2n];
__device__ double g_stats[16];
__device__ float  g_mu[8];
__device__ float  g_rstd[8];

// weight offsets inside g_wt
#define W_HIN   0
#define W_VIN   786432
#define W_HOUT  1572864
#define W_VOUT  1835008
#define W_HFC   2097152
#define W_VFC   2280448

// ---------------- tf32 helpers ----------------
__device__ __forceinline__ unsigned f2tf(float f) {
    unsigned r;
    asm("cvt.rna.tf32.f32 %0, %1;" : "=r"(r) : "f"(f));
    return r;
}

__global__ void conv_t32_kernel(const float* __restrict__ in, float* __restrict__ out, int n)
{
    int i = blockIdx.x * 256 + threadIdx.x;
    if (i < n) out[i] = __uint_as_float(f2tf(in[i]));
}

__device__ __forceinline__ void mma_tf32(float acc[4], const unsigned a[4], const unsigned b[2]) {
    asm volatile(
        "mma.sync.aligned.m16n8k8.row.col.f32.tf32.tf32.f32 "
        "{%0,%1,%2,%3}, {%4,%5,%6,%7}, {%8,%9}, {%0,%1,%2,%3};\n"
        : "+f"(acc[0]), "+f"(acc[1]), "+f"(acc[2]), "+f"(acc[3])
        : "r"(a[0]), "r"(a[1]), "r"(a[2]), "r"(a[3]), "r"(b[0]), "r"(b[1]));
}

__device__ __forceinline__ void cp16(unsigned saddr, const void* gptr, bool pred) {
    int sz = pred ? 16 : 0;
    asm volatile("cp.async.cg.shared.global [%0], [%1], 16, %2;\n"
                 :: "r"(saddr), "l"(gptr), "r"(sz));
}

// ---------------- transpose x(b,c,h,w) -> tf32 token rows [row, C] ------------
__global__ void transpose_kernel(const float* __restrict__ x,
                                 float* __restrict__ out, int mode)
{
    __shared__ float tile[32][33];
    int bb = blockIdx.z;
    int l0 = blockIdx.x * 32, c0 = blockIdx.y * 32;
    int tx = threadIdx.x, ty = threadIdx.y;   // (32, 8)
#pragma unroll
    for (int j = 0; j < 4; j++) {
        int c = c0 + ty + j * 8;
        tile[ty + j * 8][tx] = x[((size_t)(bb * Cn + c)) * HWn + l0 + tx];
    }
    __syncthreads();
#pragma unroll
    for (int j = 0; j < 4; j++) {
        int l = l0 + ty + j * 8;
        int row;
        if (mode == 0) {
            row = l * Bn + bb;
        } else {
            int xx = l & 63, y = l >> 6;
            int wd = xx & 3, nwi = xx >> 2;
            row = y * 512 + wd * 128 + bb * 16 + nwi;
        }
        out[(size_t)row * Cn + c0 + tx] = __uint_as_float(f2tf(tile[tx][ty + j * 8]));
    }
}

// ---------------- 4x4 avg pool -> tf32 kv token rows ----------------
__global__ void pool_kernel(const float* __restrict__ x, float* __restrict__ out)
{
    int idx = blockIdx.x * 256 + threadIdx.x;
    if (idx >= Bn * Cn * 256) return;
    int px = idx & 15, py = (idx >> 4) & 15, c = (idx >> 8) & 511, bb = idx >> 17;
    const float* base = x + (((size_t)(bb * Cn + c)) * Hn + py * 4) * Wn + px * 4;
    float s = 0.f;
#pragma unroll
    for (int i = 0; i < 4; i++)
#pragma unroll
        for (int j = 0; j < 4; j++) s += base[i * Wn + j];
    out[((size_t)((py * 16 + px) * Bn + bb)) * Cn + c] = __uint_as_float(f2tf(s * 0.0625f));
}

// ---------------- tf32 tensor-core GEMM, cp.async 2-stage pipeline ------------
// A, Bm hold tf32 bit patterns, row-major [M,K] / [N,K]. M%128==0, K%32==0.
// CTA tile 128x64, 8 warps 4(m) x 2(n), warp tile 32x32, K-chunk 32.
// Optional Ct32: also store tf32 bits of the result (for downstream GEMMs).
__global__ __launch_bounds__(256) void gemm_t32(
    const unsigned* __restrict__ A, const unsigned* __restrict__ Bm,
    const float* __restrict__ bias, float* __restrict__ Cc,
    unsigned* __restrict__ Ct32,
    int M, int N, int K, int ldc, int mode)
{
    extern __shared__ unsigned sm[];
    unsigned* As[2] = { sm,              sm + 128 * 36 };
    unsigned* Bs[2] = { sm + 2*128*36,   sm + 2*128*36 + 64*36 };

    int tid  = threadIdx.x;
    int warp = tid >> 5, lane = tid & 31;
    int wm = warp & 3, wn = warp >> 2;        // 4 x 2 warps
    int g = lane >> 2, t = lane & 3;
    int m0 = blockIdx.y * 128, n0 = blockIdx.x * 64;

    float acc[2][4][4];
#pragma unroll
    for (int mi = 0; mi < 2; mi++)
#pragma unroll
        for (int ni = 0; ni < 4; ni++)
#pragma unroll
            for (int j = 0; j < 4; j++) acc[mi][ni][j] = 0.f;

    int arow = tid >> 3;             // 0..31, rows arow + i*32
    int ac   = (tid & 7) * 4;        // k-col base
    int brow = tid >> 2;             // 0..63
    int bc0  = (tid & 3) * 4;        // k-cols bc0, bc0+16
    bool bpred = (n0 + brow) < N;

    const unsigned* Ab = A  + (size_t)(m0 + arow) * K + ac;
    const unsigned* Bb = Bm + (size_t)(n0 + brow) * K + bc0;

    unsigned sa[2], sb[2];
#pragma unroll
    for (int s = 0; s < 2; s++) {
        sa[s] = (unsigned)__cvta_generic_to_shared(As[s]);
        sb[s] = (unsigned)__cvta_generic_to_shared(Bs[s]);
    }

#define STAGE(s, k0) do {                                                       \
    _Pragma("unroll")                                                           \
    for (int i = 0; i < 4; i++)                                                 \
        cp16(sa[s] + (unsigned)(((arow + i * 32) * 36 + ac) * 4),               \
             Ab + (size_t)i * 32 * K + (k0), true);                             \
    _Pragma("unroll")                                                           \
    for (int i = 0; i < 2; i++)                                                 \
        cp16(sb[s] + (unsigned)((brow * 36 + bc0 + i * 16) * 4),                \
             Bb + (k0) + i * 16, bpred);                                        \
    asm volatile("cp.async.commit_group;\n" ::);                                \
} while (0)

    STAGE(0, 0);
    STAGE(1, 32);

    int s = 0;
    for (int k0 = 0; k0 < K; k0 += 32) {
        // FIX (R4 bug): on the final tile there is NO younger in-flight group,
        // so wait_group 1 would let the tile we're about to read stay in flight.
        if (k0 + 32 < K)
            asm volatile("cp.async.wait_group 1;\n" ::);
        else
            asm volatile("cp.async.wait_group 0;\n" ::);
        __syncthreads();

        const unsigned* as = As[s];
        const unsigned* bs = Bs[s];
#pragma unroll
        for (int kk = 0; kk < 32; kk += 8) {
            unsigned af[2][4], bf[4][2];
#pragma unroll
            for (int mi = 0; mi < 2; mi++) {
                int rm = wm * 32 + mi * 16 + g;
                af[mi][0] = as[rm * 36 + kk + t];
                af[mi][1] = as[(rm + 8) * 36 + kk + t];
                af[mi][2] = as[rm * 36 + kk + t + 4];
                af[mi][3] = as[(rm + 8) * 36 + kk + t + 4];
            }
#pragma unroll
            for (int ni = 0; ni < 4; ni++) {
                int rn = wn * 32 + ni * 8 + g;
                bf[ni][0] = bs[rn * 36 + kk + t];
                bf[ni][1] = bs[rn * 36 + kk + t + 4];
            }
#pragma unroll
            for (int mi = 0; mi < 2; mi++)
#pragma unroll
                for (int ni = 0; ni < 4; ni++)
                    mma_tf32(acc[mi][ni], af[mi], bf[ni]);
        }
        __syncthreads();

        if (k0 + 64 < K) STAGE(s, k0 + 64);
        s ^= 1;
    }
#undef STAGE

    // epilogue: C row = g (+8), col = ni*8 + 2t + {0,1}
#pragma unroll
    for (int mi = 0; mi < 2; mi++) {
#pragma unroll
        for (int half = 0; half < 2; half++) {
            int m = m0 + wm * 32 + mi * 16 + g + half * 8;
            int orow;
            if (mode == 0) {
                orow = m;
            } else {
                int nwi = m & 15, bb = (m >> 4) & 7, wd = (m >> 7) & 3, y = m >> 9;
                orow = ((y << 6) + (nwi << 2) + wd) * Bn + bb;
            }
            float* cr = Cc + (size_t)orow * ldc;
            unsigned* ct = Ct32 ? Ct32 + (size_t)orow * ldc : 0;
#pragma unroll
            for (int ni = 0; ni < 4; ni++) {
                int n = n0 + wn * 32 + ni * 8 + t * 2;
                if (n < N) {
                    float v0 = acc[mi][ni][half * 2 + 0] + bias[n];
                    float v1 = acc[mi][ni][half * 2 + 1] + bias[n + 1];
                    cr[n] = v0; cr[n + 1] = v1;
                    if (ct) { ct[n] = f2tf(v0); ct[n + 1] = f2tf(v1); }
                }
            }
        }
    }
}

// ---------------- attention: one query per thread, K/V in smem (256 thr) ------
// writes tf32 bits (output feeds only the out-projection GEMM)
__global__ __launch_bounds__(256, 1) void attn_kernel(
    const float* __restrict__ qb, const float* __restrict__ kb,
    const float* __restrict__ vb, float* __restrict__ ob,
    int Lq, int Lk, int Bt, int qld, int kld, int oldd)
{
    extern __shared__ float smf[];
    int tid = threadIdx.x;
    int hd = blockIdx.y, bb = blockIdx.z;
    float4* Ks = (float4*)smf;
    float4* Vs = Ks + Lk * 16;
    for (int idx = tid; idx < Lk * 16; idx += 256) {
        int r = idx >> 4, cc = idx & 15;
        Ks[idx] = *(const float4*)(kb + (size_t)(r * Bt + bb) * kld + hd * 64 + cc * 4);
        Vs[idx] = *(const float4*)(vb + (size_t)(r * Bt + bb) * kld + hd * 64 + cc * 4);
    }
    __syncthreads();

    int qi = blockIdx.x * 256 + tid;
    if (qi >= Lq) return;
    const float* qrow = qb + (size_t)(qi * Bt + bb) * qld + hd * 64;
    float4 q4[16], acc[16];
#pragma unroll
    for (int i = 0; i < 16; i++) {
        q4[i]  = ((const float4*)qrow)[i];
        acc[i] = make_float4(0.f, 0.f, 0.f, 0.f);
    }
    float mmax = -1e30f, lsum = 0.f;
    for (int k = 0; k < Lk; k++) {
        const float4* kr = Ks + k * 16;
        float s = 0.f;
#pragma unroll
        for (int i = 0; i < 16; i++) {
            float4 kv = kr[i];
            s += q4[i].x * kv.x + q4[i].y * kv.y + q4[i].z * kv.z + q4[i].w * kv.w;
        }
        s *= 0.125f;   // 1/sqrt(64)
        float p;
        if (s > mmax) {
            float corr = __expf(mmax - s);
            mmax = s;
            lsum *= corr;
#pragma unroll
            for (int i = 0; i < 16; i++) {
                acc[i].x *= corr; acc[i].y *= corr; acc[i].z *= corr; acc[i].w *= corr;
            }
            p = 1.f;
        } else {
            p = __expf(s - mmax);
        }
        lsum += p;
        const float4* vr = Vs + k * 16;
#pragma unroll
        for (int i = 0; i < 16; i++) {
            float4 vv = vr[i];
            acc[i].x += p * vv.x; acc[i].y += p * vv.y;
            acc[i].z += p * vv.z; acc[i].w += p * vv.w;
        }
    }
    float inv = 1.f / lsum;
    float* orw = ob + (size_t)(qi * Bt + bb) * oldd + hd * 64;
#pragma unroll
    for (int i = 0; i < 16; i++) {
        float4 o = acc[i];
        o.x = __uint_as_float(f2tf(o.x * inv));
        o.y = __uint_as_float(f2tf(o.y * inv));
        o.z = __uint_as_float(f2tf(o.z * inv));
        o.w = __uint_as_float(f2tf(o.w * inv));
        ((float4*)orw)[i] = o;
    }
}

// ---------------- stats / concat / normalize ----------------
__global__ void zero_stats_kernel()
{
    if (threadIdx.x < 16) g_stats[threadIdx.x] = 0.0;
}

__global__ void concat_stats_kernel(const float* __restrict__ x, float* __restrict__ attn_out)
{
    __shared__ float tile[32][33];
    int bb = blockIdx.z;
    int l0 = blockIdx.x * 32, c0 = blockIdx.y * 32;
    int tx = threadIdx.x, ty = threadIdx.y;   // (32, 8)
#pragma unroll
    for (int j = 0; j < 4; j++) {
        int c = c0 + tx;
        int l = l0 + ty + j * 8;
        int row = l * Bn + bb;
        float v = (c < C1n) ? g_ha[(size_t)row * C1n + c]
                            : g_va[(size_t)row * C2n + (c - C1n)];
        tile[ty + j * 8][tx] = v;
    }
    __syncthreads();
    float lsum = 0.f, lsq = 0.f;
#pragma unroll
    for (int j = 0; j < 4; j++) {
        int c = c0 + ty + j * 8;
        int l = l0 + tx;
        float av = tile[tx][ty + j * 8];
        size_t gi = ((size_t)(bb * Cn + c)) * HWn + l;
        attn_out[gi] = av;
        float r = av + x[gi];
        lsum += r; lsq += r * r;
    }
#pragma unroll
    for (int off = 16; off > 0; off >>= 1) {
        lsum += __shfl_xor_sync(0xffffffffu, lsum, off);
        lsq  += __shfl_xor_sync(0xffffffffu, lsq,  off);
    }
    if (tx == 0) {
        atomicAdd(&g_stats[bb * 2 + 0], (double)lsum);
        atomicAdd(&g_stats[bb * 2 + 1], (double)lsq);
    }
}

__global__ void finalize_stats_kernel()
{
    int b = threadIdx.x;
    if (b < 8) {
        const double N = (double)Cn * HWn;
        double mu  = g_stats[2 * b + 0] / N;
        double var = g_stats[2 * b + 1] / N - mu * mu;
        g_mu[b]   = (float)mu;
        g_rstd[b] = (float)(1.0 / sqrt(var + 1e-5));
    }
}

__global__ void norm_kernel(const float* __restrict__ attn,
                            const float* __restrict__ x,
                            float* __restrict__ out)
{
    int i = blockIdx.x * 256 + threadIdx.x;
    int bb = i >> 21;
    float r = attn[i] + x[i];
    out[i] = (r - g_mu[bb]) * g_rstd[bb];
}

// ---------------- host launcher ----------------
extern "C" void kernel_launch(void* const* d_in, const int* in_sizes, int n_in,
                              void* d_out, int out_size)
{
    const float* x       = (const float*)d_in[0];
    const float* h_in_w  = (const float*)d_in[1];
    const float* h_in_b  = (const float*)d_in[2];
    const float* h_out_w = (const float*)d_in[3];
    const float* h_out_b = (const float*)d_in[4];
    const float* v_in_w  = (const float*)d_in[5];
    const float* v_in_b  = (const float*)d_in[6];
    const float* v_out_w = (const float*)d_in[7];
    const float* v_out_b = (const float*)d_in[8];
    const float* hfc_w   = (const float*)d_in[9];
    const float* hfc_b   = (const float*)d_in[10];
    const float* vfc_w   = (const float*)d_in[11];
    const float* vfc_b   = (const float*)d_in[12];

    float* out      = (float*)d_out;
    float* out_res  = out;                                   // result   [b,C,h,w]
    float* out_hax  = out + (size_t)NTOK * Cn;               // ha_x     [h,w,b,c]
    float* out_vax  = out + 2 * (size_t)NTOK * Cn;           // va_x     [h,w,b,c]
    float* out_attn = out + 3 * (size_t)NTOK * Cn;           // attn     [b,C,h,w]

    float *p_qh_in, *p_kv_in, *p_xv_in, *p_qh, *p_kvh, *p_qkvv, *p_oh, *p_ov;
    float *p_hax32, *p_vax32, *p_wt, *p_ha, *p_va;
    cudaGetSymbolAddress((void**)&p_qh_in, g_qh_in);
    cudaGetSymbolAddress((void**)&p_kv_in, g_kv_in);
    cudaGetSymbolAddress((void**)&p_xv_in, g_xv_in);
    cudaGetSymbolAddress((void**)&p_qh,    g_qh);
    cudaGetSymbolAddress((void**)&p_kvh,   g_kvh);
    cudaGetSymbolAddress((void**)&p_qkvv,  g_qkvv);
    cudaGetSymbolAddress((void**)&p_oh,    g_oh);
    cudaGetSymbolAddress((void**)&p_ov,    g_ov);
    cudaGetSymbolAddress((void**)&p_hax32, g_hax_t32);
    cudaGetSymbolAddress((void**)&p_vax32, g_vax_t32);
    cudaGetSymbolAddress((void**)&p_wt,    g_wt);
    cudaGetSymbolAddress((void**)&p_ha,    g_ha);
    cudaGetSymbolAddress((void**)&p_va,    g_va);

    dim3 tb(32, 8);
    const int GSMEM = (2 * 128 * 36 + 2 * 64 * 36) * 4;   // 55296 B
    cudaFuncSetAttribute(gemm_t32, cudaFuncAttributeMaxDynamicSharedMemorySize, GSMEM);
    int asmem = 2 * 256 * 64 * (int)sizeof(float);        // 128 KB K+V
    cudaFuncSetAttribute(attn_kernel, cudaFuncAttributeMaxDynamicSharedMemorySize, asmem);

    // 0) weight conversion to tf32 bits
    conv_t32_kernel<<<(786432 + 255) / 256, 256>>>(h_in_w,  p_wt + W_HIN,  786432);
    conv_t32_kernel<<<(786432 + 255) / 256, 256>>>(v_in_w,  p_wt + W_VIN,  786432);
    conv_t32_kernel<<<(262144 + 255) / 256, 256>>>(h_out_w, p_wt + W_HOUT, 262144);
    conv_t32_kernel<<<(262144 + 255) / 256, 256>>>(v_out_w, p_wt + W_VOUT, 262144);
    conv_t32_kernel<<<(183296 + 255) / 256, 256>>>(hfc_w,   p_wt + W_HFC,  183296);
    conv_t32_kernel<<<(78848  + 255) / 256, 256>>>(vfc_w,   p_wt + W_VFC,  78848);

    // 1) layout transforms (emit tf32 bits)
    transpose_kernel<<<dim3(128, 16, 8), tb>>>(x, p_qh_in, 0);
    transpose_kernel<<<dim3(128, 16, 8), tb>>>(x, p_xv_in, 1);
    pool_kernel<<<(Bn * Cn * 256 + 255) / 256, 256>>>(x, p_kv_in);

    // 2) input projections
    gemm_t32<<<dim3(8, 256), 256, GSMEM>>>((unsigned*)p_qh_in, (unsigned*)(p_wt + W_HIN),
        h_in_b, p_qh, 0, NTOK, 512, 512, 512, 0);
    gemm_t32<<<dim3(16, 16), 256, GSMEM>>>((unsigned*)p_kv_in, (unsigned*)(p_wt + W_HIN + 512 * 512),
        h_in_b + 512, p_kvh, 0, NKV, 1024, 512, 1024, 0);
    gemm_t32<<<dim3(24, 256), 256, GSMEM>>>((unsigned*)p_xv_in, (unsigned*)(p_wt + W_VIN),
        v_in_b, p_qkvv, 0, NTOK, 1536, 512, 1536, 0);

    // 3) attention (outputs tf32 bits)
    attn_kernel<<<dim3(16, 8, 8),  256, asmem>>>(p_qh,   p_kvh,        p_kvh + 512,   p_oh, 4096, 256, 8,   512,  1024, 512);
    attn_kernel<<<dim3(1, 8, 128), 256, asmem>>>(p_qkvv, p_qkvv + 512, p_qkvv + 1024, p_ov, 256,  256, 128, 1536, 1536, 512);

    // 4) output projections: fp32 to d_out + tf32 copy for fc heads
    gemm_t32<<<dim3(8, 256), 256, GSMEM>>>((unsigned*)p_oh, (unsigned*)(p_wt + W_HOUT),
        h_out_b, out_hax, (unsigned*)p_hax32, NTOK, 512, 512, 512, 0);
    gemm_t32<<<dim3(8, 256), 256, GSMEM>>>((unsigned*)p_ov, (unsigned*)(p_wt + W_VOUT),
        v_out_b, out_vax, (unsigned*)p_vax32, NTOK, 512, 512, 512, 1);

    // 5) fc heads
    gemm_t32<<<dim3(6, 256), 256, GSMEM>>>((unsigned*)p_hax32, (unsigned*)(p_wt + W_HFC),
        hfc_b, p_ha, 0, NTOK, C1n, 512, C1n, 0);
    gemm_t32<<<dim3(3, 256), 256, GSMEM>>>((unsigned*)p_vax32, (unsigned*)(p_wt + W_VFC),
        vfc_b, p_va, 0, NTOK, C2n, 512, C2n, 0);

    // 6) concat + residual stats + layernorm
    zero_stats_kernel<<<1, 32>>>();
    concat_stats_kernel<<<dim3(128, 16, 8), tb>>>(x, out_attn);
    finalize_stats_kernel<<<1, 32>>>();
    norm_kernel<<<NTOK * Cn / 256, 256>>>(out_attn, x, out_res);
}

// round 6
// speedup vs baseline: 1.7431x; 1.3373x over previous
#include <cuda_runtime.h>
#include <cstdint>
#include <math.h>

// ---------------- problem constants ----------------
#define Bn    8
#define Cn    512
#define Hn    64
#define Wn    64
#define HWn   4096          // 64*64
#define NTOK  32768         // 4096*8 tokens
#define NKV   2048          // 256*8
#define C1n   358
#define C2n   154

// ---------------- scratch (static device, no allocs) ----------------
__device__ float  g_qh_in[NTOK * Cn];           // tf32 bits
__device__ float  g_kv_in[NKV * Cn];            // tf32 bits
__device__ float  g_xv_in[NTOK * Cn];           // tf32 bits
__device__ float  g_qh   [NTOK * Cn];           // fp32
__device__ float  g_kvh  [NKV * 2 * Cn];        // fp32
__device__ float  g_qkvv [(size_t)NTOK * 3 * Cn]; // fp32
__device__ float  g_oh   [NTOK * Cn];           // tf32 bits (attn out -> GEMM)
__device__ float  g_ov   [NTOK * Cn];           // tf32 bits
__device__ float  g_hax_t32[NTOK * Cn];         // tf32 bits (fc-h input)
__device__ float  g_vax_t32[NTOK * Cn];         // tf32 bits (fc-v input)
__device__ float  g_wt  [2359296];              // tf32 bits of all weights
__device__ float  g_ha  [(size_t)NTOK * C1n];
__device__ float  g_va  [(size_t)NTOK * C2n];
__device__ double g_stats[16];
__device__ float  g_mu[8];
__device__ float  g_rstd[8];

// weight offsets inside g_wt
#define W_HIN   0
#define W_VIN   786432
#define W_HOUT  1572864
#define W_VOUT  1835008
#define W_HFC   2097152
#define W_VFC   2280448

// ---------------- tf32 helpers ----------------
__device__ __forceinline__ unsigned f2tf(float f) {
    unsigned r;
    asm("cvt.rna.tf32.f32 %0, %1;" : "=r"(r) : "f"(f));
    return r;
}

__global__ void conv_t32_kernel(const float* __restrict__ in, float* __restrict__ out, int n)
{
    int i = blockIdx.x * 256 + threadIdx.x;
    if (i < n) out[i] = __uint_as_float(f2tf(in[i]));
}

__device__ __forceinline__ void mma_tf32(float acc[4], const unsigned a[4], const unsigned b[2]) {
    asm volatile(
        "mma.sync.aligned.m16n8k8.row.col.f32.tf32.tf32.f32 "
        "{%0,%1,%2,%3}, {%4,%5,%6,%7}, {%8,%9}, {%0,%1,%2,%3};\n"
        : "+f"(acc[0]), "+f"(acc[1]), "+f"(acc[2]), "+f"(acc[3])
        : "r"(a[0]), "r"(a[1]), "r"(a[2]), "r"(a[3]), "r"(b[0]), "r"(b[1]));
}

__device__ __forceinline__ void cp16(unsigned saddr, const void* gptr, bool pred) {
    int sz = pred ? 16 : 0;
    asm volatile("cp.async.cg.shared.global [%0], [%1], 16, %2;\n"
                 :: "r"(saddr), "l"(gptr), "r"(sz));
}

// ---------------- transpose x(b,c,h,w) -> tf32 token rows [row, C] ------------
__global__ void transpose_kernel(const float* __restrict__ x,
                                 float* __restrict__ out, int mode)
{
    __shared__ float tile[32][33];
    int bb = blockIdx.z;
    int l0 = blockIdx.x * 32, c0 = blockIdx.y * 32;
    int tx = threadIdx.x, ty = threadIdx.y;   // (32, 8)
#pragma unroll
    for (int j = 0; j < 4; j++) {
        int c = c0 + ty + j * 8;
        tile[ty + j * 8][tx] = x[((size_t)(bb * Cn + c)) * HWn + l0 + tx];
    }
    __syncthreads();
#pragma unroll
    for (int j = 0; j < 4; j++) {
        int l = l0 + ty + j * 8;
        int row;
        if (mode == 0) {
            row = l * Bn + bb;
        } else {
            int xx = l & 63, y = l >> 6;
            int wd = xx & 3, nwi = xx >> 2;
            row = y * 512 + wd * 128 + bb * 16 + nwi;
        }
        out[(size_t)row * Cn + c0 + tx] = __uint_as_float(f2tf(tile[tx][ty + j * 8]));
    }
}

// ---------------- 4x4 avg pool -> tf32 kv token rows ----------------
__global__ void pool_kernel(const float* __restrict__ x, float* __restrict__ out)
{
    int idx = blockIdx.x * 256 + threadIdx.x;
    if (idx >= Bn * Cn * 256) return;
    int px = idx & 15, py = (idx >> 4) & 15, c = (idx >> 8) & 511, bb = idx >> 17;
    const float* base = x + (((size_t)(bb * Cn + c)) * Hn + py * 4) * Wn + px * 4;
    float s = 0.f;
#pragma unroll
    for (int i = 0; i < 4; i++)
#pragma unroll
        for (int j = 0; j < 4; j++) s += base[i * Wn + j];
    out[((size_t)((py * 16 + px) * Bn + bb)) * Cn + c] = __uint_as_float(f2tf(s * 0.0625f));
}

// ---------------- tf32 tensor-core GEMM, cp.async 2-stage pipeline ------------
__global__ __launch_bounds__(256) void gemm_t32(
    const unsigned* __restrict__ A, const unsigned* __restrict__ Bm,
    const float* __restrict__ bias, float* __restrict__ Cc,
    unsigned* __restrict__ Ct32,
    int M, int N, int K, int ldc, int mode)
{
    extern __shared__ unsigned sm[];
    unsigned* As[2] = { sm,              sm + 128 * 36 };
    unsigned* Bs[2] = { sm + 2*128*36,   sm + 2*128*36 + 64*36 };

    int tid  = threadIdx.x;
    int warp = tid >> 5, lane = tid & 31;
    int wm = warp & 3, wn = warp >> 2;        // 4 x 2 warps
    int g = lane >> 2, t = lane & 3;
    int m0 = blockIdx.y * 128, n0 = blockIdx.x * 64;

    float acc[2][4][4];
#pragma unroll
    for (int mi = 0; mi < 2; mi++)
#pragma unroll
        for (int ni = 0; ni < 4; ni++)
#pragma unroll
            for (int j = 0; j < 4; j++) acc[mi][ni][j] = 0.f;

    int arow = tid >> 3;             // 0..31, rows arow + i*32
    int ac   = (tid & 7) * 4;        // k-col base
    int brow = tid >> 2;             // 0..63
    int bc0  = (tid & 3) * 4;        // k-cols bc0, bc0+16
    bool bpred = (n0 + brow) < N;

    const unsigned* Ab = A  + (size_t)(m0 + arow) * K + ac;
    const unsigned* Bb = Bm + (size_t)(n0 + brow) * K + bc0;

    unsigned sa[2], sb[2];
#pragma unroll
    for (int s = 0; s < 2; s++) {
        sa[s] = (unsigned)__cvta_generic_to_shared(As[s]);
        sb[s] = (unsigned)__cvta_generic_to_shared(Bs[s]);
    }

#define STAGE(s, k0) do {                                                       \
    _Pragma("unroll")                                                           \
    for (int i = 0; i < 4; i++)                                                 \
        cp16(sa[s] + (unsigned)(((arow + i * 32) * 36 + ac) * 4),               \
             Ab + (size_t)i * 32 * K + (k0), true);                             \
    _Pragma("unroll")                                                           \
    for (int i = 0; i < 2; i++)                                                 \
        cp16(sb[s] + (unsigned)((brow * 36 + bc0 + i * 16) * 4),                \
             Bb + (k0) + i * 16, bpred);                                        \
    asm volatile("cp.async.commit_group;\n" ::);                                \
} while (0)

    STAGE(0, 0);
    STAGE(1, 32);

    int s = 0;
    for (int k0 = 0; k0 < K; k0 += 32) {
        if (k0 + 32 < K)
            asm volatile("cp.async.wait_group 1;\n" ::);
        else
            asm volatile("cp.async.wait_group 0;\n" ::);
        __syncthreads();

        const unsigned* as = As[s];
        const unsigned* bs = Bs[s];
#pragma unroll
        for (int kk = 0; kk < 32; kk += 8) {
            unsigned af[2][4], bf[4][2];
#pragma unroll
            for (int mi = 0; mi < 2; mi++) {
                int rm = wm * 32 + mi * 16 + g;
                af[mi][0] = as[rm * 36 + kk + t];
                af[mi][1] = as[(rm + 8) * 36 + kk + t];
                af[mi][2] = as[rm * 36 + kk + t + 4];
                af[mi][3] = as[(rm + 8) * 36 + kk + t + 4];
            }
#pragma unroll
            for (int ni = 0; ni < 4; ni++) {
                int rn = wn * 32 + ni * 8 + g;
                bf[ni][0] = bs[rn * 36 + kk + t];
                bf[ni][1] = bs[rn * 36 + kk + t + 4];
            }
#pragma unroll
            for (int mi = 0; mi < 2; mi++)
#pragma unroll
                for (int ni = 0; ni < 4; ni++)
                    mma_tf32(acc[mi][ni], af[mi], bf[ni]);
        }
        __syncthreads();

        if (k0 + 64 < K) STAGE(s, k0 + 64);
        s ^= 1;
    }
#undef STAGE

#pragma unroll
    for (int mi = 0; mi < 2; mi++) {
#pragma unroll
        for (int half = 0; half < 2; half++) {
            int m = m0 + wm * 32 + mi * 16 + g + half * 8;
            int orow;
            if (mode == 0) {
                orow = m;
            } else {
                int nwi = m & 15, bb = (m >> 4) & 7, wd = (m >> 7) & 3, y = m >> 9;
                orow = ((y << 6) + (nwi << 2) + wd) * Bn + bb;
            }
            float* cr = Cc + (size_t)orow * ldc;
            unsigned* ct = Ct32 ? Ct32 + (size_t)orow * ldc : 0;
#pragma unroll
            for (int ni = 0; ni < 4; ni++) {
                int n = n0 + wn * 32 + ni * 8 + t * 2;
                if (n < N) {
                    float v0 = acc[mi][ni][half * 2 + 0] + bias[n];
                    float v1 = acc[mi][ni][half * 2 + 1] + bias[n + 1];
                    cr[n] = v0; cr[n + 1] = v1;
                    if (ct) { ct[n] = f2tf(v0); ct[n + 1] = f2tf(v1); }
                }
            }
        }
    }
}

// ---------------- flash attention on tf32 tensor cores ------------------------
// CTA: 128 queries x one (head, batch). 8 warps, 16 queries/warp.
// K/V: 256 keys staged whole in smem as tf32 bits.
//   Ks [256][68] (key, dim)  -> QK^T B-frag addr pattern (4g+t) mod 32: bijective
//   Vs [256][72] (key, dim)  -> PV   B-frag addr pattern (8t+g) mod 32: bijective
//   Pw per-warp [16][68]     -> PV   A-frag addr pattern (4g+t): bijective
// Output written as tf32 bits (feeds the out-projection GEMM).
#define KS_S 68
#define VS_S 72
#define P_S  68
#define ATT_SMEM ((256 * KS_S + 256 * VS_S + 8 * 16 * P_S) * 4)

__global__ __launch_bounds__(256, 1) void attn_mma(
    const float* __restrict__ qb, const float* __restrict__ kb,
    const float* __restrict__ vb, float* __restrict__ ob,
    int Bt, int qld, int kld, int oldd)
{
    extern __shared__ unsigned smu[];
    unsigned* Ks = smu;                       // [256][68]
    unsigned* Vs = smu + 256 * KS_S;          // [256][72]
    int tid  = threadIdx.x;
    int warp = tid >> 5, lane = tid & 31;
    int g = lane >> 2, t = lane & 3;
    int hd = blockIdx.y, bb = blockIdx.z;
    unsigned* Pw = smu + 256 * KS_S + 256 * VS_S + warp * (16 * P_S);

    // stage K/V (fp32 -> tf32 bits)
    for (int idx = tid; idx < 256 * 16; idx += 256) {
        int r = idx >> 4, c = (idx & 15) * 4;
        size_t base = ((size_t)(r * Bt + bb)) * kld + hd * 64 + c;
        float4 kv = *(const float4*)(kb + base);
        float4 vv = *(const float4*)(vb + base);
        Ks[r * KS_S + c + 0] = f2tf(kv.x); Ks[r * KS_S + c + 1] = f2tf(kv.y);
        Ks[r * KS_S + c + 2] = f2tf(kv.z); Ks[r * KS_S + c + 3] = f2tf(kv.w);
        Vs[r * VS_S + c + 0] = f2tf(vv.x); Vs[r * VS_S + c + 1] = f2tf(vv.y);
        Vs[r * VS_S + c + 2] = f2tf(vv.z); Vs[r * VS_S + c + 3] = f2tf(vv.w);
    }
    __syncthreads();

    int qrow0 = blockIdx.x * 128 + warp * 16 + g;   // rows qrow0 and qrow0+8
    unsigned aq[8][4];
    {
        const float* q0 = qb + ((size_t)(qrow0 * Bt + bb)) * qld + hd * 64;
        const float* q1 = qb + ((size_t)((qrow0 + 8) * Bt + bb)) * qld + hd * 64;
#pragma unroll
        for (int ks = 0; ks < 8; ks++) {
            aq[ks][0] = f2tf(q0[ks * 8 + t]     * 0.125f);
            aq[ks][1] = f2tf(q1[ks * 8 + t]     * 0.125f);
            aq[ks][2] = f2tf(q0[ks * 8 + t + 4] * 0.125f);
            aq[ks][3] = f2tf(q1[ks * 8 + t + 4] * 0.125f);
        }
    }

    float o[8][4];
#pragma unroll
    for (int ni = 0; ni < 8; ni++)
#pragma unroll
        for (int j = 0; j < 4; j++) o[ni][j] = 0.f;
    float m0 = -1e30f, m1 = -1e30f, l0 = 0.f, l1 = 0.f;

    for (int kt = 0; kt < 4; kt++) {           // 4 key tiles of 64
        float sacc[8][4];
#pragma unroll
        for (int ni = 0; ni < 8; ni++)
#pragma unroll
            for (int j = 0; j < 4; j++) sacc[ni][j] = 0.f;

        // S = (Q*scale) K^T
#pragma unroll
        for (int ks = 0; ks < 8; ks++) {
#pragma unroll
            for (int ni = 0; ni < 8; ni++) {
                int krow = kt * 64 + ni * 8 + g;
                unsigned bf[2] = { Ks[krow * KS_S + ks * 8 + t],
                                   Ks[krow * KS_S + ks * 8 + t + 4] };
                mma_tf32(sacc[ni], aq[ks], bf);
            }
        }

        // online softmax (rows g, g+8; quad = lanes sharing g)
        float mx0 = -1e30f, mx1 = -1e30f;
#pragma unroll
        for (int ni = 0; ni < 8; ni++) {
            mx0 = fmaxf(mx0, fmaxf(sacc[ni][0], sacc[ni][1]));
            mx1 = fmaxf(mx1, fmaxf(sacc[ni][2], sacc[ni][3]));
        }
        mx0 = fmaxf(mx0, __shfl_xor_sync(0xffffffffu, mx0, 1));
        mx0 = fmaxf(mx0, __shfl_xor_sync(0xffffffffu, mx0, 2));
        mx1 = fmaxf(mx1, __shfl_xor_sync(0xffffffffu, mx1, 1));
        mx1 = fmaxf(mx1, __shfl_xor_sync(0xffffffffu, mx1, 2));
        float mn0 = fmaxf(m0, mx0), mn1 = fmaxf(m1, mx1);
        float c0 = __expf(m0 - mn0), c1 = __expf(m1 - mn1);
        m0 = mn0; m1 = mn1;

        float rs0 = 0.f, rs1 = 0.f;
#pragma unroll
        for (int ni = 0; ni < 8; ni++) {
            float p00 = __expf(sacc[ni][0] - mn0);
            float p01 = __expf(sacc[ni][1] - mn0);
            float p10 = __expf(sacc[ni][2] - mn1);
            float p11 = __expf(sacc[ni][3] - mn1);
            rs0 += p00 + p01; rs1 += p10 + p11;
            *(uint2*)&Pw[g * P_S + ni * 8 + 2 * t]       = make_uint2(f2tf(p00), f2tf(p01));
            *(uint2*)&Pw[(g + 8) * P_S + ni * 8 + 2 * t] = make_uint2(f2tf(p10), f2tf(p11));
            o[ni][0] *= c0; o[ni][1] *= c0; o[ni][2] *= c1; o[ni][3] *= c1;
        }
        rs0 += __shfl_xor_sync(0xffffffffu, rs0, 1);
        rs0 += __shfl_xor_sync(0xffffffffu, rs0, 2);
        rs1 += __shfl_xor_sync(0xffffffffu, rs1, 1);
        rs1 += __shfl_xor_sync(0xffffffffu, rs1, 2);
        l0 = l0 * c0 + rs0;
        l1 = l1 * c1 + rs1;
        __syncwarp();

        // O += P V
#pragma unroll
        for (int ks = 0; ks < 8; ks++) {
            unsigned ap[4] = { Pw[g * P_S + ks * 8 + t],
                               Pw[(g + 8) * P_S + ks * 8 + t],
                               Pw[g * P_S + ks * 8 + t + 4],
                               Pw[(g + 8) * P_S + ks * 8 + t + 4] };
            int vr0 = (kt * 64 + ks * 8 + t) * VS_S;
            int vr1 = (kt * 64 + ks * 8 + t + 4) * VS_S;
#pragma unroll
            for (int ni = 0; ni < 8; ni++) {
                unsigned bf[2] = { Vs[vr0 + ni * 8 + g], Vs[vr1 + ni * 8 + g] };
                mma_tf32(o[ni], ap, bf);
            }
        }
        __syncwarp();
    }

    float i0 = 1.f / l0, i1 = 1.f / l1;
    float* o0 = ob + ((size_t)(qrow0 * Bt + bb)) * oldd + hd * 64;
    float* o1 = ob + ((size_t)((qrow0 + 8) * Bt + bb)) * oldd + hd * 64;
#pragma unroll
    for (int ni = 0; ni < 8; ni++) {
        o0[ni * 8 + 2 * t]     = __uint_as_float(f2tf(o[ni][0] * i0));
        o0[ni * 8 + 2 * t + 1] = __uint_as_float(f2tf(o[ni][1] * i0));
        o1[ni * 8 + 2 * t]     = __uint_as_float(f2tf(o[ni][2] * i1));
        o1[ni * 8 + 2 * t + 1] = __uint_as_float(f2tf(o[ni][3] * i1));
    }
}

// ---------------- stats / concat / normalize ----------------
__global__ void zero_stats_kernel()
{
    if (threadIdx.x < 16) g_stats[threadIdx.x] = 0.0;
}

__global__ void concat_stats_kernel(const float* __restrict__ x, float* __restrict__ attn_out)
{
    __shared__ float tile[32][33];
    int bb = blockIdx.z;
    int l0 = blockIdx.x * 32, c0 = blockIdx.y * 32;
    int tx = threadIdx.x, ty = threadIdx.y;   // (32, 8)
#pragma unroll
    for (int j = 0; j < 4; j++) {
        int c = c0 + tx;
        int l = l0 + ty + j * 8;
        int row = l * Bn + bb;
        float v = (c < C1n) ? g_ha[(size_t)row * C1n + c]
                            : g_va[(size_t)row * C2n + (c - C1n)];
        tile[ty + j * 8][tx] = v;
    }
    __syncthreads();
    float lsum = 0.f, lsq = 0.f;
#pragma unroll
    for (int j = 0; j < 4; j++) {
        int c = c0 + ty + j * 8;
        int l = l0 + tx;
        float av = tile[tx][ty + j * 8];
        size_t gi = ((size_t)(bb * Cn + c)) * HWn + l;
        attn_out[gi] = av;
        float r = av + x[gi];
        lsum += r; lsq += r * r;
    }
#pragma unroll
    for (int off = 16; off > 0; off >>= 1) {
        lsum += __shfl_xor_sync(0xffffffffu, lsum, off);
        lsq  += __shfl_xor_sync(0xffffffffu, lsq,  off);
    }
    if (tx == 0) {
        atomicAdd(&g_stats[bb * 2 + 0], (double)lsum);
        atomicAdd(&g_stats[bb * 2 + 1], (double)lsq);
    }
}

__global__ void finalize_stats_kernel()
{
    int b = threadIdx.x;
    if (b < 8) {
        const double N = (double)Cn * HWn;
        double mu  = g_stats[2 * b + 0] / N;
        double var = g_stats[2 * b + 1] / N - mu * mu;
        g_mu[b]   = (float)mu;
        g_rstd[b] = (float)(1.0 / sqrt(var + 1e-5));
    }
}

__global__ void norm_kernel(const float* __restrict__ attn,
                            const float* __restrict__ x,
                            float* __restrict__ out)
{
    int i = blockIdx.x * 256 + threadIdx.x;
    int bb = i >> 21;
    float r = attn[i] + x[i];
    out[i] = (r - g_mu[bb]) * g_rstd[bb];
}

// ---------------- host launcher ----------------
extern "C" void kernel_launch(void* const* d_in, const int* in_sizes, int n_in,
                              void* d_out, int out_size)
{
    const float* x       = (const float*)d_in[0];
    const float* h_in_w  = (const float*)d_in[1];
    const float* h_in_b  = (const float*)d_in[2];
    const float* h_out_w = (const float*)d_in[3];
    const float* h_out_b = (const float*)d_in[4];
    const float* v_in_w  = (const float*)d_in[5];
    const float* v_in_b  = (const float*)d_in[6];
    const float* v_out_w = (const float*)d_in[7];
    const float* v_out_b = (const float*)d_in[8];
    const float* hfc_w   = (const float*)d_in[9];
    const float* hfc_b   = (const float*)d_in[10];
    const float* vfc_w   = (const float*)d_in[11];
    const float* vfc_b   = (const float*)d_in[12];

    float* out      = (float*)d_out;
    float* out_res  = out;                                   // result   [b,C,h,w]
    float* out_hax  = out + (size_t)NTOK * Cn;               // ha_x     [h,w,b,c]
    float* out_vax  = out + 2 * (size_t)NTOK * Cn;           // va_x     [h,w,b,c]
    float* out_attn = out + 3 * (size_t)NTOK * Cn;           // attn     [b,C,h,w]

    float *p_qh_in, *p_kv_in, *p_xv_in, *p_qh, *p_kvh, *p_qkvv, *p_oh, *p_ov;
    float *p_hax32, *p_vax32, *p_wt, *p_ha, *p_va;
    cudaGetSymbolAddress((void**)&p_qh_in, g_qh_in);
    cudaGetSymbolAddress((void**)&p_kv_in, g_kv_in);
    cudaGetSymbolAddress((void**)&p_xv_in, g_xv_in);
    cudaGetSymbolAddress((void**)&p_qh,    g_qh);
    cudaGetSymbolAddress((void**)&p_kvh,   g_kvh);
    cudaGetSymbolAddress((void**)&p_qkvv,  g_qkvv);
    cudaGetSymbolAddress((void**)&p_oh,    g_oh);
    cudaGetSymbolAddress((void**)&p_ov,    g_ov);
    cudaGetSymbolAddress((void**)&p_hax32, g_hax_t32);
    cudaGetSymbolAddress((void**)&p_vax32, g_vax_t32);
    cudaGetSymbolAddress((void**)&p_wt,    g_wt);
    cudaGetSymbolAddress((void**)&p_ha,    g_ha);
    cudaGetSymbolAddress((void**)&p_va,    g_va);

    dim3 tb(32, 8);
    const int GSMEM = (2 * 128 * 36 + 2 * 64 * 36) * 4;   // 55296 B
    cudaFuncSetAttribute(gemm_t32, cudaFuncAttributeMaxDynamicSharedMemorySize, GSMEM);
    cudaFuncSetAttribute(attn_mma, cudaFuncAttributeMaxDynamicSharedMemorySize, ATT_SMEM);

    // 0) weight conversion to tf32 bits
    conv_t32_kernel<<<(786432 + 255) / 256, 256>>>(h_in_w,  p_wt + W_HIN,  786432);
    conv_t32_kernel<<<(786432 + 255) / 256, 256>>>(v_in_w,  p_wt + W_VIN,  786432);
    conv_t32_kernel<<<(262144 + 255) / 256, 256>>>(h_out_w, p_wt + W_HOUT, 262144);
    conv_t32_kernel<<<(262144 + 255) / 256, 256>>>(v_out_w, p_wt + W_VOUT, 262144);
    conv_t32_kernel<<<(183296 + 255) / 256, 256>>>(hfc_w,   p_wt + W_HFC,  183296);
    conv_t32_kernel<<<(78848  + 255) / 256, 256>>>(vfc_w,   p_wt + W_VFC,  78848);

    // 1) layout transforms (emit tf32 bits)
    transpose_kernel<<<dim3(128, 16, 8), tb>>>(x, p_qh_in, 0);
    transpose_kernel<<<dim3(128, 16, 8), tb>>>(x, p_xv_in, 1);
    pool_kernel<<<(Bn * Cn * 256 + 255) / 256, 256>>>(x, p_kv_in);

    // 2) input projections
    gemm_t32<<<dim3(8, 256), 256, GSMEM>>>((unsigned*)p_qh_in, (unsigned*)(p_wt + W_HIN),
        h_in_b, p_qh, 0, NTOK, 512, 512, 512, 0);
    gemm_t32<<<dim3(16, 16), 256, GSMEM>>>((unsigned*)p_kv_in, (unsigned*)(p_wt + W_HIN + 512 * 512),
        h_in_b + 512, p_kvh, 0, NKV, 1024, 512, 1024, 0);
    gemm_t32<<<dim3(24, 256), 256, GSMEM>>>((unsigned*)p_xv_in, (unsigned*)(p_wt + W_VIN),
        v_in_b, p_qkvv, 0, NTOK, 1536, 512, 1536, 0);

    // 3) attention on tensor cores (outputs tf32 bits)
    attn_mma<<<dim3(32, 8, 8),  256, ATT_SMEM>>>(p_qh,   p_kvh,        p_kvh + 512,   p_oh, 8,   512,  1024, 512);
    attn_mma<<<dim3(2, 8, 128), 256, ATT_SMEM>>>(p_qkvv, p_qkvv + 512, p_qkvv + 1024, p_ov, 128, 1536, 1536, 512);

    // 4) output projections: fp32 to d_out + tf32 copy for fc heads
    gemm_t32<<<dim3(8, 256), 256, GSMEM>>>((unsigned*)p_oh, (unsigned*)(p_wt + W_HOUT),
        h_out_b, out_hax, (unsigned*)p_hax32, NTOK, 512, 512, 512, 0);
    gemm_t32<<<dim3(8, 256), 256, GSMEM>>>((unsigned*)p_ov, (unsigned*)(p_wt + W_VOUT),
        v_out_b, out_vax, (unsigned*)p_vax32, NTOK, 512, 512, 512, 1);

    // 5) fc heads
    gemm_t32<<<dim3(6, 256), 256, GSMEM>>>((unsigned*)p_hax32, (unsigned*)(p_wt + W_HFC),
        hfc_b, p_ha, 0, NTOK, C1n, 512, C1n, 0);
    gemm_t32<<<dim3(3, 256), 256, GSMEM>>>((unsigned*)p_vax32, (unsigned*)(p_wt + W_VFC),
        vfc_b, p_va, 0, NTOK, C2n, 512, C2n, 0);

    // 6) concat + residual stats + layernorm
    zero_stats_kernel<<<1, 32>>>();
    concat_stats_kernel<<<dim3(128, 16, 8), tb>>>(x, out_attn);
    finalize_stats_kernel<<<1, 32>>>();
    norm_kernel<<<NTOK * Cn / 256, 256>>>(out_attn, x, out_res);
}

// round 7
// speedup vs baseline: 2.1199x; 1.2161x over previous
#include <cuda_runtime.h>
#include <cstdint>
#include <math.h>

// ---------------- problem constants ----------------
#define Bn    8
#define Cn    512
#define Hn    64
#define Wn    64
#define HWn   4096          // 64*64
#define NTOK  32768         // 4096*8 tokens
#define NKV   2048          // 256*8
#define C1n   358
#define C2n   154

// ---------------- scratch (static device, no allocs) ----------------
__device__ float  g_qh_in[NTOK * Cn];           // tf32 bits
__device__ float  g_kv_in[NKV * Cn];            // tf32 bits
__device__ float  g_xv_in[NTOK * Cn];           // tf32 bits
__device__ float  g_qh   [NTOK * Cn];           // fp32
__device__ float  g_kvh  [NKV * 2 * Cn];        // fp32
__device__ float  g_qkvv [(size_t)NTOK * 3 * Cn]; // fp32
__device__ float  g_oh   [NTOK * Cn];           // tf32 bits (attn out -> GEMM)
__device__ float  g_ov   [NTOK * Cn];           // tf32 bits
__device__ float  g_hax_t32[NTOK * Cn];         // tf32 bits (fc-h input)
__device__ float  g_vax_t32[NTOK * Cn];         // tf32 bits (fc-v input)
__device__ float  g_wt  [2359296];              // tf32 bits of all weights
__device__ float  g_ha  [(size_t)NTOK * C1n];
__device__ float  g_va  [(size_t)NTOK * C2n];
__device__ double g_stats[16];
__device__ float  g_mu[8];
__device__ float  g_rstd[8];

// weight offsets inside g_wt
#define W_HIN   0
#define W_VIN   786432
#define W_HOUT  1572864
#define W_VOUT  1835008
#define W_HFC   2097152
#define W_VFC   2280448

// ---------------- tf32 helpers ----------------
__device__ __forceinline__ unsigned f2tf(float f) {
    unsigned r;
    asm("cvt.rna.tf32.f32 %0, %1;" : "=r"(r) : "f"(f));
    return r;
}

__global__ void conv_t32_kernel(const float* __restrict__ in, float* __restrict__ out, int n)
{
    int i = blockIdx.x * 256 + threadIdx.x;
    if (i < n) out[i] = __uint_as_float(f2tf(in[i]));
}

__device__ __forceinline__ void mma_tf32(float acc[4], const unsigned a[4], const unsigned b[2]) {
    asm volatile(
        "mma.sync.aligned.m16n8k8.row.col.f32.tf32.tf32.f32 "
        "{%0,%1,%2,%3}, {%4,%5,%6,%7}, {%8,%9}, {%0,%1,%2,%3};\n"
        : "+f"(acc[0]), "+f"(acc[1]), "+f"(acc[2]), "+f"(acc[3])
        : "r"(a[0]), "r"(a[1]), "r"(a[2]), "r"(a[3]), "r"(b[0]), "r"(b[1]));
}

__device__ __forceinline__ void cp16(unsigned saddr, const void* gptr, bool pred) {
    int sz = pred ? 16 : 0;
    asm volatile("cp.async.cg.shared.global [%0], [%1], 16, %2;\n"
                 :: "r"(saddr), "l"(gptr), "r"(sz));
}

// ---------------- transpose x(b,c,h,w) -> tf32 token rows [row, C] ------------
__global__ void transpose_kernel(const float* __restrict__ x,
                                 float* __restrict__ out, int mode)
{
    __shared__ float tile[32][33];
    int bb = blockIdx.z;
    int l0 = blockIdx.x * 32, c0 = blockIdx.y * 32;
    int tx = threadIdx.x, ty = threadIdx.y;   // (32, 8)
#pragma unroll
    for (int j = 0; j < 4; j++) {
        int c = c0 + ty + j * 8;
        tile[ty + j * 8][tx] = x[((size_t)(bb * Cn + c)) * HWn + l0 + tx];
    }
    __syncthreads();
#pragma unroll
    for (int j = 0; j < 4; j++) {
        int l = l0 + ty + j * 8;
        int row;
        if (mode == 0) {
            row = l * Bn + bb;
        } else {
            int xx = l & 63, y = l >> 6;
            int wd = xx & 3, nwi = xx >> 2;
            row = y * 512 + wd * 128 + bb * 16 + nwi;
        }
        out[(size_t)row * Cn + c0 + tx] = __uint_as_float(f2tf(tile[tx][ty + j * 8]));
    }
}

// ---------------- 4x4 avg pool -> tf32 kv token rows ----------------
__global__ void pool_kernel(const float* __restrict__ x, float* __restrict__ out)
{
    int idx = blockIdx.x * 256 + threadIdx.x;
    if (idx >= Bn * Cn * 256) return;
    int px = idx & 15, py = (idx >> 4) & 15, c = (idx >> 8) & 511, bb = idx >> 17;
    const float* base = x + (((size_t)(bb * Cn + c)) * Hn + py * 4) * Wn + px * 4;
    float s = 0.f;
#pragma unroll
    for (int i = 0; i < 4; i++)
#pragma unroll
        for (int j = 0; j < 4; j++) s += base[i * Wn + j];
    out[((size_t)((py * 16 + px) * Bn + bb)) * Cn + c] = __uint_as_float(f2tf(s * 0.0625f));
}

// ---------------- tf32 tensor-core GEMM, cp.async 2-stage, 128x128 CTA tile ---
// A, Bm hold tf32 bit patterns, row-major [M,K] / [N,K]. M%128==0, K%32==0.
// 8 warps as 2(m) x 4(n), warp tile 64x32.
__global__ __launch_bounds__(256, 2) void gemm_t32(
    const unsigned* __restrict__ A, const unsigned* __restrict__ Bm,
    const float* __restrict__ bias, float* __restrict__ Cc,
    unsigned* __restrict__ Ct32,
    int M, int N, int K, int ldc, int mode)
{
    extern __shared__ unsigned sm[];
    unsigned* As[2] = { sm,            sm + 128 * 36 };
    unsigned* Bs[2] = { sm + 2*128*36, sm + 3*128*36 };

    int tid  = threadIdx.x;
    int warp = tid >> 5, lane = tid & 31;
    int wm = warp & 1, wn = warp >> 1;        // 2 x 4 warps
    int g = lane >> 2, t = lane & 3;
    int m0 = blockIdx.y * 128, n0 = blockIdx.x * 128;

    float acc[4][4][4];
#pragma unroll
    for (int mi = 0; mi < 4; mi++)
#pragma unroll
        for (int ni = 0; ni < 4; ni++)
#pragma unroll
            for (int j = 0; j < 4; j++) acc[mi][ni][j] = 0.f;

    int arow = tid >> 3;             // 0..31, rows arow + i*32
    int ac   = (tid & 7) * 4;        // k-col base
    bool bpred[4];
#pragma unroll
    for (int i = 0; i < 4; i++) bpred[i] = (n0 + arow + i * 32) < N;

    const unsigned* Ab = A  + (size_t)(m0 + arow) * K + ac;
    const unsigned* Bb = Bm + (size_t)(n0 + arow) * K + ac;

    unsigned sa[2], sb[2];
#pragma unroll
    for (int s = 0; s < 2; s++) {
        sa[s] = (unsigned)__cvta_generic_to_shared(As[s]);
        sb[s] = (unsigned)__cvta_generic_to_shared(Bs[s]);
    }

#define STAGE(s, k0) do {                                                       \
    _Pragma("unroll")                                                           \
    for (int i = 0; i < 4; i++)                                                 \
        cp16(sa[s] + (unsigned)(((arow + i * 32) * 36 + ac) * 4),               \
             Ab + (size_t)i * 32 * K + (k0), true);                             \
    _Pragma("unroll")                                                           \
    for (int i = 0; i < 4; i++)                                                 \
        cp16(sb[s] + (unsigned)(((arow + i * 32) * 36 + ac) * 4),               \
             Bb + (size_t)i * 32 * K + (k0), bpred[i]);                         \
    asm volatile("cp.async.commit_group;\n" ::);                                \
} while (0)

    STAGE(0, 0);
    STAGE(1, 32);

    int s = 0;
    for (int k0 = 0; k0 < K; k0 += 32) {
        if (k0 + 32 < K)
            asm volatile("cp.async.wait_group 1;\n" ::);
        else
            asm volatile("cp.async.wait_group 0;\n" ::);
        __syncthreads();

        const unsigned* as = As[s];
        const unsigned* bs = Bs[s];
#pragma unroll
        for (int kk = 0; kk < 32; kk += 8) {
            unsigned af[4][4], bf[4][2];
#pragma unroll
            for (int mi = 0; mi < 4; mi++) {
                int rm = wm * 64 + mi * 16 + g;
                af[mi][0] = as[rm * 36 + kk + t];
                af[mi][1] = as[(rm + 8) * 36 + kk + t];
                af[mi][2] = as[rm * 36 + kk + t + 4];
                af[mi][3] = as[(rm + 8) * 36 + kk + t + 4];
            }
#pragma unroll
            for (int ni = 0; ni < 4; ni++) {
                int rn = wn * 32 + ni * 8 + g;
                bf[ni][0] = bs[rn * 36 + kk + t];
                bf[ni][1] = bs[rn * 36 + kk + t + 4];
            }
#pragma unroll
            for (int mi = 0; mi < 4; mi++)
#pragma unroll
                for (int ni = 0; ni < 4; ni++)
                    mma_tf32(acc[mi][ni], af[mi], bf[ni]);
        }
        __syncthreads();

        if (k0 + 64 < K) STAGE(s, k0 + 64);
        s ^= 1;
    }
#undef STAGE

    // epilogue
#pragma unroll
    for (int mi = 0; mi < 4; mi++) {
#pragma unroll
        for (int half = 0; half < 2; half++) {
            int m = m0 + wm * 64 + mi * 16 + g + half * 8;
            int orow;
            if (mode == 0) {
                orow = m;
            } else {
                int nwi = m & 15, bb = (m >> 4) & 7, wd = (m >> 7) & 3, y = m >> 9;
                orow = ((y << 6) + (nwi << 2) + wd) * Bn + bb;
            }
            float* cr = Cc + (size_t)orow * ldc;
            unsigned* ct = Ct32 ? Ct32 + (size_t)orow * ldc : 0;
#pragma unroll
            for (int ni = 0; ni < 4; ni++) {
                int n = n0 + wn * 32 + ni * 8 + t * 2;
                if (n < N) {
                    float v0 = acc[mi][ni][half * 2 + 0] + bias[n];
                    float v1 = acc[mi][ni][half * 2 + 1] + bias[n + 1];
                    cr[n] = v0; cr[n + 1] = v1;
                    if (ct) { ct[n] = f2tf(v0); ct[n + 1] = f2tf(v1); }
                }
            }
        }
    }
}

// ---------------- flash attention on tf32 tensor cores ------------------------
// CTA: 128 queries x one (head, batch). 8 warps, 16 queries/warp.
// K/V processed in 2 chunks of 128 keys (smem halved -> 2 CTAs/SM).
//   Ks [128][68], Vs [128][72], Pw per-warp [16][68] (all bank-bijective)
#define KS_S 68
#define VS_S 72
#define P_S  68
#define ATT_SMEM ((128 * KS_S + 128 * VS_S + 8 * 16 * P_S) * 4)

__global__ __launch_bounds__(256, 2) void attn_mma(
    const float* __restrict__ qb, const float* __restrict__ kb,
    const float* __restrict__ vb, float* __restrict__ ob,
    int Bt, int qld, int kld, int oldd)
{
    extern __shared__ unsigned smu[];
    unsigned* Ks = smu;                       // [128][68]
    unsigned* Vs = smu + 128 * KS_S;          // [128][72]
    int tid  = threadIdx.x;
    int warp = tid >> 5, lane = tid & 31;
    int g = lane >> 2, t = lane & 3;
    int hd = blockIdx.y, bb = blockIdx.z;
    unsigned* Pw = smu + 128 * KS_S + 128 * VS_S + warp * (16 * P_S);

    int qrow0 = blockIdx.x * 128 + warp * 16 + g;   // rows qrow0 and qrow0+8
    unsigned aq[8][4];
    {
        const float* q0 = qb + ((size_t)(qrow0 * Bt + bb)) * qld + hd * 64;
        const float* q1 = qb + ((size_t)((qrow0 + 8) * Bt + bb)) * qld + hd * 64;
#pragma unroll
        for (int ks = 0; ks < 8; ks++) {
            aq[ks][0] = f2tf(q0[ks * 8 + t]     * 0.125f);
            aq[ks][1] = f2tf(q1[ks * 8 + t]     * 0.125f);
            aq[ks][2] = f2tf(q0[ks * 8 + t + 4] * 0.125f);
            aq[ks][3] = f2tf(q1[ks * 8 + t + 4] * 0.125f);
        }
    }

    float o[8][4];
#pragma unroll
    for (int ni = 0; ni < 8; ni++)
#pragma unroll
        for (int j = 0; j < 4; j++) o[ni][j] = 0.f;
    float m0 = -1e30f, m1 = -1e30f, l0 = 0.f, l1 = 0.f;

    for (int chunk = 0; chunk < 2; chunk++) {
        if (chunk) __syncthreads();           // protect Ks/Vs reuse
        // stage 128 keys (fp32 -> tf32 bits)
        for (int idx = tid; idx < 128 * 16; idx += 256) {
            int r = idx >> 4, c = (idx & 15) * 4;
            size_t base = ((size_t)((chunk * 128 + r) * Bt + bb)) * kld + hd * 64 + c;
            float4 kv = *(const float4*)(kb + base);
            float4 vv = *(const float4*)(vb + base);
            Ks[r * KS_S + c + 0] = f2tf(kv.x); Ks[r * KS_S + c + 1] = f2tf(kv.y);
            Ks[r * KS_S + c + 2] = f2tf(kv.z); Ks[r * KS_S + c + 3] = f2tf(kv.w);
            Vs[r * VS_S + c + 0] = f2tf(vv.x); Vs[r * VS_S + c + 1] = f2tf(vv.y);
            Vs[r * VS_S + c + 2] = f2tf(vv.z); Vs[r * VS_S + c + 3] = f2tf(vv.w);
        }
        __syncthreads();

        for (int kt = 0; kt < 2; kt++) {       // 2 key tiles of 64 within chunk
            float sacc[8][4];
#pragma unroll
            for (int ni = 0; ni < 8; ni++)
#pragma unroll
                for (int j = 0; j < 4; j++) sacc[ni][j] = 0.f;

            // S = (Q*scale) K^T
#pragma unroll
            for (int ks = 0; ks < 8; ks++) {
#pragma unroll
                for (int ni = 0; ni < 8; ni++) {
                    int krow = kt * 64 + ni * 8 + g;
                    unsigned bf[2] = { Ks[krow * KS_S + ks * 8 + t],
                                       Ks[krow * KS_S + ks * 8 + t + 4] };
                    mma_tf32(sacc[ni], aq[ks], bf);
                }
            }

            // online softmax (rows g, g+8; quad = lanes sharing g)
            float mx0 = -1e30f, mx1 = -1e30f;
#pragma unroll
            for (int ni = 0; ni < 8; ni++) {
                mx0 = fmaxf(mx0, fmaxf(sacc[ni][0], sacc[ni][1]));
                mx1 = fmaxf(mx1, fmaxf(sacc[ni][2], sacc[ni][3]));
            }
            mx0 = fmaxf(mx0, __shfl_xor_sync(0xffffffffu, mx0, 1));
            mx0 = fmaxf(mx0, __shfl_xor_sync(0xffffffffu, mx0, 2));
            mx1 = fmaxf(mx1, __shfl_xor_sync(0xffffffffu, mx1, 1));
            mx1 = fmaxf(mx1, __shfl_xor_sync(0xffffffffu, mx1, 2));
            float mn0 = fmaxf(m0, mx0), mn1 = fmaxf(m1, mx1);
            float c0 = __expf(m0 - mn0), c1 = __expf(m1 - mn1);
            m0 = mn0; m1 = mn1;

            float rs0 = 0.f, rs1 = 0.f;
#pragma unroll
            for (int ni = 0; ni < 8; ni++) {
                float p00 = __expf(sacc[ni][0] - mn0);
                float p01 = __expf(sacc[ni][1] - mn0);
                float p10 = __expf(sacc[ni][2] - mn1);
                float p11 = __expf(sacc[ni][3] - mn1);
                rs0 += p00 + p01; rs1 += p10 + p11;
                *(uint2*)&Pw[g * P_S + ni * 8 + 2 * t]       = make_uint2(f2tf(p00), f2tf(p01));
                *(uint2*)&Pw[(g + 8) * P_S + ni * 8 + 2 * t] = make_uint2(f2tf(p10), f2tf(p11));
                o[ni][0] *= c0; o[ni][1] *= c0; o[ni][2] *= c1; o[ni][3] *= c1;
            }
            rs0 += __shfl_xor_sync(0xffffffffu, rs0, 1);
            rs0 += __shfl_xor_sync(0xffffffffu, rs0, 2);
            rs1 += __shfl_xor_sync(0xffffffffu, rs1, 1);
            rs1 += __shfl_xor_sync(0xffffffffu, rs1, 2);
            l0 = l0 * c0 + rs0;
            l1 = l1 * c1 + rs1;
            __syncwarp();

            // O += P V
#pragma unroll
            for (int ks = 0; ks < 8; ks++) {
                unsigned ap[4] = { Pw[g * P_S + ks * 8 + t],
                                   Pw[(g + 8) * P_S + ks * 8 + t],
                                   Pw[g * P_S + ks * 8 + t + 4],
                                   Pw[(g + 8) * P_S + ks * 8 + t + 4] };
                int vr0 = (kt * 64 + ks * 8 + t) * VS_S;
                int vr1 = (kt * 64 + ks * 8 + t + 4) * VS_S;
#pragma unroll
                for (int ni = 0; ni < 8; ni++) {
                    unsigned bf[2] = { Vs[vr0 + ni * 8 + g], Vs[vr1 + ni * 8 + g] };
                    mma_tf32(o[ni], ap, bf);
                }
            }
            __syncwarp();
        }
    }

    float i0 = 1.f / l0, i1 = 1.f / l1;
    float* o0 = ob + ((size_t)(qrow0 * Bt + bb)) * oldd + hd * 64;
    float* o1 = ob + ((size_t)((qrow0 + 8) * Bt + bb)) * oldd + hd * 64;
#pragma unroll
    for (int ni = 0; ni < 8; ni++) {
        o0[ni * 8 + 2 * t]     = __uint_as_float(f2tf(o[ni][0] * i0));
        o0[ni * 8 + 2 * t + 1] = __uint_as_float(f2tf(o[ni][1] * i0));
        o1[ni * 8 + 2 * t]     = __uint_as_float(f2tf(o[ni][2] * i1));
        o1[ni * 8 + 2 * t + 1] = __uint_as_float(f2tf(o[ni][3] * i1));
    }
}

// ---------------- stats / concat / normalize ----------------
__global__ void zero_stats_kernel()
{
    if (threadIdx.x < 16) g_stats[threadIdx.x] = 0.0;
}

__global__ void concat_stats_kernel(const float* __restrict__ x, float* __restrict__ attn_out)
{
    __shared__ float tile[32][33];
    int bb = blockIdx.z;
    int l0 = blockIdx.x * 32, c0 = blockIdx.y * 32;
    int tx = threadIdx.x, ty = threadIdx.y;   // (32, 8)
#pragma unroll
    for (int j = 0; j < 4; j++) {
        int c = c0 + tx;
        int l = l0 + ty + j * 8;
        int row = l * Bn + bb;
        float v = (c < C1n) ? g_ha[(size_t)row * C1n + c]
                            : g_va[(size_t)row * C2n + (c - C1n)];
        tile[ty + j * 8][tx] = v;
    }
    __syncthreads();
    float lsum = 0.f, lsq = 0.f;
#pragma unroll
    for (int j = 0; j < 4; j++) {
        int c = c0 + ty + j * 8;
        int l = l0 + tx;
        float av = tile[tx][ty + j * 8];
        size_t gi = ((size_t)(bb * Cn + c)) * HWn + l;
        attn_out[gi] = av;
        float r = av + x[gi];
        lsum += r; lsq += r * r;
    }
#pragma unroll
    for (int off = 16; off > 0; off >>= 1) {
        lsum += __shfl_xor_sync(0xffffffffu, lsum, off);
        lsq  += __shfl_xor_sync(0xffffffffu, lsq,  off);
    }
    if (tx == 0) {
        atomicAdd(&g_stats[bb * 2 + 0], (double)lsum);
        atomicAdd(&g_stats[bb * 2 + 1], (double)lsq);
    }
}

__global__ void finalize_stats_kernel()
{
    int b = threadIdx.x;
    if (b < 8) {
        const double N = (double)Cn * HWn;
        double mu  = g_stats[2 * b + 0] / N;
        double var = g_stats[2 * b + 1] / N - mu * mu;
        g_mu[b]   = (float)mu;
        g_rstd[b] = (float)(1.0 / sqrt(var + 1e-5));
    }
}

__global__ void norm_kernel(const float* __restrict__ attn,
                            const float* __restrict__ x,
                            float* __restrict__ out)
{
    int i = blockIdx.x * 256 + threadIdx.x;
    int bb = i >> 21;
    float r = attn[i] + x[i];
    out[i] = (r - g_mu[bb]) * g_rstd[bb];
}

// ---------------- host launcher ----------------
extern "C" void kernel_launch(void* const* d_in, const int* in_sizes, int n_in,
                              void* d_out, int out_size)
{
    const float* x       = (const float*)d_in[0];
    const float* h_in_w  = (const float*)d_in[1];
    const float* h_in_b  = (const float*)d_in[2];
    const float* h_out_w = (const float*)d_in[3];
    const float* h_out_b = (const float*)d_in[4];
    const float* v_in_w  = (const float*)d_in[5];
    const float* v_in_b  = (const float*)d_in[6];
    const float* v_out_w = (const float*)d_in[7];
    const float* v_out_b = (const float*)d_in[8];
    const float* hfc_w   = (const float*)d_in[9];
    const float* hfc_b   = (const float*)d_in[10];
    const float* vfc_w   = (const float*)d_in[11];
    const float* vfc_b   = (const float*)d_in[12];

    float* out      = (float*)d_out;
    float* out_res  = out;                                   // result   [b,C,h,w]
    float* out_hax  = out + (size_t)NTOK * Cn;               // ha_x     [h,w,b,c]
    float* out_vax  = out + 2 * (size_t)NTOK * Cn;           // va_x     [h,w,b,c]
    float* out_attn = out + 3 * (size_t)NTOK * Cn;           // attn     [b,C,h,w]

    float *p_qh_in, *p_kv_in, *p_xv_in, *p_qh, *p_kvh, *p_qkvv, *p_oh, *p_ov;
    float *p_hax32, *p_vax32, *p_wt, *p_ha, *p_va;
    cudaGetSymbolAddress((void**)&p_qh_in, g_qh_in);
    cudaGetSymbolAddress((void**)&p_kv_in, g_kv_in);
    cudaGetSymbolAddress((void**)&p_xv_in, g_xv_in);
    cudaGetSymbolAddress((void**)&p_qh,    g_qh);
    cudaGetSymbolAddress((void**)&p_kvh,   g_kvh);
    cudaGetSymbolAddress((void**)&p_qkvv,  g_qkvv);
    cudaGetSymbolAddress((void**)&p_oh,    g_oh);
    cudaGetSymbolAddress((void**)&p_ov,    g_ov);
    cudaGetSymbolAddress((void**)&p_hax32, g_hax_t32);
    cudaGetSymbolAddress((void**)&p_vax32, g_vax_t32);
    cudaGetSymbolAddress((void**)&p_wt,    g_wt);
    cudaGetSymbolAddress((void**)&p_ha,    g_ha);
    cudaGetSymbolAddress((void**)&p_va,    g_va);

    dim3 tb(32, 8);
    const int GSMEM = 4 * 128 * 36 * 4;   // 73728 B (2-stage A+B, 128x128 tile)
    cudaFuncSetAttribute(gemm_t32, cudaFuncAttributeMaxDynamicSharedMemorySize, GSMEM);
    cudaFuncSetAttribute(attn_mma, cudaFuncAttributeMaxDynamicSharedMemorySize, ATT_SMEM);

    // 0) weight conversion to tf32 bits
    conv_t32_kernel<<<(786432 + 255) / 256, 256>>>(h_in_w,  p_wt + W_HIN,  786432);
    conv_t32_kernel<<<(786432 + 255) / 256, 256>>>(v_in_w,  p_wt + W_VIN,  786432);
    conv_t32_kernel<<<(262144 + 255) / 256, 256>>>(h_out_w, p_wt + W_HOUT, 262144);
    conv_t32_kernel<<<(262144 + 255) / 256, 256>>>(v_out_w, p_wt + W_VOUT, 262144);
    conv_t32_kernel<<<(183296 + 255) / 256, 256>>>(hfc_w,   p_wt + W_HFC,  183296);
    conv_t32_kernel<<<(78848  + 255) / 256, 256>>>(vfc_w,   p_wt + W_VFC,  78848);

    // 1) layout transforms (emit tf32 bits)
    transpose_kernel<<<dim3(128, 16, 8), tb>>>(x, p_qh_in, 0);
    transpose_kernel<<<dim3(128, 16, 8), tb>>>(x, p_xv_in, 1);
    pool_kernel<<<(Bn * Cn * 256 + 255) / 256, 256>>>(x, p_kv_in);

    // 2) input projections
    gemm_t32<<<dim3(4, 256), 256, GSMEM>>>((unsigned*)p_qh_in, (unsigned*)(p_wt + W_HIN),
        h_in_b, p_qh, 0, NTOK, 512, 512, 512, 0);
    gemm_t32<<<dim3(8, 16), 256, GSMEM>>>((unsigned*)p_kv_in, (unsigned*)(p_wt + W_HIN + 512 * 512),
        h_in_b + 512, p_kvh, 0, NKV, 1024, 512, 1024, 0);
    gemm_t32<<<dim3(12, 256), 256, GSMEM>>>((unsigned*)p_xv_in, (unsigned*)(p_wt + W_VIN),
        v_in_b, p_qkvv, 0, NTOK, 1536, 512, 1536, 0);

    // 3) attention on tensor cores (outputs tf32 bits)
    attn_mma<<<dim3(32, 8, 8),  256, ATT_SMEM>>>(p_qh,   p_kvh,        p_kvh + 512,   p_oh, 8,   512,  1024, 512);
    attn_mma<<<dim3(2, 8, 128), 256, ATT_SMEM>>>(p_qkvv, p_qkvv + 512, p_qkvv + 1024, p_ov, 128, 1536, 1536, 512);

    // 4) output projections: fp32 to d_out + tf32 copy for fc heads
    gemm_t32<<<dim3(4, 256), 256, GSMEM>>>((unsigned*)p_oh, (unsigned*)(p_wt + W_HOUT),
        h_out_b, out_hax, (unsigned*)p_hax32, NTOK, 512, 512, 512, 0);
    gemm_t32<<<dim3(4, 256), 256, GSMEM>>>((unsigned*)p_ov, (unsigned*)(p_wt + W_VOUT),
        v_out_b, out_vax, (unsigned*)p_vax32, NTOK, 512, 512, 512, 1);

    // 5) fc heads
    gemm_t32<<<dim3(3, 256), 256, GSMEM>>>((unsigned*)p_hax32, (unsigned*)(p_wt + W_HFC),
        hfc_b, p_ha, 0, NTOK, C1n, 512, C1n, 0);
    gemm_t32<<<dim3(2, 256), 256, GSMEM>>>((unsigned*)p_vax32, (unsigned*)(p_wt + W_VFC),
        vfc_b, p_va, 0, NTOK, C2n, 512, C2n, 0);

    // 6) concat + residual stats + layernorm
    zero_stats_kernel<<<1, 32>>>();
    concat_stats_kernel<<<dim3(128, 16, 8), tb>>>(x, out_attn);
    finalize_stats_kernel<<<1, 32>>>();
    norm_kernel<<<NTOK * Cn / 256, 256>>>(out_attn, x, out_res);
}

// round 8
// speedup vs baseline: 2.2427x; 1.0579x over previous
#include <cuda_runtime.h>
#include <cstdint>
#include <math.h>

// ---------------- problem constants ----------------
#define Bn    8
#define Cn    512
#define Hn    64
#define Wn    64
#define HWn   4096          // 64*64
#define NTOK  32768         // 4096*8 tokens
#define NKV   2048          // 256*8
#define C1n   358
#define C2n   154

// ---------------- scratch (static device, no allocs) ----------------
// "perm" buffers hold tf32 bits with columns k permuted within 8-groups.
__device__ float  g_qh_in[NTOK * Cn];           // tf32 bits, perm
__device__ float  g_kv_in[NKV * Cn];            // tf32 bits, perm
__device__ float  g_xv_in[NTOK * Cn];           // tf32 bits, perm
__device__ float  g_qh   [NTOK * Cn];           // fp32 (attn input)
__device__ float  g_kvh  [NKV * 2 * Cn];        // fp32
__device__ float  g_qkvv [(size_t)NTOK * 3 * Cn]; // fp32
__device__ float  g_oh   [NTOK * Cn];           // tf32 bits, perm
__device__ float  g_ov   [NTOK * Cn];           // tf32 bits, perm
__device__ float  g_hax_t32[NTOK * Cn];         // tf32 bits, perm
__device__ float  g_vax_t32[NTOK * Cn];         // tf32 bits, perm
__device__ float  g_wt  [2359296];              // tf32 bits, perm (weights)
__device__ float  g_ha  [(size_t)NTOK * C1n];
__device__ float  g_va  [(size_t)NTOK * C2n];
__device__ double g_stats[16];
__device__ float  g_mu[8];
__device__ float  g_rstd[8];

// weight offsets inside g_wt
#define W_HIN   0
#define W_VIN   786432
#define W_HOUT  1572864
#define W_VOUT  1835008
#define W_HFC   2097152
#define W_VFC   2280448

// k-permutation within 8-groups: logical pair (t, t+4) -> physical (2t, 2t+1)
__device__ __forceinline__ int pcol(int k) {
    return (k & ~7) | (((k & 3) << 1) | ((k >> 2) & 1));
}

// ---------------- tf32 helpers ----------------
__device__ __forceinline__ unsigned f2tf(float f) {
    unsigned r;
    asm("cvt.rna.tf32.f32 %0, %1;" : "=r"(r) : "f"(f));
    return r;
}

__device__ __forceinline__ void mma_tf32(float acc[4], const unsigned a[4], const unsigned b[2]) {
    asm volatile(
        "mma.sync.aligned.m16n8k8.row.col.f32.tf32.tf32.f32 "
        "{%0,%1,%2,%3}, {%4,%5,%6,%7}, {%8,%9}, {%0,%1,%2,%3};\n"
        : "+f"(acc[0]), "+f"(acc[1]), "+f"(acc[2]), "+f"(acc[3])
        : "r"(a[0]), "r"(a[1]), "r"(a[2]), "r"(a[3]), "r"(b[0]), "r"(b[1]));
}

__device__ __forceinline__ void cp16(unsigned saddr, const void* gptr, bool pred) {
    int sz = pred ? 16 : 0;
    asm volatile("cp.async.cg.shared.global [%0], [%1], 16, %2;\n"
                 :: "r"(saddr), "l"(gptr), "r"(sz));
}

// ---------------- fused weight conversion (fp32 -> tf32 bits, k-permuted) -----
// All six weight matrices have K=512 rows; permute within each row.
__global__ void conv_all_kernel(
    const float* __restrict__ w0, const float* __restrict__ w1,
    const float* __restrict__ w2, const float* __restrict__ w3,
    const float* __restrict__ w4, const float* __restrict__ w5)
{
    int i = blockIdx.x * 256 + threadIdx.x;
    if (i >= 2359296) return;
    const float* src;
    int off;
    if      (i < W_VIN)  { src = w0; off = i - W_HIN;  }
    else if (i < W_HOUT) { src = w1; off = i - W_VIN;  }
    else if (i < W_VOUT) { src = w2; off = i - W_HOUT; }
    else if (i < W_HFC)  { src = w3; off = i - W_VOUT; }
    else if (i < W_VFC)  { src = w4; off = i - W_HFC;  }
    else                 { src = w5; off = i - W_VFC;  }
    int row = off >> 9, col = off & 511;
    g_wt[(i - off) + row * 512 + pcol(col)] = __uint_as_float(f2tf(src[off]));
}

// ---------------- transpose x(b,c,h,w) -> tf32 token rows [row, C] (perm) -----
__global__ void transpose_kernel(const float* __restrict__ x,
                                 float* __restrict__ out, int mode)
{
    __shared__ float tile[32][33];
    int bb = blockIdx.z;
    int l0 = blockIdx.x * 32, c0 = blockIdx.y * 32;
    int tx = threadIdx.x, ty = threadIdx.y;   // (32, 8)
#pragma unroll
    for (int j = 0; j < 4; j++) {
        int c = c0 + ty + j * 8;
        tile[ty + j * 8][tx] = x[((size_t)(bb * Cn + c)) * HWn + l0 + tx];
    }
    __syncthreads();
#pragma unroll
    for (int j = 0; j < 4; j++) {
        int l = l0 + ty + j * 8;
        int row;
        if (mode == 0) {
            row = l * Bn + bb;
        } else {
            int xx = l & 63, y = l >> 6;
            int wd = xx & 3, nwi = xx >> 2;
            row = y * 512 + wd * 128 + bb * 16 + nwi;
        }
        out[(size_t)row * Cn + pcol(c0 + tx)] = __uint_as_float(f2tf(tile[tx][ty + j * 8]));
    }
}

// ---------------- 4x4 avg pool -> tf32 kv token rows (perm) ----------------
__global__ void pool_kernel(const float* __restrict__ x, float* __restrict__ out)
{
    int idx = blockIdx.x * 256 + threadIdx.x;
    if (idx >= Bn * Cn * 256) return;
    int px = idx & 15, py = (idx >> 4) & 15, c = (idx >> 8) & 511, bb = idx >> 17;
    const float* base = x + (((size_t)(bb * Cn + c)) * Hn + py * 4) * Wn + px * 4;
    float s = 0.f;
#pragma unroll
    for (int i = 0; i < 4; i++)
#pragma unroll
        for (int j = 0; j < 4; j++) s += base[i * Wn + j];
    out[((size_t)((py * 16 + px) * Bn + bb)) * Cn + pcol(c)] = __uint_as_float(f2tf(s * 0.0625f));
}

// ---------------- tf32 tensor-core GEMM, cp.async 2-stage, 128x128 CTA tile ---
// A, Bm: tf32 bits, k-permuted, row-major [M,K] / [N,K]. M%128==0, K%32==0.
// 8 warps as 2(m) x 4(n), warp tile 64x32. Smem row stride 40 words
// (40 mod 32 = 8 -> LDS.64 fragment loads conflict-free: banks 8g+2t).
#define GST 40
__global__ __launch_bounds__(256, 2) void gemm_t32(
    const unsigned* __restrict__ A, const unsigned* __restrict__ Bm,
    const float* __restrict__ bias, float* __restrict__ Cc,
    unsigned* __restrict__ Ct32,
    int M, int N, int K, int ldc, int mode)
{
    extern __shared__ unsigned sm[];
    unsigned* As[2] = { sm,             sm + 128 * GST };
    unsigned* Bs[2] = { sm + 2*128*GST, sm + 3*128*GST };

    int tid  = threadIdx.x;
    int warp = tid >> 5, lane = tid & 31;
    int wm = warp & 1, wn = warp >> 1;        // 2 x 4 warps
    int g = lane >> 2, t = lane & 3;
    int m0 = blockIdx.y * 128, n0 = blockIdx.x * 128;

    float acc[4][4][4];
#pragma unroll
    for (int mi = 0; mi < 4; mi++)
#pragma unroll
        for (int ni = 0; ni < 4; ni++)
#pragma unroll
            for (int j = 0; j < 4; j++) acc[mi][ni][j] = 0.f;

    int arow = tid >> 3;             // 0..31, rows arow + i*32
    int ac   = (tid & 7) * 4;        // k-col base (physical)
    bool bpred[4];
#pragma unroll
    for (int i = 0; i < 4; i++) bpred[i] = (n0 + arow + i * 32) < N;

    const unsigned* Ab = A  + (size_t)(m0 + arow) * K + ac;
    const unsigned* Bb = Bm + (size_t)(n0 + arow) * K + ac;

    unsigned sa[2], sb[2];
#pragma unroll
    for (int s = 0; s < 2; s++) {
        sa[s] = (unsigned)__cvta_generic_to_shared(As[s]);
        sb[s] = (unsigned)__cvta_generic_to_shared(Bs[s]);
    }

#define STAGE(s, k0) do {                                                       \
    _Pragma("unroll")                                                           \
    for (int i = 0; i < 4; i++)                                                 \
        cp16(sa[s] + (unsigned)(((arow + i * 32) * GST + ac) * 4),              \
             Ab + (size_t)i * 32 * K + (k0), true);                             \
    _Pragma("unroll")                                                           \
    for (int i = 0; i < 4; i++)                                                 \
        cp16(sb[s] + (unsigned)(((arow + i * 32) * GST + ac) * 4),              \
             Bb + (size_t)i * 32 * K + (k0), bpred[i]);                         \
    asm volatile("cp.async.commit_group;\n" ::);                                \
} while (0)

    STAGE(0, 0);
    STAGE(1, 32);

    int s = 0;
    for (int k0 = 0; k0 < K; k0 += 32) {
        if (k0 + 32 < K)
            asm volatile("cp.async.wait_group 1;\n" ::);
        else
            asm volatile("cp.async.wait_group 0;\n" ::);
        __syncthreads();

        const unsigned* as = As[s];
        const unsigned* bs = Bs[s];
#pragma unroll
        for (int kk = 0; kk < 32; kk += 8) {
            unsigned af[4][4], bf[4][2];
#pragma unroll
            for (int mi = 0; mi < 4; mi++) {
                int rm = wm * 64 + mi * 16 + g;
                uint2 lo = *(const uint2*)&as[rm * GST + kk + 2 * t];
                uint2 hi = *(const uint2*)&as[(rm + 8) * GST + kk + 2 * t];
                af[mi][0] = lo.x; af[mi][2] = lo.y;   // logical (t, t+4) row rm
                af[mi][1] = hi.x; af[mi][3] = hi.y;   // row rm+8
            }
#pragma unroll
            for (int ni = 0; ni < 4; ni++) {
                int rn = wn * 32 + ni * 8 + g;
                uint2 bv = *(const uint2*)&bs[rn * GST + kk + 2 * t];
                bf[ni][0] = bv.x; bf[ni][1] = bv.y;
            }
#pragma unroll
            for (int mi = 0; mi < 4; mi++)
#pragma unroll
                for (int ni = 0; ni < 4; ni++)
                    mma_tf32(acc[mi][ni], af[mi], bf[ni]);
        }
        __syncthreads();

        if (k0 + 64 < K) STAGE(s, k0 + 64);
        s ^= 1;
    }
#undef STAGE

    // epilogue
#pragma unroll
    for (int mi = 0; mi < 4; mi++) {
#pragma unroll
        for (int half = 0; half < 2; half++) {
            int m = m0 + wm * 64 + mi * 16 + g + half * 8;
            int orow;
            if (mode == 0) {
                orow = m;
            } else {
                int nwi = m & 15, bb = (m >> 4) & 7, wd = (m >> 7) & 3, y = m >> 9;
                orow = ((y << 6) + (nwi << 2) + wd) * Bn + bb;
            }
            float* cr = Cc + (size_t)orow * ldc;
            unsigned* ct = Ct32 ? Ct32 + (size_t)orow * ldc : 0;
#pragma unroll
            for (int ni = 0; ni < 4; ni++) {
                int n = n0 + wn * 32 + ni * 8 + t * 2;
                if (n < N) {
                    float v0 = acc[mi][ni][half * 2 + 0] + bias[n];
                    float v1 = acc[mi][ni][half * 2 + 1] + bias[n + 1];
                    cr[n] = v0; cr[n + 1] = v1;
                    if (ct) { ct[pcol(n)] = f2tf(v0); ct[pcol(n + 1)] = f2tf(v1); }
                }
            }
        }
    }
}

// ---------------- flash attention on tf32 tensor cores ------------------------
// CTA: 128 queries x one (head, batch). 8 warps, 16 queries/warp.
// K/V in 2 chunks of 128 keys. Ks k-permuted, stride 72 (72 mod 32 = 8 ->
// LDS.64 B-frag loads conflict-free). Vs/Pw logical layout as before.
#define KS_S 72
#define VS_S 72
#define P_S  68
#define ATT_SMEM ((128 * KS_S + 128 * VS_S + 8 * 16 * P_S) * 4)

__global__ __launch_bounds__(256, 2) void attn_mma(
    const float* __restrict__ qb, const float* __restrict__ kb,
    const float* __restrict__ vb, float* __restrict__ ob,
    int Bt, int qld, int kld, int oldd)
{
    extern __shared__ unsigned smu[];
    unsigned* Ks = smu;                       // [128][72], k-permuted
    unsigned* Vs = smu + 128 * KS_S;          // [128][72], logical
    int tid  = threadIdx.x;
    int warp = tid >> 5, lane = tid & 31;
    int g = lane >> 2, t = lane & 3;
    int hd = blockIdx.y, bb = blockIdx.z;
    unsigned* Pw = smu + 128 * KS_S + 128 * VS_S + warp * (16 * P_S);

    int qrow0 = blockIdx.x * 128 + warp * 16 + g;   // rows qrow0 and qrow0+8
    unsigned aq[8][4];
    {
        const float* q0 = qb + ((size_t)(qrow0 * Bt + bb)) * qld + hd * 64;
        const float* q1 = qb + ((size_t)((qrow0 + 8) * Bt + bb)) * qld + hd * 64;
#pragma unroll
        for (int ks = 0; ks < 8; ks++) {
            aq[ks][0] = f2tf(q0[ks * 8 + t]     * 0.125f);
            aq[ks][1] = f2tf(q1[ks * 8 + t]     * 0.125f);
            aq[ks][2] = f2tf(q0[ks * 8 + t + 4] * 0.125f);
            aq[ks][3] = f2tf(q1[ks * 8 + t + 4] * 0.125f);
        }
    }

    float o[8][4];
#pragma unroll
    for (int ni = 0; ni < 8; ni++)
#pragma unroll
        for (int j = 0; j < 4; j++) o[ni][j] = 0.f;
    float m0 = -1e30f, m1 = -1e30f, l0 = 0.f, l1 = 0.f;

    for (int chunk = 0; chunk < 2; chunk++) {
        if (chunk) __syncthreads();           // protect Ks/Vs reuse
        // stage 128 keys (fp32 -> tf32 bits; K permuted, V logical)
        for (int idx = tid; idx < 128 * 16; idx += 256) {
            int r = idx >> 4, cc = (idx & 15) * 4;
            size_t base = ((size_t)((chunk * 128 + r) * Bt + bb)) * kld + hd * 64 + cc;
            float4 kv = *(const float4*)(kb + base);
            float4 vv = *(const float4*)(vb + base);
            int grp = cc & ~7, sub = (cc & 4) ? 1 : 0;
            Ks[r * KS_S + grp + sub + 0] = f2tf(kv.x);
            Ks[r * KS_S + grp + sub + 2] = f2tf(kv.y);
            Ks[r * KS_S + grp + sub + 4] = f2tf(kv.z);
            Ks[r * KS_S + grp + sub + 6] = f2tf(kv.w);
            Vs[r * VS_S + cc + 0] = f2tf(vv.x); Vs[r * VS_S + cc + 1] = f2tf(vv.y);
            Vs[r * VS_S + cc + 2] = f2tf(vv.z); Vs[r * VS_S + cc + 3] = f2tf(vv.w);
        }
        __syncthreads();

        for (int kt = 0; kt < 2; kt++) {       // 2 key tiles of 64 within chunk
            float sacc[8][4];
#pragma unroll
            for (int ni = 0; ni < 8; ni++)
#pragma unroll
                for (int j = 0; j < 4; j++) sacc[ni][j] = 0.f;

            // S = (Q*scale) K^T   (B-frags via LDS.64, conflict-free)
#pragma unroll
            for (int ks = 0; ks < 8; ks++) {
#pragma unroll
                for (int ni = 0; ni < 8; ni++) {
                    int krow = kt * 64 + ni * 8 + g;
                    uint2 bv = *(const uint2*)&Ks[krow * KS_S + ks * 8 + 2 * t];
                    unsigned bf[2] = { bv.x, bv.y };
                    mma_tf32(sacc[ni], aq[ks], bf);
                }
            }

            // online softmax (rows g, g+8; quad = lanes sharing g)
            float mx0 = -1e30f, mx1 = -1e30f;
#pragma unroll
            for (int ni = 0; ni < 8; ni++) {
                mx0 = fmaxf(mx0, fmaxf(sacc[ni][0], sacc[ni][1]));
                mx1 = fmaxf(mx1, fmaxf(sacc[ni][2], sacc[ni][3]));
            }
            mx0 = fmaxf(mx0, __shfl_xor_sync(0xffffffffu, mx0, 1));
            mx0 = fmaxf(mx0, __shfl_xor_sync(0xffffffffu, mx0, 2));
            mx1 = fmaxf(mx1, __shfl_xor_sync(0xffffffffu, mx1, 1));
            mx1 = fmaxf(mx1, __shfl_xor_sync(0xffffffffu, mx1, 2));
            float mn0 = fmaxf(m0, mx0), mn1 = fmaxf(m1, mx1);
            float c0 = __expf(m0 - mn0), c1 = __expf(m1 - mn1);
            m0 = mn0; m1 = mn1;

            float rs0 = 0.f, rs1 = 0.f;
#pragma unroll
            for (int ni = 0; ni < 8; ni++) {
                float p00 = __expf(sacc[ni][0] - mn0);
                float p01 = __expf(sacc[ni][1] - mn0);
                float p10 = __expf(sacc[ni][2] - mn1);
                float p11 = __expf(sacc[ni][3] - mn1);
                rs0 += p00 + p01; rs1 += p10 + p11;
                *(uint2*)&Pw[g * P_S + ni * 8 + 2 * t]       = make_uint2(f2tf(p00), f2tf(p01));
                *(uint2*)&Pw[(g + 8) * P_S + ni * 8 + 2 * t] = make_uint2(f2tf(p10), f2tf(p11));
                o[ni][0] *= c0; o[ni][1] *= c0; o[ni][2] *= c1; o[ni][3] *= c1;
            }
            rs0 += __shfl_xor_sync(0xffffffffu, rs0, 1);
            rs0 += __shfl_xor_sync(0xffffffffu, rs0, 2);
            rs1 += __shfl_xor_sync(0xffffffffu, rs1, 1);
            rs1 += __shfl_xor_sync(0xffffffffu, rs1, 2);
            l0 = l0 * c0 + rs0;
            l1 = l1 * c1 + rs1;
            __syncwarp();

            // O += P V
#pragma unroll
            for (int ks = 0; ks < 8; ks++) {
                unsigned ap[4] = { Pw[g * P_S + ks * 8 + t],
                                   Pw[(g + 8) * P_S + ks * 8 + t],
                                   Pw[g * P_S + ks * 8 + t + 4],
                                   Pw[(g + 8) * P_S + ks * 8 + t + 4] };
                int vr0 = (kt * 64 + ks * 8 + t) * VS_S;
                int vr1 = (kt * 64 + ks * 8 + t + 4) * VS_S;
#pragma unroll
                for (int ni = 0; ni < 8; ni++) {
                    unsigned bf[2] = { Vs[vr0 + ni * 8 + g], Vs[vr1 + ni * 8 + g] };
                    mma_tf32(o[ni], ap, bf);
                }
            }
            __syncwarp();
        }
    }

    // epilogue: write tf32 bits with k-permuted columns (feeds GEMM A)
    float i0 = 1.f / l0, i1 = 1.f / l1;
    float* o0 = ob + ((size_t)(qrow0 * Bt + bb)) * oldd + hd * 64;
    float* o1 = ob + ((size_t)((qrow0 + 8) * Bt + bb)) * oldd + hd * 64;
#pragma unroll
    for (int ni = 0; ni < 8; ni++) {
        int c = ni * 8 + 2 * t;
        o0[pcol(c)]     = __uint_as_float(f2tf(o[ni][0] * i0));
        o0[pcol(c + 1)] = __uint_as_float(f2tf(o[ni][1] * i0));
        o1[pcol(c)]     = __uint_as_float(f2tf(o[ni][2] * i1));
        o1[pcol(c + 1)] = __uint_as_float(f2tf(o[ni][3] * i1));
    }
}

// ---------------- stats / concat / normalize ----------------
__global__ void zero_stats_kernel()
{
    if (threadIdx.x < 16) g_stats[threadIdx.x] = 0.0;
}

__global__ void concat_stats_kernel(const float* __restrict__ x, float* __restrict__ attn_out)
{
    __shared__ float tile[32][33];
    int bb = blockIdx.z;
    int l0 = blockIdx.x * 32, c0 = blockIdx.y * 32;
    int tx = threadIdx.x, ty = threadIdx.y;   // (32, 8)
#pragma unroll
    for (int j = 0; j < 4; j++) {
        int c = c0 + tx;
        int l = l0 + ty + j * 8;
        int row = l * Bn + bb;
        float v = (c < C1n) ? g_ha[(size_t)row * C1n + c]
                            : g_va[(size_t)row * C2n + (c - C1n)];
        tile[ty + j * 8][tx] = v;
    }
    __syncthreads();
    float lsum = 0.f, lsq = 0.f;
#pragma unroll
    for (int j = 0; j < 4; j++) {
        int c = c0 + ty + j * 8;
        int l = l0 + tx;
        float av = tile[tx][ty + j * 8];
        size_t gi = ((size_t)(bb * Cn + c)) * HWn + l;
        attn_out[gi] = av;
        float r = av + x[gi];
        lsum += r; lsq += r * r;
    }
#pragma unroll
    for (int off = 16; off > 0; off >>= 1) {
        lsum += __shfl_xor_sync(0xffffffffu, lsum, off);
        lsq  += __shfl_xor_sync(0xffffffffu, lsq,  off);
    }
    if (tx == 0) {
        atomicAdd(&g_stats[bb * 2 + 0], (double)lsum);
        atomicAdd(&g_stats[bb * 2 + 1], (double)lsq);
    }
}

__global__ void finalize_stats_kernel()
{
    int b = threadIdx.x;
    if (b < 8) {
        const double N = (double)Cn * HWn;
        double mu  = g_stats[2 * b + 0] / N;
        double var = g_stats[2 * b + 1] / N - mu * mu;
        g_mu[b]   = (float)mu;
        g_rstd[b] = (float)(1.0 / sqrt(var + 1e-5));
    }
}

__global__ void norm_kernel(const float* __restrict__ attn,
                            const float* __restrict__ x,
                            float* __restrict__ out)
{
    int i = blockIdx.x * 256 + threadIdx.x;
    int bb = i >> 21;
    float r = attn[i] + x[i];
    out[i] = (r - g_mu[bb]) * g_rstd[bb];
}

// ---------------- host launcher ----------------
extern "C" void kernel_launch(void* const* d_in, const int* in_sizes, int n_in,
                              void* d_out, int out_size)
{
    const float* x       = (const float*)d_in[0];
    const float* h_in_w  = (const float*)d_in[1];
    const float* h_in_b  = (const float*)d_in[2];
    const float* h_out_w = (const float*)d_in[3];
    const float* h_out_b = (const float*)d_in[4];
    const float* v_in_w  = (const float*)d_in[5];
    const float* v_in_b  = (const float*)d_in[6];
    const float* v_out_w = (const float*)d_in[7];
    const float* v_out_b = (const float*)d_in[8];
    const float* hfc_w   = (const float*)d_in[9];
    const float* hfc_b   = (const float*)d_in[10];
    const float* vfc_w   = (const float*)d_in[11];
    const float* vfc_b   = (const float*)d_in[12];

    float* out      = (float*)d_out;
    float* out_res  = out;                                   // result   [b,C,h,w]
    float* out_hax  = out + (size_t)NTOK * Cn;               // ha_x     [h,w,b,c]
    float* out_vax  = out + 2 * (size_t)NTOK * Cn;           // va_x     [h,w,b,c]
    float* out_attn = out + 3 * (size_t)NTOK * Cn;           // attn     [b,C,h,w]

    float *p_qh_in, *p_kv_in, *p_xv_in, *p_qh, *p_kvh, *p_qkvv, *p_oh, *p_ov;
    float *p_hax32, *p_vax32, *p_wt, *p_ha, *p_va;
    cudaGetSymbolAddress((void**)&p_qh_in, g_qh_in);
    cudaGetSymbolAddress((void**)&p_kv_in, g_kv_in);
    cudaGetSymbolAddress((void**)&p_xv_in, g_xv_in);
    cudaGetSymbolAddress((void**)&p_qh,    g_qh);
    cudaGetSymbolAddress((void**)&p_kvh,   g_kvh);
    cudaGetSymbolAddress((void**)&p_qkvv,  g_qkvv);
    cudaGetSymbolAddress((void**)&p_oh,    g_oh);
    cudaGetSymbolAddress((void**)&p_ov,    g_ov);
    cudaGetSymbolAddress((void**)&p_hax32, g_hax_t32);
    cudaGetSymbolAddress((void**)&p_vax32, g_vax_t32);
    cudaGetSymbolAddress((void**)&p_wt,    g_wt);
    cudaGetSymbolAddress((void**)&p_ha,    g_ha);
    cudaGetSymbolAddress((void**)&p_va,    g_va);

    dim3 tb(32, 8);
    const int GSMEM = 4 * 128 * GST * 4;   // 81920 B (2-stage A+B, stride 40)
    cudaFuncSetAttribute(gemm_t32, cudaFuncAttributeMaxDynamicSharedMemorySize, GSMEM);
    cudaFuncSetAttribute(attn_mma, cudaFuncAttributeMaxDynamicSharedMemorySize, ATT_SMEM);

    // launch 0: fused weight conversion (tf32 bits, k-permuted)
    conv_all_kernel<<<(2359296 + 255) / 256, 256>>>(h_in_w, v_in_w, h_out_w, v_out_w, hfc_w, vfc_w);

    // launches 1-3: layout transforms (emit tf32 bits, k-permuted)
    transpose_kernel<<<dim3(128, 16, 8), tb>>>(x, p_qh_in, 0);
    transpose_kernel<<<dim3(128, 16, 8), tb>>>(x, p_xv_in, 1);
    pool_kernel<<<(Bn * Cn * 256 + 255) / 256, 256>>>(x, p_kv_in);

    // launches 4-6: input projections (launch #5 = big v-proj for ncu -s 5)
    gemm_t32<<<dim3(8, 16), 256, GSMEM>>>((unsigned*)p_kv_in, (unsigned*)(p_wt + W_HIN + 512 * 512),
        h_in_b + 512, p_kvh, 0, NKV, 1024, 512, 1024, 0);
    gemm_t32<<<dim3(12, 256), 256, GSMEM>>>((unsigned*)p_xv_in, (unsigned*)(p_wt + W_VIN),
        v_in_b, p_qkvv, 0, NTOK, 1536, 512, 1536, 0);
    gemm_t32<<<dim3(4, 256), 256, GSMEM>>>((unsigned*)p_qh_in, (unsigned*)(p_wt + W_HIN),
        h_in_b, p_qh, 0, NTOK, 512, 512, 512, 0);

    // attention on tensor cores (outputs tf32 bits, k-permuted)
    attn_mma<<<dim3(32, 8, 8),  256, ATT_SMEM>>>(p_qh,   p_kvh,        p_kvh + 512,   p_oh, 8,   512,  1024, 512);
    attn_mma<<<dim3(2, 8, 128), 256, ATT_SMEM>>>(p_qkvv, p_qkvv + 512, p_qkvv + 1024, p_ov, 128, 1536, 1536, 512);

    // output projections: fp32 to d_out + permuted tf32 copy for fc heads
    gemm_t32<<<dim3(4, 256), 256, GSMEM>>>((unsigned*)p_oh, (unsigned*)(p_wt + W_HOUT),
        h_out_b, out_hax, (unsigned*)p_hax32, NTOK, 512, 512, 512, 0);
    gemm_t32<<<dim3(4, 256), 256, GSMEM>>>((unsigned*)p_ov, (unsigned*)(p_wt + W_VOUT),
        v_out_b, out_vax, (unsigned*)p_vax32, NTOK, 512, 512, 512, 1);

    // fc heads
    gemm_t32<<<dim3(3, 256), 256, GSMEM>>>((unsigned*)p_hax32, (unsigned*)(p_wt + W_HFC),
        hfc_b, p_ha, 0, NTOK, C1n, 512, C1n, 0);
    gemm_t32<<<dim3(2, 256), 256, GSMEM>>>((unsigned*)p_vax32, (unsigned*)(p_wt + W_VFC),
        vfc_b, p_va, 0, NTOK, C2n, 512, C2n, 0);

    // concat + residual stats + layernorm
    zero_stats_kernel<<<1, 32>>>();
    concat_stats_kernel<<<dim3(128, 16, 8), tb>>>(x, out_attn);
    finalize_stats_kernel<<<1, 32>>>();
    norm_kernel<<<NTOK * Cn / 256, 256>>>(out_attn, x, out_res);
}

// round 9
// speedup vs baseline: 2.3136x; 1.0316x over previous
#include <cuda_runtime.h>
#include <cstdint>
#include <math.h>

// ---------------- problem constants ----------------
#define Bn    8
#define Cn    512
#define Hn    64
#define Wn    64
#define HWn   4096          // 64*64
#define NTOK  32768         // 4096*8 tokens
#define NKV   2048          // 256*8
#define C1n   358
#define C2n   154

// ---------------- scratch (static device, no allocs) ----------------
// "perm" buffers hold tf32 bits with columns k permuted within 8-groups.
__device__ float  g_qh_in[NTOK * Cn];           // tf32 bits, perm
__device__ float  g_kv_in[NKV * Cn];            // tf32 bits, perm
__device__ float  g_xv_in[NTOK * Cn];           // tf32 bits, perm
__device__ float  g_qh   [NTOK * Cn];           // tf32 bits: Q logical
__device__ float  g_kvh  [NKV * 2 * Cn];        // tf32 bits: K perm | V logical
__device__ float  g_qkvv [(size_t)NTOK * 3 * Cn]; // tf32 bits: Q log | K perm | V log
__device__ float  g_oh   [NTOK * Cn];           // tf32 bits, perm
__device__ float  g_ov   [NTOK * Cn];           // tf32 bits, perm
__device__ float  g_hax_t32[NTOK * Cn];         // tf32 bits, perm
__device__ float  g_vax_t32[NTOK * Cn];         // tf32 bits, perm
__device__ float  g_wt  [2359296];              // tf32 bits, perm (weights)
__device__ float  g_ha  [(size_t)NTOK * C1n];
__device__ float  g_va  [(size_t)NTOK * C2n];
__device__ double g_stats[16];
__device__ float  g_mu[8];
__device__ float  g_rstd[8];

// weight offsets inside g_wt
#define W_HIN   0
#define W_VIN   786432
#define W_HOUT  1572864
#define W_VOUT  1835008
#define W_HFC   2097152
#define W_VFC   2280448

// k-permutation within 8-groups: logical pair (t, t+4) -> physical (2t, 2t+1)
__device__ __forceinline__ int pcol(int k) {
    return (k & ~7) | (((k & 3) << 1) | ((k >> 2) & 1));
}

// ---------------- tf32 helpers ----------------
__device__ __forceinline__ unsigned f2tf(float f) {
    unsigned r;
    asm("cvt.rna.tf32.f32 %0, %1;" : "=r"(r) : "f"(f));
    return r;
}

__device__ __forceinline__ void mma_tf32(float acc[4], const unsigned a[4], const unsigned b[2]) {
    asm volatile(
        "mma.sync.aligned.m16n8k8.row.col.f32.tf32.tf32.f32 "
        "{%0,%1,%2,%3}, {%4,%5,%6,%7}, {%8,%9}, {%0,%1,%2,%3};\n"
        : "+f"(acc[0]), "+f"(acc[1]), "+f"(acc[2]), "+f"(acc[3])
        : "r"(a[0]), "r"(a[1]), "r"(a[2]), "r"(a[3]), "r"(b[0]), "r"(b[1]));
}

__device__ __forceinline__ void cp16(unsigned saddr, const void* gptr, bool pred) {
    int sz = pred ? 16 : 0;
    asm volatile("cp.async.cg.shared.global [%0], [%1], 16, %2;\n"
                 :: "r"(saddr), "l"(gptr), "r"(sz));
}

// ---------------- fused weight conversion + stats zero ------------------------
__global__ void conv_all_kernel(
    const float* __restrict__ w0, const float* __restrict__ w1,
    const float* __restrict__ w2, const float* __restrict__ w3,
    const float* __restrict__ w4, const float* __restrict__ w5)
{
    int i = blockIdx.x * 256 + threadIdx.x;
    if (blockIdx.x == 0 && threadIdx.x < 16) g_stats[threadIdx.x] = 0.0;
    if (i >= 2359296) return;
    const float* src;
    int off;
    if      (i < W_VIN)  { src = w0; off = i - W_HIN;  }
    else if (i < W_HOUT) { src = w1; off = i - W_VIN;  }
    else if (i < W_VOUT) { src = w2; off = i - W_HOUT; }
    else if (i < W_HFC)  { src = w3; off = i - W_VOUT; }
    else if (i < W_VFC)  { src = w4; off = i - W_HFC;  }
    else                 { src = w5; off = i - W_VFC;  }
    int row = off >> 9, col = off & 511;
    g_wt[(i - off) + row * 512 + pcol(col)] = __uint_as_float(f2tf(src[off]));
}

// ---------------- transpose x(b,c,h,w) -> tf32 token rows [row, C] (perm) -----
__global__ void transpose_kernel(const float* __restrict__ x,
                                 float* __restrict__ out, int mode)
{
    __shared__ float tile[32][33];
    int bb = blockIdx.z;
    int l0 = blockIdx.x * 32, c0 = blockIdx.y * 32;
    int tx = threadIdx.x, ty = threadIdx.y;   // (32, 8)
#pragma unroll
    for (int j = 0; j < 4; j++) {
        int c = c0 + ty + j * 8;
        tile[ty + j * 8][tx] = x[((size_t)(bb * Cn + c)) * HWn + l0 + tx];
    }
    __syncthreads();
#pragma unroll
    for (int j = 0; j < 4; j++) {
        int l = l0 + ty + j * 8;
        int row;
        if (mode == 0) {
            row = l * Bn + bb;
        } else {
            int xx = l & 63, y = l >> 6;
            int wd = xx & 3, nwi = xx >> 2;
            row = y * 512 + wd * 128 + bb * 16 + nwi;
        }
        out[(size_t)row * Cn + pcol(c0 + tx)] = __uint_as_float(f2tf(tile[tx][ty + j * 8]));
    }
}

// ---------------- 4x4 avg pool -> tf32 kv token rows (perm) ----------------
__global__ void pool_kernel(const float* __restrict__ x, float* __restrict__ out)
{
    int idx = blockIdx.x * 256 + threadIdx.x;
    if (idx >= Bn * Cn * 256) return;
    int px = idx & 15, py = (idx >> 4) & 15, c = (idx >> 8) & 511, bb = idx >> 17;
    const float* base = x + (((size_t)(bb * Cn + c)) * Hn + py * 4) * Wn + px * 4;
    float s = 0.f;
#pragma unroll
    for (int i = 0; i < 4; i++)
#pragma unroll
        for (int j = 0; j < 4; j++) s += base[i * Wn + j];
    out[((size_t)((py * 16 + px) * Bn + bb)) * Cn + pcol(c)] = __uint_as_float(f2tf(s * 0.0625f));
}

// ---------------- tf32 tensor-core GEMM, cp.async 2-stage, 128x128 CTA tile ---
// A, Bm: tf32 bits, k-permuted, row-major [M,K] / [N,K]. M%128==0, K%32==0.
// 8 warps as 2(m) x 4(n), warp tile 64x32. Smem row stride 40 words.
// t32pk: -2 -> fp32 output (+ optional Ct32 perm tf32 copy).
//        else tf32-bit output; columns with (n>>9)==t32pk are k-permuted.
#define GST 40
__global__ __launch_bounds__(256, 2) void gemm_t32(
    const unsigned* __restrict__ A, const unsigned* __restrict__ Bm,
    const float* __restrict__ bias, float* __restrict__ Cc,
    unsigned* __restrict__ Ct32,
    int M, int N, int K, int ldc, int mode, int t32pk)
{
    extern __shared__ unsigned sm[];
    unsigned* As[2] = { sm,             sm + 128 * GST };
    unsigned* Bs[2] = { sm + 2*128*GST, sm + 3*128*GST };

    int tid  = threadIdx.x;
    int warp = tid >> 5, lane = tid & 31;
    int wm = warp & 1, wn = warp >> 1;        // 2 x 4 warps
    int g = lane >> 2, t = lane & 3;
    int m0 = blockIdx.y * 128, n0 = blockIdx.x * 128;

    float acc[4][4][4];
#pragma unroll
    for (int mi = 0; mi < 4; mi++)
#pragma unroll
        for (int ni = 0; ni < 4; ni++)
#pragma unroll
            for (int j = 0; j < 4; j++) acc[mi][ni][j] = 0.f;

    int arow = tid >> 3;             // 0..31, rows arow + i*32
    int ac   = (tid & 7) * 4;        // k-col base (physical)
    bool bpred[4];
#pragma unroll
    for (int i = 0; i < 4; i++) bpred[i] = (n0 + arow + i * 32) < N;

    const unsigned* Ab = A  + (size_t)(m0 + arow) * K + ac;
    const unsigned* Bb = Bm + (size_t)(n0 + arow) * K + ac;

    unsigned sa[2], sb[2];
#pragma unroll
    for (int s = 0; s < 2; s++) {
        sa[s] = (unsigned)__cvta_generic_to_shared(As[s]);
        sb[s] = (unsigned)__cvta_generic_to_shared(Bs[s]);
    }

#define STAGE(s, k0) do {                                                       \
    _Pragma("unroll")                                                           \
    for (int i = 0; i < 4; i++)                                                 \
        cp16(sa[s] + (unsigned)(((arow + i * 32) * GST + ac) * 4),              \
             Ab + (size_t)i * 32 * K + (k0), true);                             \
    _Pragma("unroll")                                                           \
    for (int i = 0; i < 4; i++)                                                 \
        cp16(sb[s] + (unsigned)(((arow + i * 32) * GST + ac) * 4),              \
             Bb + (size_t)i * 32 * K + (k0), bpred[i]);                         \
    asm volatile("cp.async.commit_group;\n" ::);                                \
} while (0)

    STAGE(0, 0);
    STAGE(1, 32);

    int s = 0;
    for (int k0 = 0; k0 < K; k0 += 32) {
        if (k0 + 32 < K)
            asm volatile("cp.async.wait_group 1;\n" ::);
        else
            asm volatile("cp.async.wait_group 0;\n" ::);
        __syncthreads();

        const unsigned* as = As[s];
        const unsigned* bs = Bs[s];
#pragma unroll
        for (int kk = 0; kk < 32; kk += 8) {
            unsigned af[4][4], bf[4][2];
#pragma unroll
            for (int mi = 0; mi < 4; mi++) {
                int rm = wm * 64 + mi * 16 + g;
                uint2 lo = *(const uint2*)&as[rm * GST + kk + 2 * t];
                uint2 hi = *(const uint2*)&as[(rm + 8) * GST + kk + 2 * t];
                af[mi][0] = lo.x; af[mi][2] = lo.y;
                af[mi][1] = hi.x; af[mi][3] = hi.y;
            }
#pragma unroll
            for (int ni = 0; ni < 4; ni++) {
                int rn = wn * 32 + ni * 8 + g;
                uint2 bv = *(const uint2*)&bs[rn * GST + kk + 2 * t];
                bf[ni][0] = bv.x; bf[ni][1] = bv.y;
            }
#pragma unroll
            for (int mi = 0; mi < 4; mi++)
#pragma unroll
                for (int ni = 0; ni < 4; ni++)
                    mma_tf32(acc[mi][ni], af[mi], bf[ni]);
        }
        __syncthreads();

        if (k0 + 64 < K) STAGE(s, k0 + 64);
        s ^= 1;
    }
#undef STAGE

    // epilogue
#pragma unroll
    for (int mi = 0; mi < 4; mi++) {
#pragma unroll
        for (int half = 0; half < 2; half++) {
            int m = m0 + wm * 64 + mi * 16 + g + half * 8;
            int orow;
            if (mode == 0) {
                orow = m;
            } else {
                int nwi = m & 15, bb = (m >> 4) & 7, wd = (m >> 7) & 3, y = m >> 9;
                orow = ((y << 6) + (nwi << 2) + wd) * Bn + bb;
            }
            float* cr = Cc + (size_t)orow * ldc;
            unsigned* ct = Ct32 ? Ct32 + (size_t)orow * ldc : 0;
#pragma unroll
            for (int ni = 0; ni < 4; ni++) {
                int n = n0 + wn * 32 + ni * 8 + t * 2;
                if (n < N) {
                    float v0 = acc[mi][ni][half * 2 + 0] + bias[n];
                    float v1 = acc[mi][ni][half * 2 + 1] + bias[n + 1];
                    if (t32pk == -2) {
                        cr[n] = v0; cr[n + 1] = v1;
                        if (ct) { ct[pcol(n)] = f2tf(v0); ct[pcol(n + 1)] = f2tf(v1); }
                    } else {
                        bool perm = (n >> 9) == t32pk;
                        int n0i = perm ? pcol(n) : n;
                        int n1i = perm ? pcol(n + 1) : (n + 1);
                        cr[n0i] = __uint_as_float(f2tf(v0));
                        cr[n1i] = __uint_as_float(f2tf(v1));
                    }
                }
            }
        }
    }
}

// ---------------- flash attention on tf32 tensor cores ------------------------
// CTA: 128 queries x one (head, batch). 8 warps, 16 queries/warp.
// Inputs are tf32 bits: Q logical, K perm, V logical. K/V staged via cp.async.
#define KS_S 72
#define VS_S 72
#define P_S  68
#define ATT_SMEM ((128 * KS_S + 128 * VS_S + 8 * 16 * P_S) * 4)

__global__ __launch_bounds__(256, 2) void attn_mma(
    const unsigned* __restrict__ qb, const unsigned* __restrict__ kb,
    const unsigned* __restrict__ vb, float* __restrict__ ob,
    int Bt, int qld, int kld, int oldd)
{
    extern __shared__ unsigned smu[];
    unsigned* Ks = smu;                       // [128][72], k-permuted
    unsigned* Vs = smu + 128 * KS_S;          // [128][72], logical
    int tid  = threadIdx.x;
    int warp = tid >> 5, lane = tid & 31;
    int g = lane >> 2, t = lane & 3;
    int hd = blockIdx.y, bb = blockIdx.z;
    unsigned* Pw = smu + 128 * KS_S + 128 * VS_S + warp * (16 * P_S);
    unsigned ksb = (unsigned)__cvta_generic_to_shared(Ks);
    unsigned vsb = (unsigned)__cvta_generic_to_shared(Vs);

    int qrow0 = blockIdx.x * 128 + warp * 16 + g;   // rows qrow0 and qrow0+8
    unsigned aq[8][4];
    {
        const unsigned* q0 = qb + ((size_t)(qrow0 * Bt + bb)) * qld + hd * 64;
        const unsigned* q1 = qb + ((size_t)((qrow0 + 8) * Bt + bb)) * qld + hd * 64;
#pragma unroll
        for (int ks = 0; ks < 8; ks++) {
            aq[ks][0] = f2tf(__uint_as_float(q0[ks * 8 + t])     * 0.125f);
            aq[ks][1] = f2tf(__uint_as_float(q1[ks * 8 + t])     * 0.125f);
            aq[ks][2] = f2tf(__uint_as_float(q0[ks * 8 + t + 4]) * 0.125f);
            aq[ks][3] = f2tf(__uint_as_float(q1[ks * 8 + t + 4]) * 0.125f);
        }
    }

    float o[8][4];
#pragma unroll
    for (int ni = 0; ni < 8; ni++)
#pragma unroll
        for (int j = 0; j < 4; j++) o[ni][j] = 0.f;
    float m0 = -1e30f, m1 = -1e30f, l0 = 0.f, l1 = 0.f;

    for (int chunk = 0; chunk < 2; chunk++) {
        if (chunk) __syncthreads();           // protect Ks/Vs reuse
        // stage 128 keys via cp.async (pure copy; conversion done upstream)
        for (int idx = tid; idx < 128 * 16; idx += 256) {
            int r = idx >> 4, cc = (idx & 15) * 4;
            size_t gbase = ((size_t)((chunk * 128 + r) * Bt + bb)) * kld + hd * 64 + cc;
            cp16(ksb + (unsigned)((r * KS_S + cc) * 4), kb + gbase, true);
            cp16(vsb + (unsigned)((r * VS_S + cc) * 4), vb + gbase, true);
        }
        asm volatile("cp.async.commit_group;\n" ::);
        asm volatile("cp.async.wait_group 0;\n" ::);
        __syncthreads();

        for (int kt = 0; kt < 2; kt++) {       // 2 key tiles of 64 within chunk
            float sacc[8][4];
#pragma unroll
            for (int ni = 0; ni < 8; ni++)
#pragma unroll
                for (int j = 0; j < 4; j++) sacc[ni][j] = 0.f;

            // S = (Q*scale) K^T   (B-frags via LDS.64, conflict-free)
#pragma unroll
            for (int ks = 0; ks < 8; ks++) {
#pragma unroll
                for (int ni = 0; ni < 8; ni++) {
                    int krow = kt * 64 + ni * 8 + g;
                    uint2 bv = *(const uint2*)&Ks[krow * KS_S + ks * 8 + 2 * t];
                    unsigned bf[2] = { bv.x, bv.y };
                    mma_tf32(sacc[ni], aq[ks], bf);
                }
            }

            // online softmax (rows g, g+8; quad = lanes sharing g)
            float mx0 = -1e30f, mx1 = -1e30f;
#pragma unroll
            for (int ni = 0; ni < 8; ni++) {
                mx0 = fmaxf(mx0, fmaxf(sacc[ni][0], sacc[ni][1]));
                mx1 = fmaxf(mx1, fmaxf(sacc[ni][2], sacc[ni][3]));
            }
            mx0 = fmaxf(mx0, __shfl_xor_sync(0xffffffffu, mx0, 1));
            mx0 = fmaxf(mx0, __shfl_xor_sync(0xffffffffu, mx0, 2));
            mx1 = fmaxf(mx1, __shfl_xor_sync(0xffffffffu, mx1, 1));
            mx1 = fmaxf(mx1, __shfl_xor_sync(0xffffffffu, mx1, 2));
            float mn0 = fmaxf(m0, mx0), mn1 = fmaxf(m1, mx1);
            float c0 = __expf(m0 - mn0), c1 = __expf(m1 - mn1);
            m0 = mn0; m1 = mn1;

            float rs0 = 0.f, rs1 = 0.f;
#pragma unroll
            for (int ni = 0; ni < 8; ni++) {
                float p00 = __expf(sacc[ni][0] - mn0);
                float p01 = __expf(sacc[ni][1] - mn0);
                float p10 = __expf(sacc[ni][2] - mn1);
                float p11 = __expf(sacc[ni][3] - mn1);
                rs0 += p00 + p01; rs1 += p10 + p11;
                *(uint2*)&Pw[g * P_S + ni * 8 + 2 * t]       = make_uint2(f2tf(p00), f2tf(p01));
                *(uint2*)&Pw[(g + 8) * P_S + ni * 8 + 2 * t] = make_uint2(f2tf(p10), f2tf(p11));
                o[ni][0] *= c0; o[ni][1] *= c0; o[ni][2] *= c1; o[ni][3] *= c1;
            }
            rs0 += __shfl_xor_sync(0xffffffffu, rs0, 1);
            rs0 += __shfl_xor_sync(0xffffffffu, rs0, 2);
            rs1 += __shfl_xor_sync(0xffffffffu, rs1, 1);
            rs1 += __shfl_xor_sync(0xffffffffu, rs1, 2);
            l0 = l0 * c0 + rs0;
            l1 = l1 * c1 + rs1;
            __syncwarp();

            // O += P V
#pragma unroll
            for (int ks = 0; ks < 8; ks++) {
                unsigned ap[4] = { Pw[g * P_S + ks * 8 + t],
                                   Pw[(g + 8) * P_S + ks * 8 + t],
                                   Pw[g * P_S + ks * 8 + t + 4],
                                   Pw[(g + 8) * P_S + ks * 8 + t + 4] };
                int vr0 = (kt * 64 + ks * 8 + t) * VS_S;
                int vr1 = (kt * 64 + ks * 8 + t + 4) * VS_S;
#pragma unroll
                for (int ni = 0; ni < 8; ni++) {
                    unsigned bf[2] = { Vs[vr0 + ni * 8 + g], Vs[vr1 + ni * 8 + g] };
                    mma_tf32(o[ni], ap, bf);
                }
            }
            __syncwarp();
        }
    }

    // epilogue: write tf32 bits with k-permuted columns (feeds GEMM A)
    float i0 = 1.f / l0, i1 = 1.f / l1;
    float* o0 = ob + ((size_t)(qrow0 * Bt + bb)) * oldd + hd * 64;
    float* o1 = ob + ((size_t)((qrow0 + 8) * Bt + bb)) * oldd + hd * 64;
#pragma unroll
    for (int ni = 0; ni < 8; ni++) {
        int c = ni * 8 + 2 * t;
        o0[pcol(c)]     = __uint_as_float(f2tf(o[ni][0] * i0));
        o0[pcol(c + 1)] = __uint_as_float(f2tf(o[ni][1] * i0));
        o1[pcol(c)]     = __uint_as_float(f2tf(o[ni][2] * i1));
        o1[pcol(c + 1)] = __uint_as_float(f2tf(o[ni][3] * i1));
    }
}

// ---------------- stats / concat / normalize ----------------
__global__ void concat_stats_kernel(const float* __restrict__ x, float* __restrict__ attn_out)
{
    __shared__ float tile[32][33];
    int bb = blockIdx.z;
    int l0 = blockIdx.x * 32, c0 = blockIdx.y * 32;
    int tx = threadIdx.x, ty = threadIdx.y;   // (32, 8)
#pragma unroll
    for (int j = 0; j < 4; j++) {
        int c = c0 + tx;
        int l = l0 + ty + j * 8;
        int row = l * Bn + bb;
        float v = (c < C1n) ? g_ha[(size_t)row * C1n + c]
                            : g_va[(size_t)row * C2n + (c - C1n)];
        tile[ty + j * 8][tx] = v;
    }
    __syncthreads();
    float lsum = 0.f, lsq = 0.f;
#pragma unroll
    for (int j = 0; j < 4; j++) {
        int c = c0 + ty + j * 8;
        int l = l0 + tx;
        float av = tile[tx][ty + j * 8];
        size_t gi = ((size_t)(bb * Cn + c)) * HWn + l;
        attn_out[gi] = av;
        float r = av + x[gi];
        lsum += r; lsq += r * r;
    }
#pragma unroll
    for (int off = 16; off > 0; off >>= 1) {
        lsum += __shfl_xor_sync(0xffffffffu, lsum, off);
        lsq  += __shfl_xor_sync(0xffffffffu, lsq,  off);
    }
    if (tx == 0) {
        atomicAdd(&g_stats[bb * 2 + 0], (double)lsum);
        atomicAdd(&g_stats[bb * 2 + 1], (double)lsq);
    }
}

__global__ void finalize_stats_kernel()
{
    int b = threadIdx.x;
    if (b < 8) {
        const double N = (double)Cn * HWn;
        double mu  = g_stats[2 * b + 0] / N;
        double var = g_stats[2 * b + 1] / N - mu * mu;
        g_mu[b]   = (float)mu;
        g_rstd[b] = (float)(1.0 / sqrt(var + 1e-5));
    }
}

__global__ void norm_kernel(const float* __restrict__ attn,
                            const float* __restrict__ x,
                            float* __restrict__ out)
{
    int i = blockIdx.x * 256 + threadIdx.x;
    int bb = i >> 21;
    float r = attn[i] + x[i];
    out[i] = (r - g_mu[bb]) * g_rstd[bb];
}

// ---------------- host launcher ----------------
extern "C" void kernel_launch(void* const* d_in, const int* in_sizes, int n_in,
                              void* d_out, int out_size)
{
    const float* x       = (const float*)d_in[0];
    const float* h_in_w  = (const float*)d_in[1];
    const float* h_in_b  = (const float*)d_in[2];
    const float* h_out_w = (const float*)d_in[3];
    const float* h_out_b = (const float*)d_in[4];
    const float* v_in_w  = (const float*)d_in[5];
    const float* v_in_b  = (const float*)d_in[6];
    const float* v_out_w = (const float*)d_in[7];
    const float* v_out_b = (const float*)d_in[8];
    const float* hfc_w   = (const float*)d_in[9];
    const float* hfc_b   = (const float*)d_in[10];
    const float* vfc_w   = (const float*)d_in[11];
    const float* vfc_b   = (const float*)d_in[12];

    float* out      = (float*)d_out;
    float* out_res  = out;                                   // result   [b,C,h,w]
    float* out_hax  = out + (size_t)NTOK * Cn;               // ha_x     [h,w,b,c]
    float* out_vax  = out + 2 * (size_t)NTOK * Cn;           // va_x     [h,w,b,c]
    float* out_attn = out + 3 * (size_t)NTOK * Cn;           // attn     [b,C,h,w]

    float *p_qh_in, *p_kv_in, *p_xv_in, *p_qh, *p_kvh, *p_qkvv, *p_oh, *p_ov;
    float *p_hax32, *p_vax32, *p_wt, *p_ha, *p_va;
    cudaGetSymbolAddress((void**)&p_qh_in, g_qh_in);
    cudaGetSymbolAddress((void**)&p_kv_in, g_kv_in);
    cudaGetSymbolAddress((void**)&p_xv_in, g_xv_in);
    cudaGetSymbolAddress((void**)&p_qh,    g_qh);
    cudaGetSymbolAddress((void**)&p_kvh,   g_kvh);
    cudaGetSymbolAddress((void**)&p_qkvv,  g_qkvv);
    cudaGetSymbolAddress((void**)&p_oh,    g_oh);
    cudaGetSymbolAddress((void**)&p_ov,    g_ov);
    cudaGetSymbolAddress((void**)&p_hax32, g_hax_t32);
    cudaGetSymbolAddress((void**)&p_vax32, g_vax_t32);
    cudaGetSymbolAddress((void**)&p_wt,    g_wt);
    cudaGetSymbolAddress((void**)&p_ha,    g_ha);
    cudaGetSymbolAddress((void**)&p_va,    g_va);

    dim3 tb(32, 8);
    const int GSMEM = 4 * 128 * GST * 4;   // 81920 B (2-stage A+B, stride 40)
    cudaFuncSetAttribute(gemm_t32, cudaFuncAttributeMaxDynamicSharedMemorySize, GSMEM);
    cudaFuncSetAttribute(attn_mma, cudaFuncAttributeMaxDynamicSharedMemorySize, ATT_SMEM);

    // idx 0: fused weight conversion (+ stats zero)
    conv_all_kernel<<<(2359296 + 255) / 256, 256>>>(h_in_w, v_in_w, h_out_w, v_out_w, hfc_w, vfc_w);

    // idx 1-2: transposes (mode1 first so the big v-proj can go at idx 3)
    transpose_kernel<<<dim3(128, 16, 8), tb>>>(x, p_xv_in, 1);
    transpose_kernel<<<dim3(128, 16, 8), tb>>>(x, p_qh_in, 0);

    // idx 3: big v projection  (ncu -s 5 profiles harness+2 = our idx 3)
    // outputs tf32 bits: Q logical (blk0), K perm (blk1), V logical (blk2)
    gemm_t32<<<dim3(12, 256), 256, GSMEM>>>((unsigned*)p_xv_in, (unsigned*)(p_wt + W_VIN),
        v_in_b, p_qkvv, 0, NTOK, 1536, 512, 1536, 0, 1);

    // idx 4: pool; idx 5-6: remaining input projections
    pool_kernel<<<(Bn * Cn * 256 + 255) / 256, 256>>>(x, p_kv_in);
    gemm_t32<<<dim3(8, 16), 256, GSMEM>>>((unsigned*)p_kv_in, (unsigned*)(p_wt + W_HIN + 512 * 512),
        h_in_b + 512, p_kvh, 0, NKV, 1024, 512, 1024, 0, 0);   // K perm (blk0), V logical
    gemm_t32<<<dim3(4, 256), 256, GSMEM>>>((unsigned*)p_qh_in, (unsigned*)(p_wt + W_HIN),
        h_in_b, p_qh, 0, NTOK, 512, 512, 512, 0, -1);          // Q logical

    // attention on tensor cores
    attn_mma<<<dim3(32, 8, 8),  256, ATT_SMEM>>>((unsigned*)p_qh, (unsigned*)p_kvh,
        (unsigned*)(p_kvh + 512), p_oh, 8, 512, 1024, 512);
    attn_mma<<<dim3(2, 8, 128), 256, ATT_SMEM>>>((unsigned*)p_qkvv, (unsigned*)(p_qkvv + 512),
        (unsigned*)(p_qkvv + 1024), p_ov, 128, 1536, 1536, 512);

    // output projections: fp32 to d_out + permuted tf32 copy for fc heads
    gemm_t32<<<dim3(4, 256), 256, GSMEM>>>((unsigned*)p_oh, (unsigned*)(p_wt + W_HOUT),
        h_out_b, out_hax, (unsigned*)p_hax32, NTOK, 512, 512, 512, 0, -2);
    gemm_t32<<<dim3(4, 256), 256, GSMEM>>>((unsigned*)p_ov, (unsigned*)(p_wt + W_VOUT),
        v_out_b, out_vax, (unsigned*)p_vax32, NTOK, 512, 512, 512, 1, -2);

    // fc heads
    gemm_t32<<<dim3(3, 256), 256, GSMEM>>>((unsigned*)p_hax32, (unsigned*)(p_wt + W_HFC),
        hfc_b, p_ha, 0, NTOK, C1n, 512, C1n, 0, -2);
    gemm_t32<<<dim3(2, 256), 256, GSMEM>>>((unsigned*)p_vax32, (unsigned*)(p_wt + W_VFC),
        vfc_b, p_va, 0, NTOK, C2n, 512, C2n, 0, -2);

    // concat + residual stats + layernorm
    concat_stats_kernel<<<dim3(128, 16, 8), tb>>>(x, out_attn);
    finalize_stats_kernel<<<1, 32>>>();
    norm_kernel<<<NTOK * Cn / 256, 256>>>(out_attn, x, out_res);
}

// round 10
// speedup vs baseline: 2.7986x; 1.2096x over previous
#include <cuda_runtime.h>
#include <cuda_fp16.h>
#include <cstdint>
#include <math.h>

// ---------------- problem constants ----------------
#define Bn    8
#define Cn    512
#define Hn    64
#define Wn    64
#define HWn   4096          // 64*64
#define NTOK  32768         // 4096*8 tokens
#define NKV   2048          // 256*8
#define C1n   358
#define C2n   154

// ---------------- scratch (static device, no allocs) ----------------
// __half buffers are fp16 with k permuted by p16 within 16-groups.
__device__ __align__(16) __half g_qh_in[NTOK * Cn];
__device__ __align__(16) __half g_kv_in[NKV * Cn];
__device__ __align__(16) __half g_xv_in[NTOK * Cn];
__device__ float  g_qh   [NTOK * Cn];             // tf32 bits: Q logical
__device__ float  g_kvh  [NKV * 2 * Cn];          // tf32 bits: K pcol | V logical
__device__ float  g_qkvv [(size_t)NTOK * 3 * Cn]; // tf32 bits: Q log | K pcol | V log
__device__ __align__(16) __half g_oh [NTOK * Cn]; // fp16 p16 (attn out)
__device__ __align__(16) __half g_ov [NTOK * Cn];
__device__ __align__(16) __half g_hax16[NTOK * Cn];
__device__ __align__(16) __half g_vax16[NTOK * Cn];
__device__ __align__(16) __half g_wt [2359296];   // fp16 p16 weights
__device__ float  g_ha  [(size_t)NTOK * C1n];
__device__ float  g_va  [(size_t)NTOK * C2n];
__device__ double g_stats[16];
__device__ float  g_mu[8];
__device__ float  g_rstd[8];

// weight offsets inside g_wt
#define W_HIN   0
#define W_VIN   786432
#define W_HOUT  1572864
#define W_VOUT  1835008
#define W_HFC   2097152
#define W_VFC   2280448

// tf32 8-group permutation (attention K tiles): pair (t, t+4) -> (2t, 2t+1)
__device__ __forceinline__ int pcol(int k) {
    return (k & ~7) | (((k & 3) << 1) | ((k >> 2) & 1));
}
// fp16 16-group permutation: half-pairs p=(k>>1)&7; pairs (p, p+4) adjacent
__device__ __forceinline__ int p16(int k) {
    int p = (k >> 1) & 7, o = k & 1;
    int np = ((p & 3) << 1) | (p >> 2);
    return (k & ~15) | (np << 1) | o;
}

// ---------------- helpers ----------------
__device__ __forceinline__ unsigned f2tf(float f) {
    unsigned r;
    asm("cvt.rna.tf32.f32 %0, %1;" : "=r"(r) : "f"(f));
    return r;
}

__device__ __forceinline__ void mma_tf32(float acc[4], const unsigned a[4], const unsigned b[2]) {
    asm volatile(
        "mma.sync.aligned.m16n8k8.row.col.f32.tf32.tf32.f32 "
        "{%0,%1,%2,%3}, {%4,%5,%6,%7}, {%8,%9}, {%0,%1,%2,%3};\n"
        : "+f"(acc[0]), "+f"(acc[1]), "+f"(acc[2]), "+f"(acc[3])
        : "r"(a[0]), "r"(a[1]), "r"(a[2]), "r"(a[3]), "r"(b[0]), "r"(b[1]));
}

__device__ __forceinline__ void mma_f16(float acc[4], const unsigned a[4], const unsigned b[2]) {
    asm volatile(
        "mma.sync.aligned.m16n8k16.row.col.f32.f16.f16.f32 "
        "{%0,%1,%2,%3}, {%4,%5,%6,%7}, {%8,%9}, {%0,%1,%2,%3};\n"
        : "+f"(acc[0]), "+f"(acc[1]), "+f"(acc[2]), "+f"(acc[3])
        : "r"(a[0]), "r"(a[1]), "r"(a[2]), "r"(a[3]), "r"(b[0]), "r"(b[1]));
}

__device__ __forceinline__ void cp16(unsigned saddr, const void* gptr, bool pred) {
    int sz = pred ? 16 : 0;
    asm volatile("cp.async.cg.shared.global [%0], [%1], 16, %2;\n"
                 :: "r"(saddr), "l"(gptr), "r"(sz));
}

// ---------------- fused weight conversion (fp32 -> fp16 p16) + stats zero -----
__global__ void conv_all_kernel(
    const float* __restrict__ w0, const float* __restrict__ w1,
    const float* __restrict__ w2, const float* __restrict__ w3,
    const float* __restrict__ w4, const float* __restrict__ w5)
{
    int i = blockIdx.x * 256 + threadIdx.x;
    if (blockIdx.x == 0 && threadIdx.x < 16) g_stats[threadIdx.x] = 0.0;
    if (i >= 2359296) return;
    const float* src;
    int off;
    if      (i < W_VIN)  { src = w0; off = i - W_HIN;  }
    else if (i < W_HOUT) { src = w1; off = i - W_VIN;  }
    else if (i < W_VOUT) { src = w2; off = i - W_HOUT; }
    else if (i < W_HFC)  { src = w3; off = i - W_VOUT; }
    else if (i < W_VFC)  { src = w4; off = i - W_HFC;  }
    else                 { src = w5; off = i - W_VFC;  }
    int row = off >> 9, col = off & 511;
    g_wt[(i - off) + row * 512 + p16(col)] = __float2half(src[off]);
}

// ---------------- transpose x(b,c,h,w) -> fp16 token rows [row, C] (p16) ------
__global__ void transpose_kernel(const float* __restrict__ x,
                                 __half* __restrict__ out, int mode)
{
    __shared__ float tile[32][33];
    int bb = blockIdx.z;
    int l0 = blockIdx.x * 32, c0 = blockIdx.y * 32;
    int tx = threadIdx.x, ty = threadIdx.y;   // (32, 8)
#pragma unroll
    for (int j = 0; j < 4; j++) {
        int c = c0 + ty + j * 8;
        tile[ty + j * 8][tx] = x[((size_t)(bb * Cn + c)) * HWn + l0 + tx];
    }
    __syncthreads();
#pragma unroll
    for (int j = 0; j < 4; j++) {
        int l = l0 + ty + j * 8;
        int row;
        if (mode == 0) {
            row = l * Bn + bb;
        } else {
            int xx = l & 63, y = l >> 6;
            int wd = xx & 3, nwi = xx >> 2;
            row = y * 512 + wd * 128 + bb * 16 + nwi;
        }
        out[(size_t)row * Cn + p16(c0 + tx)] = __float2half(tile[tx][ty + j * 8]);
    }
}

// ---------------- 4x4 avg pool -> fp16 kv token rows (p16) ----------------
__global__ void pool_kernel(const float* __restrict__ x, __half* __restrict__ out)
{
    int idx = blockIdx.x * 256 + threadIdx.x;
    if (idx >= Bn * Cn * 256) return;
    int px = idx & 15, py = (idx >> 4) & 15, c = (idx >> 8) & 511, bb = idx >> 17;
    const float* base = x + (((size_t)(bb * Cn + c)) * Hn + py * 4) * Wn + px * 4;
    float s = 0.f;
#pragma unroll
    for (int i = 0; i < 4; i++)
#pragma unroll
        for (int j = 0; j < 4; j++) s += base[i * Wn + j];
    out[((size_t)((py * 16 + px) * Bn + bb)) * Cn + p16(c)] = __float2half(s * 0.0625f);
}

// ---------------- fp16 tensor-core GEMM, cp.async 2-stage, 128x128 CTA tile ---
// A, Bm: fp16 p16-permuted, row-major [M,K] / [N,K]. M%128==0, K%64==0.
// 8 warps as 2(m) x 4(n), warp tile 64x32, k-chunk 64 halves (128B data/row).
// Smem row stride 40 words = 80 halves (per-phase conflict-free LDS.64).
// t32pk: -2 -> fp32 out to Cc (+ optional fp16-p16 copy to Ct16);
//        else tf32-bit out to Cc; 512-block (n>>9)==t32pk gets pcol perm.
#define GST 40
__global__ __launch_bounds__(256, 2) void gemm_f16(
    const __half* __restrict__ A, const __half* __restrict__ Bm,
    const float* __restrict__ bias, float* __restrict__ Cc,
    __half* __restrict__ Ct16,
    int M, int N, int K, int ldc, int mode, int t32pk)
{
    extern __shared__ __align__(16) __half smh[];
    const int RS = GST * 2;                  // 80 halves per row
    __half* As[2] = { smh,             smh + 128 * RS };
    __half* Bs[2] = { smh + 2*128*RS,  smh + 3*128*RS };

    int tid  = threadIdx.x;
    int warp = tid >> 5, lane = tid & 31;
    int wm = warp & 1, wn = warp >> 1;        // 2 x 4 warps
    int g = lane >> 2, t = lane & 3;
    int m0 = blockIdx.y * 128, n0 = blockIdx.x * 128;

    float acc[4][4][4];
#pragma unroll
    for (int mi = 0; mi < 4; mi++)
#pragma unroll
        for (int ni = 0; ni < 4; ni++)
#pragma unroll
            for (int j = 0; j < 4; j++) acc[mi][ni][j] = 0.f;

    unsigned sa[2], sb[2];
#pragma unroll
    for (int s = 0; s < 2; s++) {
        sa[s] = (unsigned)__cvta_generic_to_shared(As[s]);
        sb[s] = (unsigned)__cvta_generic_to_shared(Bs[s]);
    }

    // staging: 1024 16B-chunks per tile (128 rows x 8 chunks), 4 per thread
#define STAGE(s, k0) do {                                                       \
    _Pragma("unroll")                                                           \
    for (int i = 0; i < 4; i++) {                                               \
        int chunk = i * 256 + tid;                                              \
        int r = chunk >> 3, c8 = (chunk & 7) * 8;                               \
        cp16(sa[s] + (unsigned)((r * RS + c8) * 2),                             \
             A + (size_t)(m0 + r) * K + (k0) + c8, true);                       \
        cp16(sb[s] + (unsigned)((r * RS + c8) * 2),                             \
             Bm + (size_t)(n0 + r) * K + (k0) + c8, (n0 + r) < N);              \
    }                                                                           \
    asm volatile("cp.async.commit_group;\n" ::);                                \
} while (0)

    STAGE(0, 0);
    STAGE(1, 64);

    int s = 0;
    for (int k0 = 0; k0 < K; k0 += 64) {
        if (k0 + 64 < K)
            asm volatile("cp.async.wait_group 1;\n" ::);
        else
            asm volatile("cp.async.wait_group 0;\n" ::);
        __syncthreads();

        const __half* as = As[s];
        const __half* bs = Bs[s];
#pragma unroll
        for (int kk = 0; kk < 64; kk += 16) {
            unsigned af[4][4], bf[4][2];
#pragma unroll
            for (int mi = 0; mi < 4; mi++) {
                int rm = wm * 64 + mi * 16 + g;
                uint2 lo = *(const uint2*)&as[rm * RS + kk + 4 * t];
                uint2 hi = *(const uint2*)&as[(rm + 8) * RS + kk + 4 * t];
                af[mi][0] = lo.x; af[mi][2] = lo.y;   // row rm: k-pairs t, t+4
                af[mi][1] = hi.x; af[mi][3] = hi.y;   // row rm+8
            }
#pragma unroll
            for (int ni = 0; ni < 4; ni++) {
                int rn = wn * 32 + ni * 8 + g;
                uint2 bv = *(const uint2*)&bs[rn * RS + kk + 4 * t];
                bf[ni][0] = bv.x; bf[ni][1] = bv.y;
            }
#pragma unroll
            for (int mi = 0; mi < 4; mi++)
#pragma unroll
                for (int ni = 0; ni < 4; ni++)
                    mma_f16(acc[mi][ni], af[mi], bf[ni]);
        }
        __syncthreads();

        if (k0 + 128 < K) STAGE(s, k0 + 128);
        s ^= 1;
    }
#undef STAGE

    // epilogue
#pragma unroll
    for (int mi = 0; mi < 4; mi++) {
#pragma unroll
        for (int half = 0; half < 2; half++) {
            int m = m0 + wm * 64 + mi * 16 + g + half * 8;
            int orow;
            if (mode == 0) {
                orow = m;
            } else {
                int nwi = m & 15, bb = (m >> 4) & 7, wd = (m >> 7) & 3, y = m >> 9;
                orow = ((y << 6) + (nwi << 2) + wd) * Bn + bb;
            }
            float* cr = Cc + (size_t)orow * ldc;
            __half* ct = Ct16 ? Ct16 + (size_t)orow * ldc : 0;
#pragma unroll
            for (int ni = 0; ni < 4; ni++) {
                int n = n0 + wn * 32 + ni * 8 + t * 2;
                if (n < N) {
                    float v0 = acc[mi][ni][half * 2 + 0] + bias[n];
                    float v1 = acc[mi][ni][half * 2 + 1] + bias[n + 1];
                    if (t32pk == -2) {
                        cr[n] = v0; cr[n + 1] = v1;
                        if (ct) { ct[p16(n)] = __float2half(v0); ct[p16(n + 1)] = __float2half(v1); }
                    } else {
                        bool perm = (n >> 9) == t32pk;
                        int n0i = perm ? pcol(n) : n;
                        int n1i = perm ? pcol(n + 1) : (n + 1);
                        cr[n0i] = __uint_as_float(f2tf(v0));
                        cr[n1i] = __uint_as_float(f2tf(v1));
                    }
                }
            }
        }
    }
}

// ---------------- flash attention on tf32 tensor cores ------------------------
// CTA: 128 queries x one (head, batch). 8 warps, 16 queries/warp.
// Inputs: tf32 bits (Q logical, K pcol, V logical). Output: fp16 p16.
#define KS_S 72
#define VS_S 72
#define P_S  68
#define ATT_SMEM ((128 * KS_S + 128 * VS_S + 8 * 16 * P_S) * 4)

__global__ __launch_bounds__(256, 2) void attn_mma(
    const unsigned* __restrict__ qb, const unsigned* __restrict__ kb,
    const unsigned* __restrict__ vb, __half* __restrict__ ob,
    int Bt, int qld, int kld, int oldd)
{
    extern __shared__ unsigned smu[];
    unsigned* Ks = smu;                       // [128][72], pcol-permuted
    unsigned* Vs = smu + 128 * KS_S;          // [128][72], logical
    int tid  = threadIdx.x;
    int warp = tid >> 5, lane = tid & 31;
    int g = lane >> 2, t = lane & 3;
    int hd = blockIdx.y, bb = blockIdx.z;
    unsigned* Pw = smu + 128 * KS_S + 128 * VS_S + warp * (16 * P_S);
    unsigned ksb = (unsigned)__cvta_generic_to_shared(Ks);
    unsigned vsb = (unsigned)__cvta_generic_to_shared(Vs);

    int qrow0 = blockIdx.x * 128 + warp * 16 + g;   // rows qrow0 and qrow0+8
    unsigned aq[8][4];
    {
        const unsigned* q0 = qb + ((size_t)(qrow0 * Bt + bb)) * qld + hd * 64;
        const unsigned* q1 = qb + ((size_t)((qrow0 + 8) * Bt + bb)) * qld + hd * 64;
#pragma unroll
        for (int ks = 0; ks < 8; ks++) {
            aq[ks][0] = f2tf(__uint_as_float(q0[ks * 8 + t])     * 0.125f);
            aq[ks][1] = f2tf(__uint_as_float(q1[ks * 8 + t])     * 0.125f);
            aq[ks][2] = f2tf(__uint_as_float(q0[ks * 8 + t + 4]) * 0.125f);
            aq[ks][3] = f2tf(__uint_as_float(q1[ks * 8 + t + 4]) * 0.125f);
        }
    }

    float o[8][4];
#pragma unroll
    for (int ni = 0; ni < 8; ni++)
#pragma unroll
        for (int j = 0; j < 4; j++) o[ni][j] = 0.f;
    float m0 = -1e30f, m1 = -1e30f, l0 = 0.f, l1 = 0.f;

    for (int chunk = 0; chunk < 2; chunk++) {
        if (chunk) __syncthreads();           // protect Ks/Vs reuse
        for (int idx = tid; idx < 128 * 16; idx += 256) {
            int r = idx >> 4, cc = (idx & 15) * 4;
            size_t gbase = ((size_t)((chunk * 128 + r) * Bt + bb)) * kld + hd * 64 + cc;
            cp16(ksb + (unsigned)((r * KS_S + cc) * 4), kb + gbase, true);
            cp16(vsb + (unsigned)((r * VS_S + cc) * 4), vb + gbase, true);
        }
        asm volatile("cp.async.commit_group;\n" ::);
        asm volatile("cp.async.wait_group 0;\n" ::);
        __syncthreads();

        for (int kt = 0; kt < 2; kt++) {       // 2 key tiles of 64 within chunk
            float sacc[8][4];
#pragma unroll
            for (int ni = 0; ni < 8; ni++)
#pragma unroll
                for (int j = 0; j < 4; j++) sacc[ni][j] = 0.f;

#pragma unroll
            for (int ks = 0; ks < 8; ks++) {
#pragma unroll
                for (int ni = 0; ni < 8; ni++) {
                    int krow = kt * 64 + ni * 8 + g;
                    uint2 bv = *(const uint2*)&Ks[krow * KS_S + ks * 8 + 2 * t];
                    unsigned bf[2] = { bv.x, bv.y };
                    mma_tf32(sacc[ni], aq[ks], bf);
                }
            }

            float mx0 = -1e30f, mx1 = -1e30f;
#pragma unroll
            for (int ni = 0; ni < 8; ni++) {
                mx0 = fmaxf(mx0, fmaxf(sacc[ni][0], sacc[ni][1]));
                mx1 = fmaxf(mx1, fmaxf(sacc[ni][2], sacc[ni][3]));
            }
            mx0 = fmaxf(mx0, __shfl_xor_sync(0xffffffffu, mx0, 1));
            mx0 = fmaxf(mx0, __shfl_xor_sync(0xffffffffu, mx0, 2));
            mx1 = fmaxf(mx1, __shfl_xor_sync(0xffffffffu, mx1, 1));
            mx1 = fmaxf(mx1, __shfl_xor_sync(0xffffffffu, mx1, 2));
            float mn0 = fmaxf(m0, mx0), mn1 = fmaxf(m1, mx1);
            float c0 = __expf(m0 - mn0), c1 = __expf(m1 - mn1);
            m0 = mn0; m1 = mn1;

            float rs0 = 0.f, rs1 = 0.f;
#pragma unroll
            for (int ni = 0; ni < 8; ni++) {
                float p00 = __expf(sacc[ni][0] - mn0);
                float p01 = __expf(sacc[ni][1] - mn0);
                float p10 = __expf(sacc[ni][2] - mn1);
                float p11 = __expf(sacc[ni][3] - mn1);
                rs0 += p00 + p01; rs1 += p10 + p11;
                *(uint2*)&Pw[g * P_S + ni * 8 + 2 * t]       = make_uint2(f2tf(p00), f2tf(p01));
                *(uint2*)&Pw[(g + 8) * P_S + ni * 8 + 2 * t] = make_uint2(f2tf(p10), f2tf(p11));
                o[ni][0] *= c0; o[ni][1] *= c0; o[ni][2] *= c1; o[ni][3] *= c1;
            }
            rs0 += __shfl_xor_sync(0xffffffffu, rs0, 1);
            rs0 += __shfl_xor_sync(0xffffffffu, rs0, 2);
            rs1 += __shfl_xor_sync(0xffffffffu, rs1, 1);
            rs1 += __shfl_xor_sync(0xffffffffu, rs1, 2);
            l0 = l0 * c0 + rs0;
            l1 = l1 * c1 + rs1;
            __syncwarp();

#pragma unroll
            for (int ks = 0; ks < 8; ks++) {
                unsigned ap[4] = { Pw[g * P_S + ks * 8 + t],
                                   Pw[(g + 8) * P_S + ks * 8 + t],
                                   Pw[g * P_S + ks * 8 + t + 4],
                                   Pw[(g + 8) * P_S + ks * 8 + t + 4] };
                int vr0 = (kt * 64 + ks * 8 + t) * VS_S;
                int vr1 = (kt * 64 + ks * 8 + t + 4) * VS_S;
#pragma unroll
                for (int ni = 0; ni < 8; ni++) {
                    unsigned bf[2] = { Vs[vr0 + ni * 8 + g], Vs[vr1 + ni * 8 + g] };
                    mma_tf32(o[ni], ap, bf);
                }
            }
            __syncwarp();
        }
    }

    // epilogue: write fp16 p16 (feeds the fp16 out-projection GEMM)
    float i0 = 1.f / l0, i1 = 1.f / l1;
    __half* o0 = ob + ((size_t)(qrow0 * Bt + bb)) * oldd + hd * 64;
    __half* o1 = ob + ((size_t)((qrow0 + 8) * Bt + bb)) * oldd + hd * 64;
#pragma unroll
    for (int ni = 0; ni < 8; ni++) {
        int c = ni * 8 + 2 * t;
        o0[p16(c)]     = __float2half(o[ni][0] * i0);
        o0[p16(c + 1)] = __float2half(o[ni][1] * i0);
        o1[p16(c)]     = __float2half(o[ni][2] * i1);
        o1[p16(c + 1)] = __float2half(o[ni][3] * i1);
    }
}

// ---------------- stats / concat / normalize ----------------
__global__ void concat_stats_kernel(const float* __restrict__ x, float* __restrict__ attn_out)
{
    __shared__ float tile[32][33];
    int bb = blockIdx.z;
    int l0 = blockIdx.x * 32, c0 = blockIdx.y * 32;
    int tx = threadIdx.x, ty = threadIdx.y;   // (32, 8)
#pragma unroll
    for (int j = 0; j < 4; j++) {
        int c = c0 + tx;
        int l = l0 + ty + j * 8;
        int row = l * Bn + bb;
        float v = (c < C1n) ? g_ha[(size_t)row * C1n + c]
                            : g_va[(size_t)row * C2n + (c - C1n)];
        tile[ty + j * 8][tx] = v;
    }
    __syncthreads();
    float lsum = 0.f, lsq = 0.f;
#pragma unroll
    for (int j = 0; j < 4; j++) {
        int c = c0 + ty + j * 8;
        int l = l0 + tx;
        float av = tile[tx][ty + j * 8];
        size_t gi = ((size_t)(bb * Cn + c)) * HWn + l;
        attn_out[gi] = av;
        float r = av + x[gi];
        lsum += r; lsq += r * r;
    }
#pragma unroll
    for (int off = 16; off > 0; off >>= 1) {
        lsum += __shfl_xor_sync(0xffffffffu, lsum, off);
        lsq  += __shfl_xor_sync(0xffffffffu, lsq,  off);
    }
    if (tx == 0) {
        atomicAdd(&g_stats[bb * 2 + 0], (double)lsum);
        atomicAdd(&g_stats[bb * 2 + 1], (double)lsq);
    }
}

__global__ void finalize_stats_kernel()
{
    int b = threadIdx.x;
    if (b < 8) {
        const double N = (double)Cn * HWn;
        double mu  = g_stats[2 * b + 0] / N;
        double var = g_stats[2 * b + 1] / N - mu * mu;
        g_mu[b]   = (float)mu;
        g_rstd[b] = (float)(1.0 / sqrt(var + 1e-5));
    }
}

__global__ void norm_kernel(const float* __restrict__ attn,
                            const float* __restrict__ x,
                            float* __restrict__ out)
{
    int i = blockIdx.x * 256 + threadIdx.x;
    int bb = i >> 21;
    float r = attn[i] + x[i];
    out[i] = (r - g_mu[bb]) * g_rstd[bb];
}

// ---------------- host launcher ----------------
extern "C" void kernel_launch(void* const* d_in, const int* in_sizes, int n_in,
                              void* d_out, int out_size)
{
    const float* x       = (const float*)d_in[0];
    const float* h_in_w  = (const float*)d_in[1];
    const float* h_in_b  = (const float*)d_in[2];
    const float* h_out_w = (const float*)d_in[3];
    const float* h_out_b = (const float*)d_in[4];
    const float* v_in_w  = (const float*)d_in[5];
    const float* v_in_b  = (const float*)d_in[6];
    const float* v_out_w = (const float*)d_in[7];
    const float* v_out_b = (const float*)d_in[8];
    const float* hfc_w   = (const float*)d_in[9];
    const float* hfc_b   = (const float*)d_in[10];
    const float* vfc_w   = (const float*)d_in[11];
    const float* vfc_b   = (const float*)d_in[12];

    float* out      = (float*)d_out;
    float* out_res  = out;                                   // result   [b,C,h,w]
    float* out_hax  = out + (size_t)NTOK * Cn;               // ha_x     [h,w,b,c]
    float* out_vax  = out + 2 * (size_t)NTOK * Cn;           // va_x     [h,w,b,c]
    float* out_attn = out + 3 * (size_t)NTOK * Cn;           // attn     [b,C,h,w]

    __half *p_qh_in, *p_kv_in, *p_xv_in, *p_oh, *p_ov, *p_hax16, *p_vax16, *p_wt;
    float *p_qh, *p_kvh, *p_qkvv, *p_ha, *p_va;
    cudaGetSymbolAddress((void**)&p_qh_in, g_qh_in);
    cudaGetSymbolAddress((void**)&p_kv_in, g_kv_in);
    cudaGetSymbolAddress((void**)&p_xv_in, g_xv_in);
    cudaGetSymbolAddress((void**)&p_qh,    g_qh);
    cudaGetSymbolAddress((void**)&p_kvh,   g_kvh);
    cudaGetSymbolAddress((void**)&p_qkvv,  g_qkvv);
    cudaGetSymbolAddress((void**)&p_oh,    g_oh);
    cudaGetSymbolAddress((void**)&p_ov,    g_ov);
    cudaGetSymbolAddress((void**)&p_hax16, g_hax16);
    cudaGetSymbolAddress((void**)&p_vax16, g_vax16);
    cudaGetSymbolAddress((void**)&p_wt,    g_wt);
    cudaGetSymbolAddress((void**)&p_ha,    g_ha);
    cudaGetSymbolAddress((void**)&p_va,    g_va);

    dim3 tb(32, 8);
    const int GSMEM = 4 * 128 * GST * 4;   // 81920 B (2-stage A+B, 160B rows)
    cudaFuncSetAttribute(gemm_f16, cudaFuncAttributeMaxDynamicSharedMemorySize, GSMEM);
    cudaFuncSetAttribute(attn_mma, cudaFuncAttributeMaxDynamicSharedMemorySize, ATT_SMEM);

    // idx 0: fused weight conversion (+ stats zero)
    conv_all_kernel<<<(2359296 + 255) / 256, 256>>>(h_in_w, v_in_w, h_out_w, v_out_w, hfc_w, vfc_w);

    // idx 1-2: transposes
    transpose_kernel<<<dim3(128, 16, 8), tb>>>(x, p_xv_in, 1);
    transpose_kernel<<<dim3(128, 16, 8), tb>>>(x, p_qh_in, 0);

    // idx 3: big v projection (profiled by ncu -s 5)
    gemm_f16<<<dim3(12, 256), 256, GSMEM>>>(p_xv_in, p_wt + W_VIN,
        v_in_b, p_qkvv, 0, NTOK, 1536, 512, 1536, 0, 1);   // Q log | K pcol | V log

    // idx 4: pool; idx 5-6: remaining input projections
    pool_kernel<<<(Bn * Cn * 256 + 255) / 256, 256>>>(x, p_kv_in);
    gemm_f16<<<dim3(8, 16), 256, GSMEM>>>(p_kv_in, p_wt + W_HIN + 512 * 512,
        h_in_b + 512, p_kvh, 0, NKV, 1024, 512, 1024, 0, 0);   // K pcol | V log
    gemm_f16<<<dim3(4, 256), 256, GSMEM>>>(p_qh_in, p_wt + W_HIN,
        h_in_b, p_qh, 0, NTOK, 512, 512, 512, 0, -1);          // Q logical

    // attention (tf32 tensor cores; outputs fp16 p16)
    attn_mma<<<dim3(32, 8, 8),  256, ATT_SMEM>>>((unsigned*)p_qh, (unsigned*)p_kvh,
        (unsigned*)(p_kvh + 512), p_oh, 8, 512, 1024, 512);
    attn_mma<<<dim3(2, 8, 128), 256, ATT_SMEM>>>((unsigned*)p_qkvv, (unsigned*)(p_qkvv + 512),
        (unsigned*)(p_qkvv + 1024), p_ov, 128, 1536, 1536, 512);

    // output projections: fp32 to d_out + fp16-p16 copy for fc heads
    gemm_f16<<<dim3(4, 256), 256, GSMEM>>>(p_oh, p_wt + W_HOUT,
        h_out_b, out_hax, p_hax16, NTOK, 512, 512, 512, 0, -2);
    gemm_f16<<<dim3(4, 256), 256, GSMEM>>>(p_ov, p_wt + W_VOUT,
        v_out_b, out_vax, p_vax16, NTOK, 512, 512, 512, 1, -2);

    // fc heads
    gemm_f16<<<dim3(3, 256), 256, GSMEM>>>(p_hax16, p_wt + W_HFC,
        hfc_b, p_ha, 0, NTOK, C1n, 512, C1n, 0, -2);
    gemm_f16<<<dim3(2, 256), 256, GSMEM>>>(p_vax16, p_wt + W_VFC,
        vfc_b, p_va, 0, NTOK, C2n, 512, C2n, 0, -2);

    // concat + residual stats + layernorm
    concat_stats_kernel<<<dim3(128, 16, 8), tb>>>(x, out_attn);
    finalize_stats_kernel<<<1, 32>>>();
    norm_kernel<<<NTOK * Cn / 256, 256>>>(out_attn, x, out_res);
}

// round 11
// speedup vs baseline: 3.4065x; 1.2172x over previous
#include <cuda_runtime.h>
#include <cuda_fp16.h>
#include <cstdint>
#include <math.h>

// ---------------- problem constants ----------------
#define Bn    8
#define Cn    512
#define Hn    64
#define Wn    64
#define HWn   4096          // 64*64
#define NTOK  32768         // 4096*8 tokens
#define NKV   2048          // 256*8
#define C1n   358
#define C2n   154

// ---------------- scratch (static device, no allocs) ----------------
// fp16 buffers: k-dim permuted by p16 unless noted "logical".
__device__ __align__(16) __half g_qh_in[NTOK * Cn];
__device__ __align__(16) __half g_kv_in[NKV * Cn];
__device__ __align__(16) __half g_xv_in[NTOK * Cn];
__device__ __align__(16) __half g_qh  [NTOK * Cn];           // Q p16
__device__ __align__(16) __half g_kvh [NKV * 2 * Cn];        // K p16 | V logical
__device__ __align__(16) __half g_qkvv[(size_t)NTOK * 3 * Cn]; // Q p16 | K p16 | V logical
__device__ __align__(16) __half g_oh  [NTOK * Cn];           // attn out, p16
__device__ __align__(16) __half g_ov  [NTOK * Cn];
__device__ __align__(16) __half g_hax16[NTOK * Cn];
__device__ __align__(16) __half g_vax16[NTOK * Cn];
__device__ __align__(16) __half g_wt [2359296];              // weights p16
__device__ float  g_ha  [(size_t)NTOK * C1n];
__device__ float  g_va  [(size_t)NTOK * C2n];
__device__ double g_stats[16];
__device__ float  g_mu[8];
__device__ float  g_rstd[8];

// weight offsets inside g_wt
#define W_HIN   0
#define W_VIN   786432
#define W_HOUT  1572864
#define W_VOUT  1835008
#define W_HFC   2097152
#define W_VFC   2280448

// fp16 16-group permutation: half-pairs p=(k>>1)&7; pairs (p, p+4) adjacent
__device__ __forceinline__ int p16(int k) {
    int p = (k >> 1) & 7, o = k & 1;
    int np = ((p & 3) << 1) | (p >> 2);
    return (k & ~15) | (np << 1) | o;
}

// ---------------- helpers ----------------
__device__ __forceinline__ void mma_f16(float acc[4], const unsigned a[4], const unsigned b[2]) {
    asm volatile(
        "mma.sync.aligned.m16n8k16.row.col.f32.f16.f16.f32 "
        "{%0,%1,%2,%3}, {%4,%5,%6,%7}, {%8,%9}, {%0,%1,%2,%3};\n"
        : "+f"(acc[0]), "+f"(acc[1]), "+f"(acc[2]), "+f"(acc[3])
        : "r"(a[0]), "r"(a[1]), "r"(a[2]), "r"(a[3]), "r"(b[0]), "r"(b[1]));
}

__device__ __forceinline__ void cp16(unsigned saddr, const void* gptr, bool pred) {
    int sz = pred ? 16 : 0;
    asm volatile("cp.async.cg.shared.global [%0], [%1], 16, %2;\n"
                 :: "r"(saddr), "l"(gptr), "r"(sz));
}

// ---------------- fused weight conversion (fp32 -> fp16 p16) + stats zero -----
__global__ void conv_all_kernel(
    const float* __restrict__ w0, const float* __restrict__ w1,
    const float* __restrict__ w2, const float* __restrict__ w3,
    const float* __restrict__ w4, const float* __restrict__ w5)
{
    int i = blockIdx.x * 256 + threadIdx.x;
    if (blockIdx.x == 0 && threadIdx.x < 16) g_stats[threadIdx.x] = 0.0;
    if (i >= 2359296) return;
    const float* src;
    int off;
    if      (i < W_VIN)  { src = w0; off = i - W_HIN;  }
    else if (i < W_HOUT) { src = w1; off = i - W_VIN;  }
    else if (i < W_VOUT) { src = w2; off = i - W_HOUT; }
    else if (i < W_HFC)  { src = w3; off = i - W_VOUT; }
    else if (i < W_VFC)  { src = w4; off = i - W_HFC;  }
    else                 { src = w5; off = i - W_VFC;  }
    int row = off >> 9, col = off & 511;
    g_wt[(i - off) + row * 512 + p16(col)] = __float2half(src[off]);
}

// ---------------- transpose x(b,c,h,w) -> fp16 token rows [row, C] (p16) ------
__global__ void transpose_kernel(const float* __restrict__ x,
                                 __half* __restrict__ out, int mode)
{
    __shared__ float tile[32][33];
    int bb = blockIdx.z;
    int l0 = blockIdx.x * 32, c0 = blockIdx.y * 32;
    int tx = threadIdx.x, ty = threadIdx.y;   // (32, 8)
#pragma unroll
    for (int j = 0; j < 4; j++) {
        int c = c0 + ty + j * 8;
        tile[ty + j * 8][tx] = x[((size_t)(bb * Cn + c)) * HWn + l0 + tx];
    }
    __syncthreads();
#pragma unroll
    for (int j = 0; j < 4; j++) {
        int l = l0 + ty + j * 8;
        int row;
        if (mode == 0) {
            row = l * Bn + bb;
        } else {
            int xx = l & 63, y = l >> 6;
            int wd = xx & 3, nwi = xx >> 2;
            row = y * 512 + wd * 128 + bb * 16 + nwi;
        }
        out[(size_t)row * Cn + p16(c0 + tx)] = __float2half(tile[tx][ty + j * 8]);
    }
}

// ---------------- 4x4 avg pool -> fp16 kv token rows (p16) ----------------
__global__ void pool_kernel(const float* __restrict__ x, __half* __restrict__ out)
{
    int idx = blockIdx.x * 256 + threadIdx.x;
    if (idx >= Bn * Cn * 256) return;
    int px = idx & 15, py = (idx >> 4) & 15, c = (idx >> 8) & 511, bb = idx >> 17;
    const float* base = x + (((size_t)(bb * Cn + c)) * Hn + py * 4) * Wn + px * 4;
    float s = 0.f;
#pragma unroll
    for (int i = 0; i < 4; i++)
#pragma unroll
        for (int j = 0; j < 4; j++) s += base[i * Wn + j];
    out[((size_t)((py * 16 + px) * Bn + bb)) * Cn + p16(c)] = __float2half(s * 0.0625f);
}

// ---------------- fp16 tensor-core GEMM, cp.async 2-stage, 128x128 CTA tile ---
// A, Bm: fp16 p16-permuted, row-major [M,K] / [N,K]. M%128==0, K%64==0.
// 8 warps as 2(m) x 4(n), warp tile 64x32, k-chunk 64 halves.
// omask: -2 -> fp32 out to Cc (+ optional fp16-p16 copy to Ct16);
//        else fp16 out to (half*)Cc; 512-block b gets p16 iff (omask>>b)&1.
#define GST 40
__global__ __launch_bounds__(256, 2) void gemm_f16(
    const __half* __restrict__ A, const __half* __restrict__ Bm,
    const float* __restrict__ bias, float* __restrict__ Cc,
    __half* __restrict__ Ct16,
    int M, int N, int K, int ldc, int mode, int omask)
{
    extern __shared__ __align__(16) __half smh[];
    const int RS = GST * 2;                  // 80 halves per row
    __half* As[2] = { smh,             smh + 128 * RS };
    __half* Bs[2] = { smh + 2*128*RS,  smh + 3*128*RS };

    int tid  = threadIdx.x;
    int warp = tid >> 5, lane = tid & 31;
    int wm = warp & 1, wn = warp >> 1;        // 2 x 4 warps
    int g = lane >> 2, t = lane & 3;
    int m0 = blockIdx.y * 128, n0 = blockIdx.x * 128;

    float acc[4][4][4];
#pragma unroll
    for (int mi = 0; mi < 4; mi++)
#pragma unroll
        for (int ni = 0; ni < 4; ni++)
#pragma unroll
            for (int j = 0; j < 4; j++) acc[mi][ni][j] = 0.f;

    unsigned sa[2], sb[2];
#pragma unroll
    for (int s = 0; s < 2; s++) {
        sa[s] = (unsigned)__cvta_generic_to_shared(As[s]);
        sb[s] = (unsigned)__cvta_generic_to_shared(Bs[s]);
    }

#define STAGE(s, k0) do {                                                       \
    _Pragma("unroll")                                                           \
    for (int i = 0; i < 4; i++) {                                               \
        int chunk = i * 256 + tid;                                              \
        int r = chunk >> 3, c8 = (chunk & 7) * 8;                               \
        cp16(sa[s] + (unsigned)((r * RS + c8) * 2),                             \
             A + (size_t)(m0 + r) * K + (k0) + c8, true);                       \
        cp16(sb[s] + (unsigned)((r * RS + c8) * 2),                             \
             Bm + (size_t)(n0 + r) * K + (k0) + c8, (n0 + r) < N);              \
    }                                                                           \
    asm volatile("cp.async.commit_group;\n" ::);                                \
} while (0)

    STAGE(0, 0);
    STAGE(1, 64);

    int s = 0;
    for (int k0 = 0; k0 < K; k0 += 64) {
        if (k0 + 64 < K)
            asm volatile("cp.async.wait_group 1;\n" ::);
        else
            asm volatile("cp.async.wait_group 0;\n" ::);
        __syncthreads();

        const __half* as = As[s];
        const __half* bs = Bs[s];
#pragma unroll
        for (int kk = 0; kk < 64; kk += 16) {
            unsigned af[4][4], bf[4][2];
#pragma unroll
            for (int mi = 0; mi < 4; mi++) {
                int rm = wm * 64 + mi * 16 + g;
                uint2 lo = *(const uint2*)&as[rm * RS + kk + 4 * t];
                uint2 hi = *(const uint2*)&as[(rm + 8) * RS + kk + 4 * t];
                af[mi][0] = lo.x; af[mi][2] = lo.y;
                af[mi][1] = hi.x; af[mi][3] = hi.y;
            }
#pragma unroll
            for (int ni = 0; ni < 4; ni++) {
                int rn = wn * 32 + ni * 8 + g;
                uint2 bv = *(const uint2*)&bs[rn * RS + kk + 4 * t];
                bf[ni][0] = bv.x; bf[ni][1] = bv.y;
            }
#pragma unroll
            for (int mi = 0; mi < 4; mi++)
#pragma unroll
                for (int ni = 0; ni < 4; ni++)
                    mma_f16(acc[mi][ni], af[mi], bf[ni]);
        }
        __syncthreads();

        if (k0 + 128 < K) STAGE(s, k0 + 128);
        s ^= 1;
    }
#undef STAGE

    // epilogue
#pragma unroll
    for (int mi = 0; mi < 4; mi++) {
#pragma unroll
        for (int half = 0; half < 2; half++) {
            int m = m0 + wm * 64 + mi * 16 + g + half * 8;
            int orow;
            if (mode == 0) {
                orow = m;
            } else {
                int nwi = m & 15, bb = (m >> 4) & 7, wd = (m >> 7) & 3, y = m >> 9;
                orow = ((y << 6) + (nwi << 2) + wd) * Bn + bb;
            }
#pragma unroll
            for (int ni = 0; ni < 4; ni++) {
                int n = n0 + wn * 32 + ni * 8 + t * 2;
                if (n < N) {
                    float v0 = acc[mi][ni][half * 2 + 0] + bias[n];
                    float v1 = acc[mi][ni][half * 2 + 1] + bias[n + 1];
                    if (omask == -2) {
                        float* cr = Cc + (size_t)orow * ldc;
                        cr[n] = v0; cr[n + 1] = v1;
                        if (Ct16) {
                            __half2 hv = __floats2half2_rn(v0, v1);
                            *(__half2*)&Ct16[(size_t)orow * ldc + p16(n)] = hv;
                        }
                    } else {
                        __half* ch = (__half*)Cc;
                        bool perm = (omask >> (n >> 9)) & 1;
                        int ni0 = perm ? p16(n) : n;
                        __half2 hv = __floats2half2_rn(v0, v1);
                        *(__half2*)&ch[(size_t)orow * ldc + ni0] = hv;
                    }
                }
            }
        }
    }
}

// ---------------- full-fp16 flash attention ------------------------------------
// CTA: 128 queries x one (head, batch); 8 warps, 16 queries/warp; 256 keys staged.
// Q/K fp16 p16, V fp16 logical. Ks stride 40 words; Vs stride 72 halves
// (36 words == 4 mod 32 -> ldmatrix.trans conflict-free); Pw stride 40 words.
#define KS_W 40
#define VS_H 72
#define PW_W 40
#define ATT_SMEM (256 * KS_W * 4 + 256 * VS_H * 2 + 8 * 16 * PW_W * 4)

__global__ __launch_bounds__(256, 2) void attn_mma(
    const __half* __restrict__ qb, const __half* __restrict__ kb,
    const __half* __restrict__ vb, __half* __restrict__ ob,
    int Bt, int qld, int kld, int oldd)
{
    extern __shared__ __align__(16) unsigned smw[];
    unsigned* Ks = smw;                               // [256][40] words
    __half*   Vs = (__half*)(smw + 256 * KS_W);       // [256][72] halves
    unsigned* Pw0 = smw + 256 * KS_W + (256 * VS_H) / 2;
    int tid  = threadIdx.x;
    int warp = tid >> 5, lane = tid & 31;
    int g = lane >> 2, t = lane & 3;
    int hd = blockIdx.y, bb = blockIdx.z;
    unsigned* Pw = Pw0 + warp * (16 * PW_W);

    unsigned ksb = (unsigned)__cvta_generic_to_shared(Ks);
    unsigned vsb = (unsigned)__cvta_generic_to_shared(Vs);

    // stage all 256 keys (K p16, V logical) via cp.async
    for (int idx = tid; idx < 256 * 8; idx += 256) {
        int r = idx >> 3, c = (idx & 7) * 8;
        size_t gbase = ((size_t)(r * Bt + bb)) * kld + hd * 64 + c;
        cp16(ksb + (unsigned)(r * KS_W * 4 + c * 2), kb + gbase, true);
        cp16(vsb + (unsigned)(r * VS_H * 2 + c * 2), vb + gbase, true);
    }
    asm volatile("cp.async.commit_group;\n" ::);

    // Q fragments (p16 -> two uint2 per 16-k chunk)
    int qrow0 = blockIdx.x * 128 + warp * 16 + g;
    unsigned aq[4][4];
    {
        const __half* q0 = qb + ((size_t)(qrow0 * Bt + bb)) * qld + hd * 64;
        const __half* q1 = qb + ((size_t)((qrow0 + 8) * Bt + bb)) * qld + hd * 64;
#pragma unroll
        for (int kc = 0; kc < 4; kc++) {
            uint2 lo = *(const uint2*)(q0 + kc * 16 + 4 * t);
            uint2 hi = *(const uint2*)(q1 + kc * 16 + 4 * t);
            aq[kc][0] = lo.x; aq[kc][2] = lo.y;
            aq[kc][1] = hi.x; aq[kc][3] = hi.y;
        }
    }

    asm volatile("cp.async.wait_group 0;\n" ::);
    __syncthreads();

    float o[8][4];
#pragma unroll
    for (int ni = 0; ni < 8; ni++)
#pragma unroll
        for (int j = 0; j < 4; j++) o[ni][j] = 0.f;
    float m0 = -1e30f, m1 = -1e30f, l0 = 0.f, l1 = 0.f;

    for (int kt = 0; kt < 4; kt++) {           // 4 key tiles of 64
        float sacc[8][4];
#pragma unroll
        for (int ni = 0; ni < 8; ni++)
#pragma unroll
            for (int j = 0; j < 4; j++) sacc[ni][j] = 0.f;

        // S = Q K^T (unscaled; scale folded below)
#pragma unroll
        for (int kc = 0; kc < 4; kc++) {
#pragma unroll
            for (int ni = 0; ni < 8; ni++) {
                int krow = kt * 64 + ni * 8 + g;
                uint2 bv = *(const uint2*)&Ks[krow * KS_W + kc * 8 + 2 * t];
                unsigned bf[2] = { bv.x, bv.y };
                mma_f16(sacc[ni], aq[kc], bf);
            }
        }
#pragma unroll
        for (int ni = 0; ni < 8; ni++)
#pragma unroll
            for (int j = 0; j < 4; j++) sacc[ni][j] *= 0.125f;

        // online softmax (rows g, g+8; quad reductions)
        float mx0 = -1e30f, mx1 = -1e30f;
#pragma unroll
        for (int ni = 0; ni < 8; ni++) {
            mx0 = fmaxf(mx0, fmaxf(sacc[ni][0], sacc[ni][1]));
            mx1 = fmaxf(mx1, fmaxf(sacc[ni][2], sacc[ni][3]));
        }
        mx0 = fmaxf(mx0, __shfl_xor_sync(0xffffffffu, mx0, 1));
        mx0 = fmaxf(mx0, __shfl_xor_sync(0xffffffffu, mx0, 2));
        mx1 = fmaxf(mx1, __shfl_xor_sync(0xffffffffu, mx1, 1));
        mx1 = fmaxf(mx1, __shfl_xor_sync(0xffffffffu, mx1, 2));
        float mn0 = fmaxf(m0, mx0), mn1 = fmaxf(m1, mx1);
        float c0 = __expf(m0 - mn0), c1 = __expf(m1 - mn1);
        m0 = mn0; m1 = mn1;

        float rs0 = 0.f, rs1 = 0.f;
#pragma unroll
        for (int ni = 0; ni < 8; ni++) {
            float p00 = __expf(sacc[ni][0] - mn0);
            float p01 = __expf(sacc[ni][1] - mn0);
            float p10 = __expf(sacc[ni][2] - mn1);
            float p11 = __expf(sacc[ni][3] - mn1);
            rs0 += p00 + p01; rs1 += p10 + p11;
            int w = (ni >> 1) * 8 + 2 * t + (ni & 1);   // p16 word slot
            __half2 h0 = __floats2half2_rn(p00, p01);
            __half2 h1 = __floats2half2_rn(p10, p11);
            Pw[g * PW_W + w]       = *(unsigned*)&h0;
            Pw[(g + 8) * PW_W + w] = *(unsigned*)&h1;
            o[ni][0] *= c0; o[ni][1] *= c0; o[ni][2] *= c1; o[ni][3] *= c1;
        }
        rs0 += __shfl_xor_sync(0xffffffffu, rs0, 1);
        rs0 += __shfl_xor_sync(0xffffffffu, rs0, 2);
        rs1 += __shfl_xor_sync(0xffffffffu, rs1, 1);
        rs1 += __shfl_xor_sync(0xffffffffu, rs1, 2);
        l0 = l0 * c0 + rs0;
        l1 = l1 * c1 + rs1;
        __syncwarp();

        // O += P V   (V via ldmatrix.trans)
#pragma unroll
        for (int ks = 0; ks < 4; ks++) {       // 16-key chunks
            uint2 lo = *(const uint2*)&Pw[g * PW_W + ks * 8 + 2 * t];
            uint2 hi = *(const uint2*)&Pw[(g + 8) * PW_W + ks * 8 + 2 * t];
            unsigned ap[4] = { lo.x, hi.x, lo.y, hi.y };
#pragma unroll
            for (int nb = 0; nb < 4; nb++) {   // 16-dim chunks
                int sel = lane >> 3;
                int key = kt * 64 + ks * 16 + (sel & 1) * 8 + (lane & 7);
                int col = nb * 16 + (sel >> 1) * 8;
                unsigned addr = (unsigned)__cvta_generic_to_shared(Vs + key * VS_H + col);
                unsigned r0, r1, r2, r3;
                asm volatile(
                    "ldmatrix.sync.aligned.m8n8.x4.trans.shared.b16 {%0,%1,%2,%3}, [%4];"
                    : "=r"(r0), "=r"(r1), "=r"(r2), "=r"(r3) : "r"(addr));
                unsigned b0[2] = { r0, r1 }, b1[2] = { r2, r3 };
                mma_f16(o[nb * 2],     ap, b0);
                mma_f16(o[nb * 2 + 1], ap, b1);
            }
        }
        __syncwarp();
    }

    // epilogue: write fp16 p16 (feeds the out-projection GEMM)
    float i0 = 1.f / l0, i1 = 1.f / l1;
    __half* o0 = ob + ((size_t)(qrow0 * Bt + bb)) * oldd + hd * 64;
    __half* o1 = ob + ((size_t)((qrow0 + 8) * Bt + bb)) * oldd + hd * 64;
#pragma unroll
    for (int ni = 0; ni < 8; ni++) {
        int c = ni * 8 + 2 * t;
        __half2 h0 = __floats2half2_rn(o[ni][0] * i0, o[ni][1] * i0);
        __half2 h1 = __floats2half2_rn(o[ni][2] * i1, o[ni][3] * i1);
        *(__half2*)&o0[p16(c)] = h0;
        *(__half2*)&o1[p16(c)] = h1;
    }
}

// ---------------- stats / concat / normalize ----------------
__global__ void concat_stats_kernel(const float* __restrict__ x, float* __restrict__ attn_out)
{
    __shared__ float tile[32][33];
    int bb = blockIdx.z;
    int l0 = blockIdx.x * 32, c0 = blockIdx.y * 32;
    int tx = threadIdx.x, ty = threadIdx.y;   // (32, 8)
#pragma unroll
    for (int j = 0; j < 4; j++) {
        int c = c0 + tx;
        int l = l0 + ty + j * 8;
        int row = l * Bn + bb;
        float v = (c < C1n) ? g_ha[(size_t)row * C1n + c]
                            : g_va[(size_t)row * C2n + (c - C1n)];
        tile[ty + j * 8][tx] = v;
    }
    __syncthreads();
    float lsum = 0.f, lsq = 0.f;
#pragma unroll
    for (int j = 0; j < 4; j++) {
        int c = c0 + ty + j * 8;
        int l = l0 + tx;
        float av = tile[tx][ty + j * 8];
        size_t gi = ((size_t)(bb * Cn + c)) * HWn + l;
        attn_out[gi] = av;
        float r = av + x[gi];
        lsum += r; lsq += r * r;
    }
#pragma unroll
    for (int off = 16; off > 0; off >>= 1) {
        lsum += __shfl_xor_sync(0xffffffffu, lsum, off);
        lsq  += __shfl_xor_sync(0xffffffffu, lsq,  off);
    }
    if (tx == 0) {
        atomicAdd(&g_stats[bb * 2 + 0], (double)lsum);
        atomicAdd(&g_stats[bb * 2 + 1], (double)lsq);
    }
}

__global__ void finalize_stats_kernel()
{
    int b = threadIdx.x;
    if (b < 8) {
        const double N = (double)Cn * HWn;
        double mu  = g_stats[2 * b + 0] / N;
        double var = g_stats[2 * b + 1] / N - mu * mu;
        g_mu[b]   = (float)mu;
        g_rstd[b] = (float)(1.0 / sqrt(var + 1e-5));
    }
}

__global__ void norm_kernel(const float* __restrict__ attn,
                            const float* __restrict__ x,
                            float* __restrict__ out)
{
    int i = blockIdx.x * 256 + threadIdx.x;
    int bb = i >> 21;
    float r = attn[i] + x[i];
    out[i] = (r - g_mu[bb]) * g_rstd[bb];
}

// ---------------- host launcher ----------------
extern "C" void kernel_launch(void* const* d_in, const int* in_sizes, int n_in,
                              void* d_out, int out_size)
{
    const float* x       = (const float*)d_in[0];
    const float* h_in_w  = (const float*)d_in[1];
    const float* h_in_b  = (const float*)d_in[2];
    const float* h_out_w = (const float*)d_in[3];
    const float* h_out_b = (const float*)d_in[4];
    const float* v_in_w  = (const float*)d_in[5];
    const float* v_in_b  = (const float*)d_in[6];
    const float* v_out_w = (const float*)d_in[7];
    const float* v_out_b = (const float*)d_in[8];
    const float* hfc_w   = (const float*)d_in[9];
    const float* hfc_b   = (const float*)d_in[10];
    const float* vfc_w   = (const float*)d_in[11];
    const float* vfc_b   = (const float*)d_in[12];

    float* out      = (float*)d_out;
    float* out_res  = out;                                   // result   [b,C,h,w]
    float* out_hax  = out + (size_t)NTOK * Cn;               // ha_x     [h,w,b,c]
    float* out_vax  = out + 2 * (size_t)NTOK * Cn;           // va_x     [h,w,b,c]
    float* out_attn = out + 3 * (size_t)NTOK * Cn;           // attn     [b,C,h,w]

    __half *p_qh_in, *p_kv_in, *p_xv_in, *p_qh, *p_kvh, *p_qkvv;
    __half *p_oh, *p_ov, *p_hax16, *p_vax16, *p_wt;
    float *p_ha, *p_va;
    cudaGetSymbolAddress((void**)&p_qh_in, g_qh_in);
    cudaGetSymbolAddress((void**)&p_kv_in, g_kv_in);
    cudaGetSymbolAddress((void**)&p_xv_in, g_xv_in);
    cudaGetSymbolAddress((void**)&p_qh,    g_qh);
    cudaGetSymbolAddress((void**)&p_kvh,   g_kvh);
    cudaGetSymbolAddress((void**)&p_qkvv,  g_qkvv);
    cudaGetSymbolAddress((void**)&p_oh,    g_oh);
    cudaGetSymbolAddress((void**)&p_ov,    g_ov);
    cudaGetSymbolAddress((void**)&p_hax16, g_hax16);
    cudaGetSymbolAddress((void**)&p_vax16, g_vax16);
    cudaGetSymbolAddress((void**)&p_wt,    g_wt);
    cudaGetSymbolAddress((void**)&p_ha,    g_ha);
    cudaGetSymbolAddress((void**)&p_va,    g_va);

    dim3 tb(32, 8);
    const int GSMEM = 4 * 128 * GST * 4;   // 81920 B
    cudaFuncSetAttribute(gemm_f16, cudaFuncAttributeMaxDynamicSharedMemorySize, GSMEM);
    cudaFuncSetAttribute(attn_mma, cudaFuncAttributeMaxDynamicSharedMemorySize, ATT_SMEM);

    // idx 0: fused weight conversion (+ stats zero)
    conv_all_kernel<<<(2359296 + 255) / 256, 256>>>(h_in_w, v_in_w, h_out_w, v_out_w, hfc_w, vfc_w);

    // idx 1-2: transposes
    transpose_kernel<<<dim3(128, 16, 8), tb>>>(x, p_xv_in, 1);
    transpose_kernel<<<dim3(128, 16, 8), tb>>>(x, p_qh_in, 0);

    // idx 3: big v projection (profiled launch); out fp16: Q p16 | K p16 | V log
    gemm_f16<<<dim3(12, 256), 256, GSMEM>>>(p_xv_in, p_wt + W_VIN,
        v_in_b, (float*)p_qkvv, 0, NTOK, 1536, 512, 1536, 0, 0b011);

    // idx 4: pool; idx 5-6: remaining input projections
    pool_kernel<<<(Bn * Cn * 256 + 255) / 256, 256>>>(x, p_kv_in);
    gemm_f16<<<dim3(8, 16), 256, GSMEM>>>(p_kv_in, p_wt + W_HIN + 512 * 512,
        h_in_b + 512, (float*)p_kvh, 0, NKV, 1024, 512, 1024, 0, 0b001);  // K p16 | V log
    gemm_f16<<<dim3(4, 256), 256, GSMEM>>>(p_qh_in, p_wt + W_HIN,
        h_in_b, (float*)p_qh, 0, NTOK, 512, 512, 512, 0, 0b1);            // Q p16

    // attention (full fp16; outputs fp16 p16)
    attn_mma<<<dim3(32, 8, 8),  256, ATT_SMEM>>>(p_qh, p_kvh, p_kvh + 512,
        p_oh, 8, 512, 1024, 512);
    attn_mma<<<dim3(2, 8, 128), 256, ATT_SMEM>>>(p_qkvv, p_qkvv + 512, p_qkvv + 1024,
        p_ov, 128, 1536, 1536, 512);

    // output projections: fp32 to d_out + fp16-p16 copy for fc heads
    gemm_f16<<<dim3(4, 256), 256, GSMEM>>>(p_oh, p_wt + W_HOUT,
        h_out_b, out_hax, p_hax16, NTOK, 512, 512, 512, 0, -2);
    gemm_f16<<<dim3(4, 256), 256, GSMEM>>>(p_ov, p_wt + W_VOUT,
        v_out_b, out_vax, p_vax16, NTOK, 512, 512, 512, 1, -2);

    // fc heads (fp32 out)
    gemm_f16<<<dim3(3, 256), 256, GSMEM>>>(p_hax16, p_wt + W_HFC,
        hfc_b, p_ha, 0, NTOK, C1n, 512, C1n, 0, -2);
    gemm_f16<<<dim3(2, 256), 256, GSMEM>>>(p_vax16, p_wt + W_VFC,
        vfc_b, p_va, 0, NTOK, C2n, 512, C2n, 0, -2);

    // concat + residual stats + layernorm
    concat_stats_kernel<<<dim3(128, 16, 8), tb>>>(x, out_attn);
    finalize_stats_kernel<<<1, 32>>>();
    norm_kernel<<<NTOK * Cn / 256, 256>>>(out_attn, x, out_res);
}

// round 14
// speedup vs baseline: 3.4429x; 1.0107x over previous
#include <cuda_runtime.h>
#include <cuda_fp16.h>
#include <cstdint>
#include <math.h>

// ---------------- problem constants ----------------
#define Bn    8
#define Cn    512
#define Hn    64
#define Wn    64
#define HWn   4096          // 64*64
#define NTOK  32768         // 4096*8 tokens
#define NKV   2048          // 256*8
#define C1n   358
#define C2n   154

// ---------------- scratch (static device, no allocs) ----------------
// GEMM operand buffers: fp16, LOGICAL k-order (ldmatrix handles fragments).
// Attention Q/K blocks: fp16 p16-permuted (mma.sync LDS fragments); V logical.
__device__ __align__(16) __half g_qh_in[NTOK * Cn];
__device__ __align__(16) __half g_kv_in[NKV * Cn];
__device__ __align__(16) __half g_xv_in[NTOK * Cn];
__device__ __align__(16) __half g_qh  [NTOK * Cn];             // Q p16
__device__ __align__(16) __half g_kvh [NKV * 2 * Cn];          // K p16 | V logical
__device__ __align__(16) __half g_qkvv[(size_t)NTOK * 3 * Cn]; // Q p16 | K p16 | V log
__device__ __align__(16) __half g_oh  [NTOK * Cn];             // attn out, logical
__device__ __align__(16) __half g_ov  [NTOK * Cn];
__device__ __align__(16) __half g_hax16[NTOK * Cn];            // logical
__device__ __align__(16) __half g_vax16[NTOK * Cn];            // logical
__device__ __align__(16) __half g_wt [2359296];                // weights, logical
__device__ float  g_ha  [(size_t)NTOK * C1n];
__device__ float  g_va  [(size_t)NTOK * C2n];
__device__ double g_stats[16];
__device__ float  g_mu[8];
__device__ float  g_rstd[8];

// weight offsets inside g_wt
#define W_HIN   0
#define W_VIN   786432
#define W_HOUT  1572864
#define W_VOUT  1835008
#define W_HFC   2097152
#define W_VFC   2280448

// fp16 16-group permutation (attention mma.sync fragments)
__device__ __forceinline__ int p16(int k) {
    int p = (k >> 1) & 7, o = k & 1;
    int np = ((p & 3) << 1) | (p >> 2);
    return (k & ~15) | (np << 1) | o;
}

// ---------------- helpers ----------------
__device__ __forceinline__ void mma_f16(float acc[4], const unsigned a[4], const unsigned b[2]) {
    asm volatile(
        "mma.sync.aligned.m16n8k16.row.col.f32.f16.f16.f32 "
        "{%0,%1,%2,%3}, {%4,%5,%6,%7}, {%8,%9}, {%0,%1,%2,%3};\n"
        : "+f"(acc[0]), "+f"(acc[1]), "+f"(acc[2]), "+f"(acc[3])
        : "r"(a[0]), "r"(a[1]), "r"(a[2]), "r"(a[3]), "r"(b[0]), "r"(b[1]));
}

__device__ __forceinline__ void cp16(unsigned saddr, const void* gptr, bool pred) {
    int sz = pred ? 16 : 0;
    asm volatile("cp.async.cg.shared.global [%0], [%1], 16, %2;\n"
                 :: "r"(saddr), "l"(gptr), "r"(sz));
}

__device__ __forceinline__ void ldm_x4(unsigned addr, unsigned& r0, unsigned& r1,
                                       unsigned& r2, unsigned& r3) {
    asm volatile("ldmatrix.sync.aligned.m8n8.x4.shared.b16 {%0,%1,%2,%3}, [%4];"
                 : "=r"(r0), "=r"(r1), "=r"(r2), "=r"(r3) : "r"(addr));
}

// ---------------- fused weight conversion (fp32 -> fp16 logical) + stats zero --
__global__ void conv_all_kernel(
    const float* __restrict__ w0, const float* __restrict__ w1,
    const float* __restrict__ w2, const float* __restrict__ w3,
    const float* __restrict__ w4, const float* __restrict__ w5)
{
    int i = blockIdx.x * 256 + threadIdx.x;
    if (blockIdx.x == 0 && threadIdx.x < 16) g_stats[threadIdx.x] = 0.0;
    if (i >= 2359296) return;
    const float* src;
    int off;
    if      (i < W_VIN)  { src = w0; off = i - W_HIN;  }
    else if (i < W_HOUT) { src = w1; off = i - W_VIN;  }
    else if (i < W_VOUT) { src = w2; off = i - W_HOUT; }
    else if (i < W_HFC)  { src = w3; off = i - W_VOUT; }
    else if (i < W_VFC)  { src = w4; off = i - W_HFC;  }
    else                 { src = w5; off = i - W_VFC;  }
    g_wt[i] = __float2half(src[off]);
}

// ---------------- transpose x(b,c,h,w) -> fp16 token rows [row, C] ------------
__global__ void transpose_kernel(const float* __restrict__ x,
                                 __half* __restrict__ out, int mode)
{
    __shared__ float tile[32][33];
    int bb = blockIdx.z;
    int l0 = blockIdx.x * 32, c0 = blockIdx.y * 32;
    int tx = threadIdx.x, ty = threadIdx.y;   // (32, 8)
#pragma unroll
    for (int j = 0; j < 4; j++) {
        int c = c0 + ty + j * 8;
        tile[ty + j * 8][tx] = x[((size_t)(bb * Cn + c)) * HWn + l0 + tx];
    }
    __syncthreads();
#pragma unroll
    for (int j = 0; j < 4; j++) {
        int l = l0 + ty + j * 8;
        int row;
        if (mode == 0) {
            row = l * Bn + bb;
        } else {
            int xx = l & 63, y = l >> 6;
            int wd = xx & 3, nwi = xx >> 2;
            row = y * 512 + wd * 128 + bb * 16 + nwi;
        }
        out[(size_t)row * Cn + c0 + tx] = __float2half(tile[tx][ty + j * 8]);
    }
}

// ---------------- 4x4 avg pool -> fp16 kv token rows --------------------------
__global__ void pool_kernel(const float* __restrict__ x, __half* __restrict__ out)
{
    int idx = blockIdx.x * 256 + threadIdx.x;
    if (idx >= Bn * Cn * 256) return;
    int px = idx & 15, py = (idx >> 4) & 15, c = (idx >> 8) & 511, bb = idx >> 17;
    const float* base = x + (((size_t)(bb * Cn + c)) * Hn + py * 4) * Wn + px * 4;
    float s = 0.f;
#pragma unroll
    for (int i = 0; i < 4; i++)
#pragma unroll
        for (int j = 0; j < 4; j++) s += base[i * Wn + j];
    out[((size_t)((py * 16 + px) * Bn + bb)) * Cn + c] = __float2half(s * 0.0625f);
}

// ---------------- fp16 tensor-core GEMM, cp.async 2-stage, 128x128 CTA tile ---
// A, Bm: fp16 LOGICAL k-order, row-major [M,K] / [N,K]. M%128==0, K%64==0.
// 8 warps as 2(m) x 4(n), warp tile 64x32, k-chunk 64 halves.
// Smem rows 72 halves (36 words): ldmatrix phases tile all 32 banks.
// omask: -2 -> fp32 out to Cc (+ optional fp16 logical copy to Ct16);
//        else fp16 out to (half*)Cc; 512-block b gets p16 iff (omask>>b)&1.
#define RS 72
#define GSMEM (4 * 128 * RS * 2)   // 73728 B
__global__ __launch_bounds__(256, 2) void gemm_f16(
    const __half* __restrict__ A, const __half* __restrict__ Bm,
    const float* __restrict__ bias, float* __restrict__ Cc,
    __half* __restrict__ Ct16,
    int M, int N, int K, int ldc, int mode, int omask)
{
    extern __shared__ __align__(16) __half smh[];
    __half* As[2] = { smh,             smh + 128 * RS };
    __half* Bs[2] = { smh + 2*128*RS,  smh + 3*128*RS };

    int tid  = threadIdx.x;
    int warp = tid >> 5, lane = tid & 31;
    int wm = warp & 1, wn = warp >> 1;        // 2 x 4 warps
    int t = lane & 3;
    int m0 = blockIdx.y * 128, n0 = blockIdx.x * 128;

    float acc[4][4][4];
#pragma unroll
    for (int mi = 0; mi < 4; mi++)
#pragma unroll
        for (int ni = 0; ni < 4; ni++)
#pragma unroll
            for (int j = 0; j < 4; j++) acc[mi][ni][j] = 0.f;

    unsigned sa[2], sb[2];
#pragma unroll
    for (int s = 0; s < 2; s++) {
        sa[s] = (unsigned)__cvta_generic_to_shared(As[s]);
        sb[s] = (unsigned)__cvta_generic_to_shared(Bs[s]);
    }

    // ldmatrix lane addressing: row_in_16 = lane&15, k-offset = (lane>>4)*8
    int lrow = lane & 15, lcol = (lane >> 4) * 8;

#define STAGE(s, k0) do {                                                       \
    _Pragma("unroll")                                                           \
    for (int i = 0; i < 4; i++) {                                               \
        int chunk = i * 256 + tid;                                              \
        int r = chunk >> 3, c8 = (chunk & 7) * 8;                               \
        cp16(sa[s] + (unsigned)((r * RS + c8) * 2),                             \
             A + (size_t)(m0 + r) * K + (k0) + c8, true);                       \
        cp16(sb[s] + (unsigned)((r * RS + c8) * 2),                             \
             Bm + (size_t)(n0 + r) * K + (k0) + c8, (n0 + r) < N);              \
    }                                                                           \
    asm volatile("cp.async.commit_group;\n" ::);                                \
} while (0)

    STAGE(0, 0);
    STAGE(1, 64);

    int s = 0;
    for (int k0 = 0; k0 < K; k0 += 64) {
        if (k0 + 64 < K)
            asm volatile("cp.async.wait_group 1;\n" ::);
        else
            asm volatile("cp.async.wait_group 0;\n" ::);
        __syncthreads();

#pragma unroll
        for (int kk = 0; kk < 64; kk += 16) {
            unsigned af[4][4], bf[4][2];
#pragma unroll
            for (int mi = 0; mi < 4; mi++) {
                int rm = wm * 64 + mi * 16 + lrow;
                unsigned addr = sa[s] + (unsigned)((rm * RS + kk + lcol) * 2);
                ldm_x4(addr, af[mi][0], af[mi][1], af[mi][2], af[mi][3]);
            }
#pragma unroll
            for (int nb = 0; nb < 2; nb++) {
                int rn = wn * 32 + nb * 16 + lrow;
                unsigned addr = sb[s] + (unsigned)((rn * RS + kk + lcol) * 2);
                unsigned r0, r1, r2, r3;
                ldm_x4(addr, r0, r1, r2, r3);
                bf[nb * 2][0]     = r0; bf[nb * 2][1]     = r2;
                bf[nb * 2 + 1][0] = r1; bf[nb * 2 + 1][1] = r3;
            }
#pragma unroll
            for (int mi = 0; mi < 4; mi++)
#pragma unroll
                for (int ni = 0; ni < 4; ni++)
                    mma_f16(acc[mi][ni], af[mi], bf[ni]);
        }
        __syncthreads();

        if (k0 + 128 < K) STAGE(s, k0 + 128);
        s ^= 1;
    }
#undef STAGE

    // epilogue: C row = lane/4 (+8), col = ni*8 + 2t + {0,1}
    int g = lane >> 2;
#pragma unroll
    for (int mi = 0; mi < 4; mi++) {
#pragma unroll
        for (int half = 0; half < 2; half++) {
            int m = m0 + wm * 64 + mi * 16 + g + half * 8;
            int orow;
            if (mode == 0) {
                orow = m;
            } else {
                int nwi = m & 15, bb = (m >> 4) & 7, wd = (m >> 7) & 3, y = m >> 9;
                orow = ((y << 6) + (nwi << 2) + wd) * Bn + bb;
            }
#pragma unroll
            for (int ni = 0; ni < 4; ni++) {
                int n = n0 + wn * 32 + ni * 8 + t * 2;
                if (n < N) {
                    float v0 = acc[mi][ni][half * 2 + 0] + bias[n];
                    float v1 = acc[mi][ni][half * 2 + 1] + bias[n + 1];
                    if (omask == -2) {
                        float* cr = Cc + (size_t)orow * ldc;
                        cr[n] = v0; cr[n + 1] = v1;
                        if (Ct16) {
                            __half2 hv = __floats2half2_rn(v0, v1);
                            *(__half2*)&Ct16[(size_t)orow * ldc + n] = hv;
                        }
                    } else {
                        __half* ch = (__half*)Cc;
                        bool perm = (omask >> (n >> 9)) & 1;
                        int ni0 = perm ? p16(n) : n;
                        __half2 hv = __floats2half2_rn(v0, v1);
                        *(__half2*)&ch[(size_t)orow * ldc + ni0] = hv;
                    }
                }
            }
        }
    }
}

// ---------------- full-fp16 flash attention (mma.sync) ------------------------
// CTA: 128 queries x one (head, batch); 8 warps, 16 queries/warp; 256 keys staged.
// Q/K fp16 p16, V fp16 logical. Output LOGICAL fp16 (feeds ldmatrix GEMM).
#define KS_W 40
#define VS_H 72
#define PW_W 40
#define ATT_SMEM (256 * KS_W * 4 + 256 * VS_H * 2 + 8 * 16 * PW_W * 4)

__global__ __launch_bounds__(256, 2) void attn_mma(
    const __half* __restrict__ qb, const __half* __restrict__ kb,
    const __half* __restrict__ vb, __half* __restrict__ ob,
    int Bt, int qld, int kld, int oldd)
{
    extern __shared__ __align__(16) unsigned smw[];
    unsigned* Ks = smw;                               // [256][40] words
    __half*   Vs = (__half*)(smw + 256 * KS_W);       // [256][72] halves
    unsigned* Pw0 = smw + 256 * KS_W + (256 * VS_H) / 2;
    int tid  = threadIdx.x;
    int warp = tid >> 5, lane = tid & 31;
    int g = lane >> 2, t = lane & 3;
    int hd = blockIdx.y, bb = blockIdx.z;
    unsigned* Pw = Pw0 + warp * (16 * PW_W);

    unsigned ksb = (unsigned)__cvta_generic_to_shared(Ks);
    unsigned vsb = (unsigned)__cvta_generic_to_shared(Vs);

    for (int idx = tid; idx < 256 * 8; idx += 256) {
        int r = idx >> 3, c = (idx & 7) * 8;
        size_t gbase = ((size_t)(r * Bt + bb)) * kld + hd * 64 + c;
        cp16(ksb + (unsigned)(r * KS_W * 4 + c * 2), kb + gbase, true);
        cp16(vsb + (unsigned)(r * VS_H * 2 + c * 2), vb + gbase, true);
    }
    asm volatile("cp.async.commit_group;\n" ::);

    int qrow0 = blockIdx.x * 128 + warp * 16 + g;
    unsigned aq[4][4];
    {
        const __half* q0 = qb + ((size_t)(qrow0 * Bt + bb)) * qld + hd * 64;
        const __half* q1 = qb + ((size_t)((qrow0 + 8) * Bt + bb)) * qld + hd * 64;
#pragma unroll
        for (int kc = 0; kc < 4; kc++) {
            uint2 lo = *(const uint2*)(q0 + kc * 16 + 4 * t);
            uint2 hi = *(const uint2*)(q1 + kc * 16 + 4 * t);
            aq[kc][0] = lo.x; aq[kc][2] = lo.y;
            aq[kc][1] = hi.x; aq[kc][3] = hi.y;
        }
    }

    asm volatile("cp.async.wait_group 0;\n" ::);
    __syncthreads();

    float o[8][4];
#pragma unroll
    for (int ni = 0; ni < 8; ni++)
#pragma unroll
        for (int j = 0; j < 4; j++) o[ni][j] = 0.f;
    float m0 = -1e30f, m1 = -1e30f, l0 = 0.f, l1 = 0.f;

    for (int kt = 0; kt < 4; kt++) {           // 4 key tiles of 64
        float sacc[8][4];
#pragma unroll
        for (int ni = 0; ni < 8; ni++)
#pragma unroll
            for (int j = 0; j < 4; j++) sacc[ni][j] = 0.f;

#pragma unroll
        for (int kc = 0; kc < 4; kc++) {
#pragma unroll
            for (int ni = 0; ni < 8; ni++) {
                int krow = kt * 64 + ni * 8 + g;
                uint2 bv = *(const uint2*)&Ks[krow * KS_W + kc * 8 + 2 * t];
                unsigned bf[2] = { bv.x, bv.y };
                mma_f16(sacc[ni], aq[kc], bf);
            }
        }
#pragma unroll
        for (int ni = 0; ni < 8; ni++)
#pragma unroll
            for (int j = 0; j < 4; j++) sacc[ni][j] *= 0.125f;

        float mx0 = -1e30f, mx1 = -1e30f;
#pragma unroll
        for (int ni = 0; ni < 8; ni++) {
            mx0 = fmaxf(mx0, fmaxf(sacc[ni][0], sacc[ni][1]));
            mx1 = fmaxf(mx1, fmaxf(sacc[ni][2], sacc[ni][3]));
        }
        mx0 = fmaxf(mx0, __shfl_xor_sync(0xffffffffu, mx0, 1));
        mx0 = fmaxf(mx0, __shfl_xor_sync(0xffffffffu, mx0, 2));
        mx1 = fmaxf(mx1, __shfl_xor_sync(0xffffffffu, mx1, 1));
        mx1 = fmaxf(mx1, __shfl_xor_sync(0xffffffffu, mx1, 2));
        float mn0 = fmaxf(m0, mx0), mn1 = fmaxf(m1, mx1);
        float c0 = __expf(m0 - mn0), c1 = __expf(m1 - mn1);
        m0 = mn0; m1 = mn1;

        float rs0 = 0.f, rs1 = 0.f;
#pragma unroll
        for (int ni = 0; ni < 8; ni++) {
            float p00 = __expf(sacc[ni][0] - mn0);
            float p01 = __expf(sacc[ni][1] - mn0);
            float p10 = __expf(sacc[ni][2] - mn1);
            float p11 = __expf(sacc[ni][3] - mn1);
            rs0 += p00 + p01; rs1 += p10 + p11;
            int w = (ni >> 1) * 8 + 2 * t + (ni & 1);   // p16 word slot
            __half2 h0 = __floats2half2_rn(p00, p01);
            __half2 h1 = __floats2half2_rn(p10, p11);
            Pw[g * PW_W + w]       = *(unsigned*)&h0;
            Pw[(g + 8) * PW_W + w] = *(unsigned*)&h1;
            o[ni][0] *= c0; o[ni][1] *= c0; o[ni][2] *= c1; o[ni][3] *= c1;
        }
        rs0 += __shfl_xor_sync(0xffffffffu, rs0, 1);
        rs0 += __shfl_xor_sync(0xffffffffu, rs0, 2);
        rs1 += __shfl_xor_sync(0xffffffffu, rs1, 1);
        rs1 += __shfl_xor_sync(0xffffffffu, rs1, 2);
        l0 = l0 * c0 + rs0;
        l1 = l1 * c1 + rs1;
        __syncwarp();

#pragma unroll
        for (int ks = 0; ks < 4; ks++) {
            uint2 lo = *(const uint2*)&Pw[g * PW_W + ks * 8 + 2 * t];
            uint2 hi = *(const uint2*)&Pw[(g + 8) * PW_W + ks * 8 + 2 * t];
            unsigned ap[4] = { lo.x, hi.x, lo.y, hi.y };
#pragma unroll
            for (int nb = 0; nb < 4; nb++) {
                int sel = lane >> 3;
                int key = kt * 64 + ks * 16 + (sel & 1) * 8 + (lane & 7);
                int col = nb * 16 + (sel >> 1) * 8;
                unsigned addr = (unsigned)__cvta_generic_to_shared(Vs + key * VS_H + col);
                unsigned r0, r1, r2, r3;
                asm volatile(
                    "ldmatrix.sync.aligned.m8n8.x4.trans.shared.b16 {%0,%1,%2,%3}, [%4];"
                    : "=r"(r0), "=r"(r1), "=r"(r2), "=r"(r3) : "r"(addr));
                unsigned b0[2] = { r0, r1 }, b1[2] = { r2, r3 };
                mma_f16(o[nb * 2],     ap, b0);
                mma_f16(o[nb * 2 + 1], ap, b1);
            }
        }
        __syncwarp();
    }

    // epilogue: LOGICAL fp16 output (feeds the ldmatrix out-projection GEMM)
    float i0 = 1.f / l0, i1 = 1.f / l1;
    __half* o0 = ob + ((size_t)(qrow0 * Bt + bb)) * oldd + hd * 64;
    __half* o1 = ob + ((size_t)((qrow0 + 8) * Bt + bb)) * oldd + hd * 64;
#pragma unroll
    for (int ni = 0; ni < 8; ni++) {
        int c = ni * 8 + 2 * t;
        __half2 h0 = __floats2half2_rn(o[ni][0] * i0, o[ni][1] * i0);
        __half2 h1 = __floats2half2_rn(o[ni][2] * i1, o[ni][3] * i1);
        *(__half2*)&o0[c] = h0;
        *(__half2*)&o1[c] = h1;
    }
}

// ---------------- stats / concat / normalize ----------------
__global__ void concat_stats_kernel(const float* __restrict__ x, float* __restrict__ attn_out)
{
    __shared__ float tile[32][33];
    int bb = blockIdx.z;
    int l0 = blockIdx.x * 32, c0 = blockIdx.y * 32;
    int tx = threadIdx.x, ty = threadIdx.y;   // (32, 8)
#pragma unroll
    for (int j = 0; j < 4; j++) {
        int c = c0 + tx;
        int l = l0 + ty + j * 8;
        int row = l * Bn + bb;
        float v = (c < C1n) ? g_ha[(size_t)row * C1n + c]
                            : g_va[(size_t)row * C2n + (c - C1n)];
        tile[ty + j * 8][tx] = v;
    }
    __syncthreads();
    float lsum = 0.f, lsq = 0.f;
#pragma unroll
    for (int j = 0; j < 4; j++) {
        int c = c0 + ty + j * 8;
        int l = l0 + tx;
        float av = tile[tx][ty + j * 8];
        size_t gi = ((size_t)(bb * Cn + c)) * HWn + l;
        attn_out[gi] = av;
        float r = av + x[gi];
        lsum += r; lsq += r * r;
    }
#pragma unroll
    for (int off = 16; off > 0; off >>= 1) {
        lsum += __shfl_xor_sync(0xffffffffu, lsum, off);
        lsq  += __shfl_xor_sync(0xffffffffu, lsq,  off);
    }
    if (tx == 0) {
        atomicAdd(&g_stats[bb * 2 + 0], (double)lsum);
        atomicAdd(&g_stats[bb * 2 + 1], (double)lsq);
    }
}

__global__ void finalize_stats_kernel()
{
    int b = threadIdx.x;
    if (b < 8) {
        const double N = (double)Cn * HWn;
        double mu  = g_stats[2 * b + 0] / N;
        double var = g_stats[2 * b + 1] / N - mu * mu;
        g_mu[b]   = (float)mu;
        g_rstd[b] = (float)(1.0 / sqrt(var + 1e-5));
    }
}

__global__ void norm_kernel(const float* __restrict__ attn,
                            const float* __restrict__ x,
                            float* __restrict__ out)
{
    int i = blockIdx.x * 256 + threadIdx.x;
    int bb = i >> 21;
    float r = attn[i] + x[i];
    out[i] = (r - g_mu[bb]) * g_rstd[bb];
}

// ---------------- host launcher ----------------
extern "C" void kernel_launch(void* const* d_in, const int* in_sizes, int n_in,
                              void* d_out, int out_size)
{
    const float* x       = (const float*)d_in[0];
    const float* h_in_w  = (const float*)d_in[1];
    const float* h_in_b  = (const float*)d_in[2];
    const float* h_out_w = (const float*)d_in[3];
    const float* h_out_b = (const float*)d_in[4];
    const float* v_in_w  = (const float*)d_in[5];
    const float* v_in_b  = (const float*)d_in[6];
    const float* v_out_w = (const float*)d_in[7];
    const float* v_out_b = (const float*)d_in[8];
    const float* hfc_w   = (const float*)d_in[9];
    const float* hfc_b   = (const float*)d_in[10];
    const float* vfc_w   = (const float*)d_in[11];
    const float* vfc_b   = (const float*)d_in[12];

    float* out      = (float*)d_out;
    float* out_res  = out;                                   // result   [b,C,h,w]
    float* out_hax  = out + (size_t)NTOK * Cn;               // ha_x     [h,w,b,c]
    float* out_vax  = out + 2 * (size_t)NTOK * Cn;           // va_x     [h,w,b,c]
    float* out_attn = out + 3 * (size_t)NTOK * Cn;           // attn     [b,C,h,w]

    __half *p_qh_in, *p_kv_in, *p_xv_in, *p_qh, *p_kvh, *p_qkvv;
    __half *p_oh, *p_ov, *p_hax16, *p_vax16, *p_wt;
    float *p_ha, *p_va;
    cudaGetSymbolAddress((void**)&p_qh_in, g_qh_in);
    cudaGetSymbolAddress((void**)&p_kv_in, g_kv_in);
    cudaGetSymbolAddress((void**)&p_xv_in, g_xv_in);
    cudaGetSymbolAddress((void**)&p_qh,    g_qh);
    cudaGetSymbolAddress((void**)&p_kvh,   g_kvh);
    cudaGetSymbolAddress((void**)&p_qkvv,  g_qkvv);
    cudaGetSymbolAddress((void**)&p_oh,    g_oh);
    cudaGetSymbolAddress((void**)&p_ov,    g_ov);
    cudaGetSymbolAddress((void**)&p_hax16, g_hax16);
    cudaGetSymbolAddress((void**)&p_vax16, g_vax16);
    cudaGetSymbolAddress((void**)&p_wt,    g_wt);
    cudaGetSymbolAddress((void**)&p_ha,    g_ha);
    cudaGetSymbolAddress((void**)&p_va,    g_va);

    dim3 tb(32, 8);
    cudaFuncSetAttribute(gemm_f16, cudaFuncAttributeMaxDynamicSharedMemorySize, GSMEM);
    cudaFuncSetAttribute(attn_mma, cudaFuncAttributeMaxDynamicSharedMemorySize, ATT_SMEM);

    // idx 0: fused weight conversion (+ stats zero)
    conv_all_kernel<<<(2359296 + 255) / 256, 256>>>(h_in_w, v_in_w, h_out_w, v_out_w, hfc_w, vfc_w);

    // idx 1-2: transposes
    transpose_kernel<<<dim3(128, 16, 8), tb>>>(x, p_xv_in, 1);
    transpose_kernel<<<dim3(128, 16, 8), tb>>>(x, p_qh_in, 0);

    // idx 3: big v projection (profiled launch); out fp16: Q p16 | K p16 | V log
    gemm_f16<<<dim3(12, 256), 256, GSMEM>>>(p_xv_in, p_wt + W_VIN,
        v_in_b, (float*)p_qkvv, 0, NTOK, 1536, 512, 1536, 0, 0b011);

    // idx 4: pool; idx 5-6: remaining input projections
    pool_kernel<<<(Bn * Cn * 256 + 255) / 256, 256>>>(x, p_kv_in);
    gemm_f16<<<dim3(8, 16), 256, GSMEM>>>(p_kv_in, p_wt + W_HIN + 512 * 512,
        h_in_b + 512, (float*)p_kvh, 0, NKV, 1024, 512, 1024, 0, 0b001);  // K p16 | V log
    gemm_f16<<<dim3(4, 256), 256, GSMEM>>>(p_qh_in, p_wt + W_HIN,
        h_in_b, (float*)p_qh, 0, NTOK, 512, 512, 512, 0, 0b1);            // Q p16

    // attention (full fp16; outputs logical fp16)
    attn_mma<<<dim3(32, 8, 8),  256, ATT_SMEM>>>(p_qh, p_kvh, p_kvh + 512,
        p_oh, 8, 512, 1024, 512);
    attn_mma<<<dim3(2, 8, 128), 256, ATT_SMEM>>>(p_qkvv, p_qkvv + 512, p_qkvv + 1024,
        p_ov, 128, 1536, 1536, 512);

    // output projections: fp32 to d_out + logical fp16 copy for fc heads
    gemm_f16<<<dim3(4, 256), 256, GSMEM>>>(p_oh, p_wt + W_HOUT,
        h_out_b, out_hax, p_hax16, NTOK, 512, 512, 512, 0, -2);
    gemm_f16<<<dim3(4, 256), 256, GSMEM>>>(p_ov, p_wt + W_VOUT,
        v_out_b, out_vax, p_vax16, NTOK, 512, 512, 512, 1, -2);

    // fc heads (fp32 out)
    gemm_f16<<<dim3(3, 256), 256, GSMEM>>>(p_hax16, p_wt + W_HFC,
        hfc_b, p_ha, 0, NTOK, C1n, 512, C1n, 0, -2);
    gemm_f16<<<dim3(2, 256), 256, GSMEM>>>(p_vax16, p_wt + W_VFC,
        vfc_b, p_va, 0, NTOK, C2n, 512, C2n, 0, -2);

    // concat + residual stats + layernorm
    concat_stats_kernel<<<dim3(128, 16, 8), tb>>>(x, out_attn);
    finalize_stats_kernel<<<1, 32>>>();
    norm_kernel<<<NTOK * Cn / 256, 256>>>(out_attn, x, out_res);
}

// round 16
// speedup vs baseline: 3.5149x; 1.0209x over previous
#include <cuda_runtime.h>
#include <cuda_fp16.h>
#include <cstdint>
#include <math.h>

// ---------------- problem constants ----------------
#define Bn    8
#define Cn    512
#define Hn    64
#define Wn    64
#define HWn   4096          // 64*64
#define NTOK  32768         // 4096*8 tokens
#define NKV   2048          // 256*8
#define C1n   358
#define C2n   154

// ---------------- scratch (static device, no allocs) ----------------
// GEMM operand buffers: fp16, LOGICAL k-order (ldmatrix handles fragments).
// Attention Q/K blocks: fp16 p16-permuted (mma.sync LDS fragments); V logical.
__device__ __align__(16) __half g_qh_in[NTOK * Cn];
__device__ __align__(16) __half g_kv_in[NKV * Cn];
__device__ __align__(16) __half g_xv_in[NTOK * Cn];
__device__ __align__(16) __half g_qh  [NTOK * Cn];             // Q p16
__device__ __align__(16) __half g_kvh [NKV * 2 * Cn];          // K p16 | V logical
__device__ __align__(16) __half g_qkvv[(size_t)NTOK * 3 * Cn]; // Q p16 | K p16 | V log
__device__ __align__(16) __half g_oh  [NTOK * Cn];             // attn out, logical
__device__ __align__(16) __half g_ov  [NTOK * Cn];
__device__ __align__(16) __half g_hax16[NTOK * Cn];            // logical
__device__ __align__(16) __half g_vax16[NTOK * Cn];            // logical
__device__ __align__(16) __half g_wt [2359296];                // weights, logical
__device__ float  g_ha  [(size_t)NTOK * C1n];
__device__ float  g_va  [(size_t)NTOK * C2n];
__device__ double g_stats[16];
__device__ float  g_mu[8];
__device__ float  g_rstd[8];

// weight offsets inside g_wt
#define W_HIN   0
#define W_VIN   786432
#define W_HOUT  1572864
#define W_VOUT  1835008
#define W_HFC   2097152
#define W_VFC   2280448

// fp16 16-group permutation (attention mma.sync fragments)
__device__ __forceinline__ int p16(int k) {
    int p = (k >> 1) & 7, o = k & 1;
    int np = ((p & 3) << 1) | (p >> 2);
    return (k & ~15) | (np << 1) | o;
}

// ---------------- helpers ----------------
__device__ __forceinline__ void mma_f16(float acc[4], const unsigned a[4], const unsigned b[2]) {
    asm volatile(
        "mma.sync.aligned.m16n8k16.row.col.f32.f16.f16.f32 "
        "{%0,%1,%2,%3}, {%4,%5,%6,%7}, {%8,%9}, {%0,%1,%2,%3};\n"
        : "+f"(acc[0]), "+f"(acc[1]), "+f"(acc[2]), "+f"(acc[3])
        : "r"(a[0]), "r"(a[1]), "r"(a[2]), "r"(a[3]), "r"(b[0]), "r"(b[1]));
}

__device__ __forceinline__ void cp16(unsigned saddr, const void* gptr, bool pred) {
    int sz = pred ? 16 : 0;
    asm volatile("cp.async.cg.shared.global [%0], [%1], 16, %2;\n"
                 :: "r"(saddr), "l"(gptr), "r"(sz));
}

__device__ __forceinline__ void ldm_x4(unsigned addr, unsigned& r0, unsigned& r1,
                                       unsigned& r2, unsigned& r3) {
    asm volatile("ldmatrix.sync.aligned.m8n8.x4.shared.b16 {%0,%1,%2,%3}, [%4];"
                 : "=r"(r0), "=r"(r1), "=r"(r2), "=r"(r3) : "r"(addr));
}

// ---------------- fused weight conversion (fp32 -> fp16 logical) + stats zero --
__global__ void conv_all_kernel(
    const float* __restrict__ w0, const float* __restrict__ w1,
    const float* __restrict__ w2, const float* __restrict__ w3,
    const float* __restrict__ w4, const float* __restrict__ w5)
{
    int i = blockIdx.x * 256 + threadIdx.x;
    if (blockIdx.x == 0 && threadIdx.x < 16) g_stats[threadIdx.x] = 0.0;
    if (i >= 2359296) return;
    const float* src;
    int off;
    if      (i < W_VIN)  { src = w0; off = i - W_HIN;  }
    else if (i < W_HOUT) { src = w1; off = i - W_VIN;  }
    else if (i < W_VOUT) { src = w2; off = i - W_HOUT; }
    else if (i < W_HFC)  { src = w3; off = i - W_VOUT; }
    else if (i < W_VFC)  { src = w4; off = i - W_HFC;  }
    else                 { src = w5; off = i - W_VFC;  }
    g_wt[i] = __float2half(src[off]);
}

// ---------------- transpose x(b,c,h,w) -> fp16 token rows [row, C] ------------
__global__ void transpose_kernel(const float* __restrict__ x,
                                 __half* __restrict__ out, int mode)
{
    __shared__ float tile[32][33];
    int bb = blockIdx.z;
    int l0 = blockIdx.x * 32, c0 = blockIdx.y * 32;
    int tx = threadIdx.x, ty = threadIdx.y;   // (32, 8)
#pragma unroll
    for (int j = 0; j < 4; j++) {
        int c = c0 + ty + j * 8;
        tile[ty + j * 8][tx] = x[((size_t)(bb * Cn + c)) * HWn + l0 + tx];
    }
    __syncthreads();
#pragma unroll
    for (int j = 0; j < 4; j++) {
        int l = l0 + ty + j * 8;
        int row;
        if (mode == 0) {
            row = l * Bn + bb;
        } else {
            int xx = l & 63, y = l >> 6;
            int wd = xx & 3, nwi = xx >> 2;
            row = y * 512 + wd * 128 + bb * 16 + nwi;
        }
        out[(size_t)row * Cn + c0 + tx] = __float2half(tile[tx][ty + j * 8]);
    }
}

// ---------------- 4x4 avg pool -> fp16 kv token rows --------------------------
__global__ void pool_kernel(const float* __restrict__ x, __half* __restrict__ out)
{
    int idx = blockIdx.x * 256 + threadIdx.x;
    if (idx >= Bn * Cn * 256) return;
    int px = idx & 15, py = (idx >> 4) & 15, c = (idx >> 8) & 511, bb = idx >> 17;
    const float* base = x + (((size_t)(bb * Cn + c)) * Hn + py * 4) * Wn + px * 4;
    float s = 0.f;
#pragma unroll
    for (int i = 0; i < 4; i++)
#pragma unroll
        for (int j = 0; j < 4; j++) s += base[i * Wn + j];
    out[((size_t)((py * 16 + px) * Bn + bb)) * Cn + c] = __float2half(s * 0.0625f);
}

// ---------------- fp16 tensor-core GEMM, cp.async 2-stage, 128x128 CTA tile ---
// (R14-proven version: two barriers per k-chunk, stage after compute.)
// A, Bm: fp16 LOGICAL k-order, row-major [M,K] / [N,K]. M%128==0, K%64==0.
// 8 warps as 2(m) x 4(n), warp tile 64x32, k-chunk 64 halves.
// Smem rows 72 halves (36 words): ldmatrix phases tile all 32 banks.
// omask: -2 -> fp32 out to Cc (+ optional fp16 logical copy to Ct16);
//        else fp16 out to (half*)Cc; 512-block b gets p16 iff (omask>>b)&1.
#define RS 72
#define GSMEM (4 * 128 * RS * 2)   // 73728 B
__global__ __launch_bounds__(256, 2) void gemm_f16(
    const __half* __restrict__ A, const __half* __restrict__ Bm,
    const float* __restrict__ bias, float* __restrict__ Cc,
    __half* __restrict__ Ct16,
    int M, int N, int K, int ldc, int mode, int omask)
{
    extern __shared__ __align__(16) __half smh[];
    __half* As[2] = { smh,             smh + 128 * RS };
    __half* Bs[2] = { smh + 2*128*RS,  smh + 3*128*RS };

    int tid  = threadIdx.x;
    int warp = tid >> 5, lane = tid & 31;
    int wm = warp & 1, wn = warp >> 1;        // 2 x 4 warps
    int t = lane & 3;
    int m0 = blockIdx.y * 128, n0 = blockIdx.x * 128;

    float acc[4][4][4];
#pragma unroll
    for (int mi = 0; mi < 4; mi++)
#pragma unroll
        for (int ni = 0; ni < 4; ni++)
#pragma unroll
            for (int j = 0; j < 4; j++) acc[mi][ni][j] = 0.f;

    unsigned sa[2], sb[2];
#pragma unroll
    for (int s = 0; s < 2; s++) {
        sa[s] = (unsigned)__cvta_generic_to_shared(As[s]);
        sb[s] = (unsigned)__cvta_generic_to_shared(Bs[s]);
    }

    // ldmatrix lane addressing: row_in_16 = lane&15, k-offset = (lane>>4)*8
    int lrow = lane & 15, lcol = (lane >> 4) * 8;

#define STAGE(s, k0) do {                                                       \
    _Pragma("unroll")                                                           \
    for (int i = 0; i < 4; i++) {                                               \
        int chunk = i * 256 + tid;                                              \
        int r = chunk >> 3, c8 = (chunk & 7) * 8;                               \
        cp16(sa[s] + (unsigned)((r * RS + c8) * 2),                             \
             A + (size_t)(m0 + r) * K + (k0) + c8, true);                       \
        cp16(sb[s] + (unsigned)((r * RS + c8) * 2),                             \
             Bm + (size_t)(n0 + r) * K + (k0) + c8, (n0 + r) < N);              \
    }                                                                           \
    asm volatile("cp.async.commit_group;\n" ::);                                \
} while (0)

    STAGE(0, 0);
    STAGE(1, 64);

    int s = 0;
    for (int k0 = 0; k0 < K; k0 += 64) {
        if (k0 + 64 < K)
            asm volatile("cp.async.wait_group 1;\n" ::);
        else
            asm volatile("cp.async.wait_group 0;\n" ::);
        __syncthreads();

#pragma unroll
        for (int kk = 0; kk < 64; kk += 16) {
            unsigned af[4][4], bf[4][2];
#pragma unroll
            for (int mi = 0; mi < 4; mi++) {
                int rm = wm * 64 + mi * 16 + lrow;
                unsigned addr = sa[s] + (unsigned)((rm * RS + kk + lcol) * 2);
                ldm_x4(addr, af[mi][0], af[mi][1], af[mi][2], af[mi][3]);
            }
#pragma unroll
            for (int nb = 0; nb < 2; nb++) {
                int rn = wn * 32 + nb * 16 + lrow;
                unsigned addr = sb[s] + (unsigned)((rn * RS + kk + lcol) * 2);
                unsigned r0, r1, r2, r3;
                ldm_x4(addr, r0, r1, r2, r3);
                bf[nb * 2][0]     = r0; bf[nb * 2][1]     = r2;
                bf[nb * 2 + 1][0] = r1; bf[nb * 2 + 1][1] = r3;
            }
#pragma unroll
            for (int mi = 0; mi < 4; mi++)
#pragma unroll
                for (int ni = 0; ni < 4; ni++)
                    mma_f16(acc[mi][ni], af[mi], bf[ni]);
        }
        __syncthreads();

        if (k0 + 128 < K) STAGE(s, k0 + 128);
        s ^= 1;
    }
#undef STAGE

    // epilogue: C row = lane/4 (+8), col = ni*8 + 2t + {0,1}
    int g = lane >> 2;
#pragma unroll
    for (int mi = 0; mi < 4; mi++) {
#pragma unroll
        for (int half = 0; half < 2; half++) {
            int m = m0 + wm * 64 + mi * 16 + g + half * 8;
            int orow;
            if (mode == 0) {
                orow = m;
            } else {
                int nwi = m & 15, bb = (m >> 4) & 7, wd = (m >> 7) & 3, y = m >> 9;
                orow = ((y << 6) + (nwi << 2) + wd) * Bn + bb;
            }
#pragma unroll
            for (int ni = 0; ni < 4; ni++) {
                int n = n0 + wn * 32 + ni * 8 + t * 2;
                if (n < N) {
                    float v0 = acc[mi][ni][half * 2 + 0] + bias[n];
                    float v1 = acc[mi][ni][half * 2 + 1] + bias[n + 1];
                    if (omask == -2) {
                        float* cr = Cc + (size_t)orow * ldc;
                        cr[n] = v0; cr[n + 1] = v1;
                        if (Ct16) {
                            __half2 hv = __floats2half2_rn(v0, v1);
                            *(__half2*)&Ct16[(size_t)orow * ldc + n] = hv;
                        }
                    } else {
                        __half* ch = (__half*)Cc;
                        bool perm = (omask >> (n >> 9)) & 1;
                        int ni0 = perm ? p16(n) : n;
                        __half2 hv = __floats2half2_rn(v0, v1);
                        *(__half2*)&ch[(size_t)orow * ldc + ni0] = hv;
                    }
                }
            }
        }
    }
}

// ---------------- full-fp16 flash attention (mma.sync) ------------------------
// CTA: 128 queries x one (head, batch); 8 warps, 16 queries/warp; 256 keys staged.
// Q/K fp16 p16, V fp16 logical. Output LOGICAL fp16 (feeds ldmatrix GEMM).
#define KS_W 40
#define VS_H 72
#define PW_W 40
#define ATT_SMEM (256 * KS_W * 4 + 256 * VS_H * 2 + 8 * 16 * PW_W * 4)

__global__ __launch_bounds__(256, 2) void attn_mma(
    const __half* __restrict__ qb, const __half* __restrict__ kb,
    const __half* __restrict__ vb, __half* __restrict__ ob,
    int Bt, int qld, int kld, int oldd)
{
    extern __shared__ __align__(16) unsigned smw[];
    unsigned* Ks = smw;                               // [256][40] words
    __half*   Vs = (__half*)(smw + 256 * KS_W);       // [256][72] halves
    unsigned* Pw0 = smw + 256 * KS_W + (256 * VS_H) / 2;
    int tid  = threadIdx.x;
    int warp = tid >> 5, lane = tid & 31;
    int g = lane >> 2, t = lane & 3;
    int hd = blockIdx.y, bb = blockIdx.z;
    unsigned* Pw = Pw0 + warp * (16 * PW_W);

    unsigned ksb = (unsigned)__cvta_generic_to_shared(Ks);
    unsigned vsb = (unsigned)__cvta_generic_to_shared(Vs);

    for (int idx = tid; idx < 256 * 8; idx += 256) {
        int r = idx >> 3, c = (idx & 7) * 8;
        size_t gbase = ((size_t)(r * Bt + bb)) * kld + hd * 64 + c;
        cp16(ksb + (unsigned)(r * KS_W * 4 + c * 2), kb + gbase, true);
        cp16(vsb + (unsigned)(r * VS_H * 2 + c * 2), vb + gbase, true);
    }
    asm volatile("cp.async.commit_group;\n" ::);

    int qrow0 = blockIdx.x * 128 + warp * 16 + g;
    unsigned aq[4][4];
    {
        const __half* q0 = qb + ((size_t)(qrow0 * Bt + bb)) * qld + hd * 64;
        const __half* q1 = qb + ((size_t)((qrow0 + 8) * Bt + bb)) * qld + hd * 64;
#pragma unroll
        for (int kc = 0; kc < 4; kc++) {
            uint2 lo = *(const uint2*)(q0 + kc * 16 + 4 * t);
            uint2 hi = *(const uint2*)(q1 + kc * 16 + 4 * t);
            aq[kc][0] = lo.x; aq[kc][2] = lo.y;
            aq[kc][1] = hi.x; aq[kc][3] = hi.y;
        }
    }

    asm volatile("cp.async.wait_group 0;\n" ::);
    __syncthreads();

    float o[8][4];
#pragma unroll
    for (int ni = 0; ni < 8; ni++)
#pragma unroll
        for (int j = 0; j < 4; j++) o[ni][j] = 0.f;
    float m0 = -1e30f, m1 = -1e30f, l0 = 0.f, l1 = 0.f;

    for (int kt = 0; kt < 4; kt++) {           // 4 key tiles of 64
        float sacc[8][4];
#pragma unroll
        for (int ni = 0; ni < 8; ni++)
#pragma unroll
            for (int j = 0; j < 4; j++) sacc[ni][j] = 0.f;

#pragma unroll
        for (int kc = 0; kc < 4; kc++) {
#pragma unroll
            for (int ni = 0; ni < 8; ni++) {
                int krow = kt * 64 + ni * 8 + g;
                uint2 bv = *(const uint2*)&Ks[krow * KS_W + kc * 8 + 2 * t];
                unsigned bf[2] = { bv.x, bv.y };
                mma_f16(sacc[ni], aq[kc], bf);
            }
        }
#pragma unroll
        for (int ni = 0; ni < 8; ni++)
#pragma unroll
            for (int j = 0; j < 4; j++) sacc[ni][j] *= 0.125f;

        float mx0 = -1e30f, mx1 = -1e30f;
#pragma unroll
        for (int ni = 0; ni < 8; ni++) {
            mx0 = fmaxf(mx0, fmaxf(sacc[ni][0], sacc[ni][1]));
            mx1 = fmaxf(mx1, fmaxf(sacc[ni][2], sacc[ni][3]));
        }
        mx0 = fmaxf(mx0, __shfl_xor_sync(0xffffffffu, mx0, 1));
        mx0 = fmaxf(mx0, __shfl_xor_sync(0xffffffffu, mx0, 2));
        mx1 = fmaxf(mx1, __shfl_xor_sync(0xffffffffu, mx1, 1));
        mx1 = fmaxf(mx1, __shfl_xor_sync(0xffffffffu, mx1, 2));
        float mn0 = fmaxf(m0, mx0), mn1 = fmaxf(m1, mx1);
        float c0 = __expf(m0 - mn0), c1 = __expf(m1 - mn1);
        m0 = mn0; m1 = mn1;

        float rs0 = 0.f, rs1 = 0.f;
#pragma unroll
        for (int ni = 0; ni < 8; ni++) {
            float p00 = __expf(sacc[ni][0] - mn0);
            float p01 = __expf(sacc[ni][1] - mn0);
            float p10 = __expf(sacc[ni][2] - mn1);
            float p11 = __expf(sacc[ni][3] - mn1);
            rs0 += p00 + p01; rs1 += p10 + p11;
            int w = (ni >> 1) * 8 + 2 * t + (ni & 1);   // p16 word slot
            __half2 h0 = __floats2half2_rn(p00, p01);
            __half2 h1 = __floats2half2_rn(p10, p11);
            Pw[g * PW_W + w]       = *(unsigned*)&h0;
            Pw[(g + 8) * PW_W + w] = *(unsigned*)&h1;
            o[ni][0] *= c0; o[ni][1] *= c0; o[ni][2] *= c1; o[ni][3] *= c1;
        }
        rs0 += __shfl_xor_sync(0xffffffffu, rs0, 1);
        rs0 += __shfl_xor_sync(0xffffffffu, rs0, 2);
        rs1 += __shfl_xor_sync(0xffffffffu, rs1, 1);
        rs1 += __shfl_xor_sync(0xffffffffu, rs1, 2);
        l0 = l0 * c0 + rs0;
        l1 = l1 * c1 + rs1;
        __syncwarp();

#pragma unroll
        for (int ks = 0; ks < 4; ks++) {
            uint2 lo = *(const uint2*)&Pw[g * PW_W + ks * 8 + 2 * t];
            uint2 hi = *(const uint2*)&Pw[(g + 8) * PW_W + ks * 8 + 2 * t];
            unsigned ap[4] = { lo.x, hi.x, lo.y, hi.y };
#pragma unroll
            for (int nb = 0; nb < 4; nb++) {
                int sel = lane >> 3;
                int key = kt * 64 + ks * 16 + (sel & 1) * 8 + (lane & 7);
                int col = nb * 16 + (sel >> 1) * 8;
                unsigned addr = (unsigned)__cvta_generic_to_shared(Vs + key * VS_H + col);
                unsigned r0, r1, r2, r3;
                asm volatile(
                    "ldmatrix.sync.aligned.m8n8.x4.trans.shared.b16 {%0,%1,%2,%3}, [%4];"
                    : "=r"(r0), "=r"(r1), "=r"(r2), "=r"(r3) : "r"(addr));
                unsigned b0[2] = { r0, r1 }, b1[2] = { r2, r3 };
                mma_f16(o[nb * 2],     ap, b0);
                mma_f16(o[nb * 2 + 1], ap, b1);
            }
        }
        __syncwarp();
    }

    // epilogue: LOGICAL fp16 output (feeds the ldmatrix out-projection GEMM)
    float i0 = 1.f / l0, i1 = 1.f / l1;
    __half* o0 = ob + ((size_t)(qrow0 * Bt + bb)) * oldd + hd * 64;
    __half* o1 = ob + ((size_t)((qrow0 + 8) * Bt + bb)) * oldd + hd * 64;
#pragma unroll
    for (int ni = 0; ni < 8; ni++) {
        int c = ni * 8 + 2 * t;
        __half2 h0 = __floats2half2_rn(o[ni][0] * i0, o[ni][1] * i0);
        __half2 h1 = __floats2half2_rn(o[ni][2] * i1, o[ni][3] * i1);
        *(__half2*)&o0[c] = h0;
        *(__half2*)&o1[c] = h1;
    }
}

// ---------------- stats / concat / normalize ----------------
__global__ void concat_stats_kernel(const float* __restrict__ x, float* __restrict__ attn_out)
{
    __shared__ float tile[32][33];
    int bb = blockIdx.z;
    int l0 = blockIdx.x * 32, c0 = blockIdx.y * 32;
    int tx = threadIdx.x, ty = threadIdx.y;   // (32, 8)
#pragma unroll
    for (int j = 0; j < 4; j++) {
        int c = c0 + tx;
        int l = l0 + ty + j * 8;
        int row = l * Bn + bb;
        float v = (c < C1n) ? g_ha[(size_t)row * C1n + c]
                            : g_va[(size_t)row * C2n + (c - C1n)];
        tile[ty + j * 8][tx] = v;
    }
    __syncthreads();
    float lsum = 0.f, lsq = 0.f;
#pragma unroll
    for (int j = 0; j < 4; j++) {
        int c = c0 + ty + j * 8;
        int l = l0 + tx;
        float av = tile[tx][ty + j * 8];
        size_t gi = ((size_t)(bb * Cn + c)) * HWn + l;
        attn_out[gi] = av;
        float r = av + x[gi];
        lsum += r; lsq += r * r;
    }
#pragma unroll
    for (int off = 16; off > 0; off >>= 1) {
        lsum += __shfl_xor_sync(0xffffffffu, lsum, off);
        lsq  += __shfl_xor_sync(0xffffffffu, lsq,  off);
    }
    if (tx == 0) {
        atomicAdd(&g_stats[bb * 2 + 0], (double)lsum);
        atomicAdd(&g_stats[bb * 2 + 1], (double)lsq);
    }
}

__global__ void finalize_stats_kernel()
{
    int b = threadIdx.x;
    if (b < 8) {
        const double N = (double)Cn * HWn;
        double mu  = g_stats[2 * b + 0] / N;
        double var = g_stats[2 * b + 1] / N - mu * mu;
        g_mu[b]   = (float)mu;
        g_rstd[b] = (float)(1.0 / sqrt(var + 1e-5));
    }
}

// float4-vectorized: per-batch 2^21 floats = 2^19 float4s
__global__ void norm_kernel(const float4* __restrict__ attn,
                            const float4* __restrict__ x,
                            float4* __restrict__ out)
{
    int i = blockIdx.x * 256 + threadIdx.x;
    int bb = i >> 19;
    float mu = g_mu[bb], rs = g_rstd[bb];
    float4 a = attn[i], xv = x[i];
    float4 r;
    r.x = (a.x + xv.x - mu) * rs;
    r.y = (a.y + xv.y - mu) * rs;
    r.z = (a.z + xv.z - mu) * rs;
    r.w = (a.w + xv.w - mu) * rs;
    out[i] = r;
}

// ---------------- host launcher ----------------
extern "C" void kernel_launch(void* const* d_in, const int* in_sizes, int n_in,
                              void* d_out, int out_size)
{
    const float* x       = (const float*)d_in[0];
    const float* h_in_w  = (const float*)d_in[1];
    const float* h_in_b  = (const float*)d_in[2];
    const float* h_out_w = (const float*)d_in[3];
    const float* h_out_b = (const float*)d_in[4];
    const float* v_in_w  = (const float*)d_in[5];
    const float* v_in_b  = (const float*)d_in[6];
    const float* v_out_w = (const float*)d_in[7];
    const float* v_out_b = (const float*)d_in[8];
    const float* hfc_w   = (const float*)d_in[9];
    const float* hfc_b   = (const float*)d_in[10];
    const float* vfc_w   = (const float*)d_in[11];
    const float* vfc_b   = (const float*)d_in[12];

    float* out      = (float*)d_out;
    float* out_res  = out;                                   // result   [b,C,h,w]
    float* out_hax  = out + (size_t)NTOK * Cn;               // ha_x     [h,w,b,c]
    float* out_vax  = out + 2 * (size_t)NTOK * Cn;           // va_x     [h,w,b,c]
    float* out_attn = out + 3 * (size_t)NTOK * Cn;           // attn     [b,C,h,w]

    __half *p_qh_in, *p_kv_in, *p_xv_in, *p_qh, *p_kvh, *p_qkvv;
    __half *p_oh, *p_ov, *p_hax16, *p_vax16, *p_wt;
    float *p_ha, *p_va;
    cudaGetSymbolAddress((void**)&p_qh_in, g_qh_in);
    cudaGetSymbolAddress((void**)&p_kv_in, g_kv_in);
    cudaGetSymbolAddress((void**)&p_xv_in, g_xv_in);
    cudaGetSymbolAddress((void**)&p_qh,    g_qh);
    cudaGetSymbolAddress((void**)&p_kvh,   g_kvh);
    cudaGetSymbolAddress((void**)&p_qkvv,  g_qkvv);
    cudaGetSymbolAddress((void**)&p_oh,    g_oh);
    cudaGetSymbolAddress((void**)&p_ov,    g_ov);
    cudaGetSymbolAddress((void**)&p_hax16, g_hax16);
    cudaGetSymbolAddress((void**)&p_vax16, g_vax16);
    cudaGetSymbolAddress((void**)&p_wt,    g_wt);
    cudaGetSymbolAddress((void**)&p_ha,    g_ha);
    cudaGetSymbolAddress((void**)&p_va,    g_va);

    dim3 tb(32, 8);
    cudaFuncSetAttribute(gemm_f16, cudaFuncAttributeMaxDynamicSharedMemorySize, GSMEM);
    cudaFuncSetAttribute(attn_mma, cudaFuncAttributeMaxDynamicSharedMemorySize, ATT_SMEM);

    // idx 0: fused weight conversion (+ stats zero)
    conv_all_kernel<<<(2359296 + 255) / 256, 256>>>(h_in_w, v_in_w, h_out_w, v_out_w, hfc_w, vfc_w);

    // idx 1-2: transposes
    transpose_kernel<<<dim3(128, 16, 8), tb>>>(x, p_xv_in, 1);
    transpose_kernel<<<dim3(128, 16, 8), tb>>>(x, p_qh_in, 0);

    // idx 3: big v projection (profiled launch); out fp16: Q p16 | K p16 | V log
    gemm_f16<<<dim3(12, 256), 256, GSMEM>>>(p_xv_in, p_wt + W_VIN,
        v_in_b, (float*)p_qkvv, 0, NTOK, 1536, 512, 1536, 0, 0b011);

    // idx 4: pool; idx 5-6: remaining input projections
    pool_kernel<<<(Bn * Cn * 256 + 255) / 256, 256>>>(x, p_kv_in);
    gemm_f16<<<dim3(8, 16), 256, GSMEM>>>(p_kv_in, p_wt + W_HIN + 512 * 512,
        h_in_b + 512, (float*)p_kvh, 0, NKV, 1024, 512, 1024, 0, 0b001);  // K p16 | V log
    gemm_f16<<<dim3(4, 256), 256, GSMEM>>>(p_qh_in, p_wt + W_HIN,
        h_in_b, (float*)p_qh, 0, NTOK, 512, 512, 512, 0, 0b1);            // Q p16

    // attention (full fp16; outputs logical fp16)
    attn_mma<<<dim3(32, 8, 8),  256, ATT_SMEM>>>(p_qh, p_kvh, p_kvh + 512,
        p_oh, 8, 512, 1024, 512);
    attn_mma<<<dim3(2, 8, 128), 256, ATT_SMEM>>>(p_qkvv, p_qkvv + 512, p_qkvv + 1024,
        p_ov, 128, 1536, 1536, 512);

    // output projections: fp32 to d_out + logical fp16 copy for fc heads
    gemm_f16<<<dim3(4, 256), 256, GSMEM>>>(p_oh, p_wt + W_HOUT,
        h_out_b, out_hax, p_hax16, NTOK, 512, 512, 512, 0, -2);
    gemm_f16<<<dim3(4, 256), 256, GSMEM>>>(p_ov, p_wt + W_VOUT,
        v_out_b, out_vax, p_vax16, NTOK, 512, 512, 512, 1, -2);

    // fc heads (fp32 out)
    gemm_f16<<<dim3(3, 256), 256, GSMEM>>>(p_hax16, p_wt + W_HFC,
        hfc_b, p_ha, 0, NTOK, C1n, 512, C1n, 0, -2);
    gemm_f16<<<dim3(2, 256), 256, GSMEM>>>(p_vax16, p_wt + W_VFC,
        vfc_b, p_va, 0, NTOK, C2n, 512, C2n, 0, -2);

    // concat + residual stats + layernorm
    concat_stats_kernel<<<dim3(128, 16, 8), tb>>>(x, out_attn);
    finalize_stats_kernel<<<1, 32>>>();
    norm_kernel<<<NTOK * Cn / 4 / 256, 256>>>((const float4*)out_attn,
        (const float4*)x, (float4*)out_res);
}

// round 17
// speedup vs baseline: 3.5272x; 1.0035x over previous
#include <cuda_runtime.h>
#include <cuda_fp16.h>
#include <cstdint>
#include <math.h>

// ---------------- problem constants ----------------
#define Bn    8
#define Cn    512
#define Hn    64
#define Wn    64
#define HWn   4096          // 64*64
#define NTOK  32768         // 4096*8 tokens
#define NKV   2048          // 256*8
#define C1n   358
#define C2n   154

// ---------------- scratch (static device, no allocs) ----------------
// ALL fp16 buffers are in LOGICAL k-order (ldmatrix handles fragment shuffles).
__device__ __align__(16) __half g_qh_in[NTOK * Cn];
__device__ __align__(16) __half g_kv_in[NKV * Cn];
__device__ __align__(16) __half g_xv_in[NTOK * Cn];
__device__ __align__(16) __half g_qh  [NTOK * Cn];
__device__ __align__(16) __half g_kvh [NKV * 2 * Cn];
__device__ __align__(16) __half g_qkvv[(size_t)NTOK * 3 * Cn];
__device__ __align__(16) __half g_oh  [NTOK * Cn];
__device__ __align__(16) __half g_ov  [NTOK * Cn];
__device__ __align__(16) __half g_hax16[NTOK * Cn];
__device__ __align__(16) __half g_vax16[NTOK * Cn];
__device__ __align__(16) __half g_wt [2359296];
__device__ float  g_ha  [(size_t)NTOK * C1n];
__device__ float  g_va  [(size_t)NTOK * C2n];
__device__ double g_stats[16];
__device__ float  g_mu[8];
__device__ float  g_rstd[8];

// weight offsets inside g_wt
#define W_HIN   0
#define W_VIN   786432
#define W_HOUT  1572864
#define W_VOUT  1835008
#define W_HFC   2097152
#define W_VFC   2280448

// ---------------- helpers ----------------
__device__ __forceinline__ void mma_f16(float acc[4], const unsigned a[4], const unsigned b[2]) {
    asm volatile(
        "mma.sync.aligned.m16n8k16.row.col.f32.f16.f16.f32 "
        "{%0,%1,%2,%3}, {%4,%5,%6,%7}, {%8,%9}, {%0,%1,%2,%3};\n"
        : "+f"(acc[0]), "+f"(acc[1]), "+f"(acc[2]), "+f"(acc[3])
        : "r"(a[0]), "r"(a[1]), "r"(a[2]), "r"(a[3]), "r"(b[0]), "r"(b[1]));
}

__device__ __forceinline__ void cp16(unsigned saddr, const void* gptr, bool pred) {
    int sz = pred ? 16 : 0;
    asm volatile("cp.async.cg.shared.global [%0], [%1], 16, %2;\n"
                 :: "r"(saddr), "l"(gptr), "r"(sz));
}

__device__ __forceinline__ void ldm_x4(unsigned addr, unsigned& r0, unsigned& r1,
                                       unsigned& r2, unsigned& r3) {
    asm volatile("ldmatrix.sync.aligned.m8n8.x4.shared.b16 {%0,%1,%2,%3}, [%4];"
                 : "=r"(r0), "=r"(r1), "=r"(r2), "=r"(r3) : "r"(addr));
}

__device__ __forceinline__ unsigned packh2(float a, float b) {
    __half2 h = __floats2half2_rn(a, b);
    return *(unsigned*)&h;
}

// ---------------- fused weight conversion (fp32 -> fp16 logical) + stats zero --
__global__ void conv_all_kernel(
    const float* __restrict__ w0, const float* __restrict__ w1,
    const float* __restrict__ w2, const float* __restrict__ w3,
    const float* __restrict__ w4, const float* __restrict__ w5)
{
    int i = blockIdx.x * 256 + threadIdx.x;
    if (blockIdx.x == 0 && threadIdx.x < 16) g_stats[threadIdx.x] = 0.0;
    if (i >= 2359296) return;
    const float* src;
    int off;
    if      (i < W_VIN)  { src = w0; off = i - W_HIN;  }
    else if (i < W_HOUT) { src = w1; off = i - W_VIN;  }
    else if (i < W_VOUT) { src = w2; off = i - W_HOUT; }
    else if (i < W_HFC)  { src = w3; off = i - W_VOUT; }
    else if (i < W_VFC)  { src = w4; off = i - W_HFC;  }
    else                 { src = w5; off = i - W_VFC;  }
    g_wt[i] = __float2half(src[off]);
}

// ---------------- transpose x(b,c,h,w) -> fp16 token rows [row, C] ------------
__global__ void transpose_kernel(const float* __restrict__ x,
                                 __half* __restrict__ out, int mode)
{
    __shared__ float tile[32][33];
    int bb = blockIdx.z;
    int l0 = blockIdx.x * 32, c0 = blockIdx.y * 32;
    int tx = threadIdx.x, ty = threadIdx.y;   // (32, 8)
#pragma unroll
    for (int j = 0; j < 4; j++) {
        int c = c0 + ty + j * 8;
        tile[ty + j * 8][tx] = x[((size_t)(bb * Cn + c)) * HWn + l0 + tx];
    }
    __syncthreads();
#pragma unroll
    for (int j = 0; j < 4; j++) {
        int l = l0 + ty + j * 8;
        int row;
        if (mode == 0) {
            row = l * Bn + bb;
        } else {
            int xx = l & 63, y = l >> 6;
            int wd = xx & 3, nwi = xx >> 2;
            row = y * 512 + wd * 128 + bb * 16 + nwi;
        }
        out[(size_t)row * Cn + c0 + tx] = __float2half(tile[tx][ty + j * 8]);
    }
}

// ---------------- 4x4 avg pool -> fp16 kv token rows --------------------------
__global__ void pool_kernel(const float* __restrict__ x, __half* __restrict__ out)
{
    int idx = blockIdx.x * 256 + threadIdx.x;
    if (idx >= Bn * Cn * 256) return;
    int px = idx & 15, py = (idx >> 4) & 15, c = (idx >> 8) & 511, bb = idx >> 17;
    const float* base = x + (((size_t)(bb * Cn + c)) * Hn + py * 4) * Wn + px * 4;
    float s = 0.f;
#pragma unroll
    for (int i = 0; i < 4; i++)
#pragma unroll
        for (int j = 0; j < 4; j++) s += base[i * Wn + j];
    out[((size_t)((py * 16 + px) * Bn + bb)) * Cn + c] = __float2half(s * 0.0625f);
}

// ---------------- fp16 tensor-core GEMM, cp.async 2-stage, 128x128 CTA tile ---
// (proven R14 structure: two barriers per k-chunk, stage after compute)
// A, Bm: fp16 LOGICAL k-order, row-major [M,K] / [N,K]. M%128==0, K%64==0.
// 8 warps as 2(m) x 4(n), warp tile 64x32, k-chunk 64 halves.
// Smem rows 72 halves (36 words): ldmatrix phases tile all 32 banks.
// omask: -2 -> fp32 out to Cc (+ optional fp16 logical copy to Ct16);
//        else fp16 logical out to (half*)Cc.
#define RS 72
#define GSMEM (4 * 128 * RS * 2)   // 73728 B
__global__ __launch_bounds__(256, 2) void gemm_f16(
    const __half* __restrict__ A, const __half* __restrict__ Bm,
    const float* __restrict__ bias, float* __restrict__ Cc,
    __half* __restrict__ Ct16,
    int M, int N, int K, int ldc, int mode, int omask)
{
    extern __shared__ __align__(16) __half smh[];
    __half* As[2] = { smh,             smh + 128 * RS };
    __half* Bs[2] = { smh + 2*128*RS,  smh + 3*128*RS };

    int tid  = threadIdx.x;
    int warp = tid >> 5, lane = tid & 31;
    int wm = warp & 1, wn = warp >> 1;        // 2 x 4 warps
    int t = lane & 3;
    int m0 = blockIdx.y * 128, n0 = blockIdx.x * 128;

    float acc[4][4][4];
#pragma unroll
    for (int mi = 0; mi < 4; mi++)
#pragma unroll
        for (int ni = 0; ni < 4; ni++)
#pragma unroll
            for (int j = 0; j < 4; j++) acc[mi][ni][j] = 0.f;

    unsigned sa[2], sb[2];
#pragma unroll
    for (int s = 0; s < 2; s++) {
        sa[s] = (unsigned)__cvta_generic_to_shared(As[s]);
        sb[s] = (unsigned)__cvta_generic_to_shared(Bs[s]);
    }

    // ldmatrix lane addressing: row_in_16 = lane&15, k-offset = (lane>>4)*8
    int lrow = lane & 15, lcol = (lane >> 4) * 8;

#define STAGE(s, k0) do {                                                       \
    _Pragma("unroll")                                                           \
    for (int i = 0; i < 4; i++) {                                               \
        int chunk = i * 256 + tid;                                              \
        int r = chunk >> 3, c8 = (chunk & 7) * 8;                               \
        cp16(sa[s] + (unsigned)((r * RS + c8) * 2),                             \
             A + (size_t)(m0 + r) * K + (k0) + c8, true);                       \
        cp16(sb[s] + (unsigned)((r * RS + c8) * 2),                             \
             Bm + (size_t)(n0 + r) * K + (k0) + c8, (n0 + r) < N);              \
    }                                                                           \
    asm volatile("cp.async.commit_group;\n" ::);                                \
} while (0)

    STAGE(0, 0);
    STAGE(1, 64);

    int s = 0;
    for (int k0 = 0; k0 < K; k0 += 64) {
        if (k0 + 64 < K)
            asm volatile("cp.async.wait_group 1;\n" ::);
        else
            asm volatile("cp.async.wait_group 0;\n" ::);
        __syncthreads();

#pragma unroll
        for (int kk = 0; kk < 64; kk += 16) {
            unsigned af[4][4], bf[4][2];
#pragma unroll
            for (int mi = 0; mi < 4; mi++) {
                int rm = wm * 64 + mi * 16 + lrow;
                unsigned addr = sa[s] + (unsigned)((rm * RS + kk + lcol) * 2);
                ldm_x4(addr, af[mi][0], af[mi][1], af[mi][2], af[mi][3]);
            }
#pragma unroll
            for (int nb = 0; nb < 2; nb++) {
                int rn = wn * 32 + nb * 16 + lrow;
                unsigned addr = sb[s] + (unsigned)((rn * RS + kk + lcol) * 2);
                unsigned r0, r1, r2, r3;
                ldm_x4(addr, r0, r1, r2, r3);
                bf[nb * 2][0]     = r0; bf[nb * 2][1]     = r2;
                bf[nb * 2 + 1][0] = r1; bf[nb * 2 + 1][1] = r3;
            }
#pragma unroll
            for (int mi = 0; mi < 4; mi++)
#pragma unroll
                for (int ni = 0; ni < 4; ni++)
                    mma_f16(acc[mi][ni], af[mi], bf[ni]);
        }
        __syncthreads();

        if (k0 + 128 < K) STAGE(s, k0 + 128);
        s ^= 1;
    }
#undef STAGE

    // epilogue: C row = lane/4 (+8), col = ni*8 + 2t + {0,1}
    int g = lane >> 2;
#pragma unroll
    for (int mi = 0; mi < 4; mi++) {
#pragma unroll
        for (int half = 0; half < 2; half++) {
            int m = m0 + wm * 64 + mi * 16 + g + half * 8;
            int orow;
            if (mode == 0) {
                orow = m;
            } else {
                int nwi = m & 15, bb = (m >> 4) & 7, wd = (m >> 7) & 3, y = m >> 9;
                orow = ((y << 6) + (nwi << 2) + wd) * Bn + bb;
            }
#pragma unroll
            for (int ni = 0; ni < 4; ni++) {
                int n = n0 + wn * 32 + ni * 8 + t * 2;
                if (n < N) {
                    float v0 = acc[mi][ni][half * 2 + 0] + bias[n];
                    float v1 = acc[mi][ni][half * 2 + 1] + bias[n + 1];
                    if (omask == -2) {
                        float* cr = Cc + (size_t)orow * ldc;
                        cr[n] = v0; cr[n + 1] = v1;
                        if (Ct16) {
                            __half2 hv = __floats2half2_rn(v0, v1);
                            *(__half2*)&Ct16[(size_t)orow * ldc + n] = hv;
                        }
                    } else {
                        __half* ch = (__half*)Cc;
                        __half2 hv = __floats2half2_rn(v0, v1);
                        *(__half2*)&ch[(size_t)orow * ldc + n] = hv;
                    }
                }
            }
        }
    }
}

// ---------------- full-fp16 flash attention (mma.sync, register-P) ------------
// CTA: 128 queries x one (head, batch); 8 warps, 16 queries/warp; 256 keys staged.
// Q/K/V all fp16 LOGICAL. K frags via ldmatrix (GEMM-proven B path);
// P stays in registers (C-frag of S == A-frag of P). Output LOGICAL fp16.
#define KS_H 72
#define VS_H 72
#define ATT_SMEM (256 * KS_H * 2 + 256 * VS_H * 2)   // 73728 B

__global__ __launch_bounds__(256, 2) void attn_mma(
    const __half* __restrict__ qb, const __half* __restrict__ kb,
    const __half* __restrict__ vb, __half* __restrict__ ob,
    int Bt, int qld, int kld, int oldd)
{
    extern __shared__ __align__(16) __half smh[];
    __half* Ks = smh;                 // [256][72]
    __half* Vs = smh + 256 * KS_H;    // [256][72]
    int tid  = threadIdx.x;
    int warp = tid >> 5, lane = tid & 31;
    int g = lane >> 2, t = lane & 3;
    int hd = blockIdx.y, bb = blockIdx.z;

    unsigned ksb = (unsigned)__cvta_generic_to_shared(Ks);
    unsigned vsb = (unsigned)__cvta_generic_to_shared(Vs);

    for (int idx = tid; idx < 256 * 8; idx += 256) {
        int r = idx >> 3, c = (idx & 7) * 8;
        size_t gbase = ((size_t)(r * Bt + bb)) * kld + hd * 64 + c;
        cp16(ksb + (unsigned)((r * KS_H + c) * 2), kb + gbase, true);
        cp16(vsb + (unsigned)((r * VS_H + c) * 2), vb + gbase, true);
    }
    asm volatile("cp.async.commit_group;\n" ::);

    // Q fragments from gmem (logical layout)
    int qrow0 = blockIdx.x * 128 + warp * 16 + g;
    unsigned aq[4][4];
    {
        const __half* q0 = qb + ((size_t)(qrow0 * Bt + bb)) * qld + hd * 64;
        const __half* q1 = qb + ((size_t)((qrow0 + 8) * Bt + bb)) * qld + hd * 64;
#pragma unroll
        for (int kc = 0; kc < 4; kc++) {
            aq[kc][0] = *(const unsigned*)(q0 + kc * 16 + 2 * t);
            aq[kc][1] = *(const unsigned*)(q1 + kc * 16 + 2 * t);
            aq[kc][2] = *(const unsigned*)(q0 + kc * 16 + 2 * t + 8);
            aq[kc][3] = *(const unsigned*)(q1 + kc * 16 + 2 * t + 8);
        }
    }

    asm volatile("cp.async.wait_group 0;\n" ::);
    __syncthreads();

    int lrow = lane & 15, lcolk = (lane >> 4) * 8;

    float o[8][4];
#pragma unroll
    for (int ni = 0; ni < 8; ni++)
#pragma unroll
        for (int j = 0; j < 4; j++) o[ni][j] = 0.f;
    float m0 = -1e30f, m1 = -1e30f, l0 = 0.f, l1 = 0.f;

    for (int kt = 0; kt < 4; kt++) {           // 4 key tiles of 64
        float sacc[8][4];
#pragma unroll
        for (int ni = 0; ni < 8; ni++)
#pragma unroll
            for (int j = 0; j < 4; j++) sacc[ni][j] = 0.f;

        // S = Q K^T  (K B-frags via ldmatrix, same mapping as GEMM B path)
#pragma unroll
        for (int kc = 0; kc < 4; kc++) {
#pragma unroll
            for (int kg = 0; kg < 4; kg++) {
                unsigned addr = ksb + (unsigned)(((kt * 64 + kg * 16 + lrow) * KS_H
                                                 + kc * 16 + lcolk) * 2);
                unsigned r0, r1, r2, r3;
                ldm_x4(addr, r0, r1, r2, r3);
                unsigned b0[2] = { r0, r2 };
                unsigned b1[2] = { r1, r3 };
                mma_f16(sacc[2 * kg],     aq[kc], b0);
                mma_f16(sacc[2 * kg + 1], aq[kc], b1);
            }
        }
#pragma unroll
        for (int ni = 0; ni < 8; ni++)
#pragma unroll
            for (int j = 0; j < 4; j++) sacc[ni][j] *= 0.125f;

        // online softmax (rows g, g+8; quad reductions)
        float mx0 = -1e30f, mx1 = -1e30f;
#pragma unroll
        for (int ni = 0; ni < 8; ni++) {
            mx0 = fmaxf(mx0, fmaxf(sacc[ni][0], sacc[ni][1]));
            mx1 = fmaxf(mx1, fmaxf(sacc[ni][2], sacc[ni][3]));
        }
        mx0 = fmaxf(mx0, __shfl_xor_sync(0xffffffffu, mx0, 1));
        mx0 = fmaxf(mx0, __shfl_xor_sync(0xffffffffu, mx0, 2));
        mx1 = fmaxf(mx1, __shfl_xor_sync(0xffffffffu, mx1, 1));
        mx1 = fmaxf(mx1, __shfl_xor_sync(0xffffffffu, mx1, 2));
        float mn0 = fmaxf(m0, mx0), mn1 = fmaxf(m1, mx1);
        float c0 = __expf(m0 - mn0), c1 = __expf(m1 - mn1);
        m0 = mn0; m1 = mn1;

        float rs0 = 0.f, rs1 = 0.f;
#pragma unroll
        for (int ni = 0; ni < 8; ni++) {
            float p00 = __expf(sacc[ni][0] - mn0);
            float p01 = __expf(sacc[ni][1] - mn0);
            float p10 = __expf(sacc[ni][2] - mn1);
            float p11 = __expf(sacc[ni][3] - mn1);
            rs0 += p00 + p01; rs1 += p10 + p11;
            sacc[ni][0] = p00; sacc[ni][1] = p01;
            sacc[ni][2] = p10; sacc[ni][3] = p11;
            o[ni][0] *= c0; o[ni][1] *= c0; o[ni][2] *= c1; o[ni][3] *= c1;
        }
        rs0 += __shfl_xor_sync(0xffffffffu, rs0, 1);
        rs0 += __shfl_xor_sync(0xffffffffu, rs0, 2);
        rs1 += __shfl_xor_sync(0xffffffffu, rs1, 1);
        rs1 += __shfl_xor_sync(0xffffffffu, rs1, 2);
        l0 = l0 * c0 + rs0;
        l1 = l1 * c1 + rs1;

        // O += P V : P packed straight from the S accumulator (no smem)
#pragma unroll
        for (int ks = 0; ks < 4; ks++) {       // 16-key chunks
            unsigned ap[4];
            ap[0] = packh2(sacc[2 * ks][0],     sacc[2 * ks][1]);      // row g,  keys 2t,2t+1
            ap[1] = packh2(sacc[2 * ks][2],     sacc[2 * ks][3]);      // row g+8
            ap[2] = packh2(sacc[2 * ks + 1][0], sacc[2 * ks + 1][1]);  // row g,  keys +8
            ap[3] = packh2(sacc[2 * ks + 1][2], sacc[2 * ks + 1][3]);  // row g+8
#pragma unroll
            for (int nb = 0; nb < 4; nb++) {   // 16-dim chunks
                int sel = lane >> 3;
                int key = kt * 64 + ks * 16 + (sel & 1) * 8 + (lane & 7);
                int col = nb * 16 + (sel >> 1) * 8;
                unsigned addr = (unsigned)__cvta_generic_to_shared(Vs + key * VS_H + col);
                unsigned r0, r1, r2, r3;
                asm volatile(
                    "ldmatrix.sync.aligned.m8n8.x4.trans.shared.b16 {%0,%1,%2,%3}, [%4];"
                    : "=r"(r0), "=r"(r1), "=r"(r2), "=r"(r3) : "r"(addr));
                unsigned b0[2] = { r0, r1 }, b1[2] = { r2, r3 };
                mma_f16(o[nb * 2],     ap, b0);
                mma_f16(o[nb * 2 + 1], ap, b1);
            }
        }
    }

    // epilogue: LOGICAL fp16 output (feeds the ldmatrix out-projection GEMM)
    float i0 = 1.f / l0, i1 = 1.f / l1;
    __half* o0 = ob + ((size_t)(qrow0 * Bt + bb)) * oldd + hd * 64;
    __half* o1 = ob + ((size_t)((qrow0 + 8) * Bt + bb)) * oldd + hd * 64;
#pragma unroll
    for (int ni = 0; ni < 8; ni++) {
        int c = ni * 8 + 2 * t;
        __half2 h0 = __floats2half2_rn(o[ni][0] * i0, o[ni][1] * i0);
        __half2 h1 = __floats2half2_rn(o[ni][2] * i1, o[ni][3] * i1);
        *(__half2*)&o0[c] = h0;
        *(__half2*)&o1[c] = h1;
    }
}

// ---------------- stats / concat / normalize ----------------
__global__ void concat_stats_kernel(const float* __restrict__ x, float* __restrict__ attn_out)
{
    __shared__ float tile[32][33];
    int bb = blockIdx.z;
    int l0 = blockIdx.x * 32, c0 = blockIdx.y * 32;
    int tx = threadIdx.x, ty = threadIdx.y;   // (32, 8)
#pragma unroll
    for (int j = 0; j < 4; j++) {
        int c = c0 + tx;
        int l = l0 + ty + j * 8;
        int row = l * Bn + bb;
        float v = (c < C1n) ? g_ha[(size_t)row * C1n + c]
                            : g_va[(size_t)row * C2n + (c - C1n)];
        tile[ty + j * 8][tx] = v;
    }
    __syncthreads();
    float lsum = 0.f, lsq = 0.f;
#pragma unroll
    for (int j = 0; j < 4; j++) {
        int c = c0 + ty + j * 8;
        int l = l0 + tx;
        float av = tile[tx][ty + j * 8];
        size_t gi = ((size_t)(bb * Cn + c)) * HWn + l;
        attn_out[gi] = av;
        float r = av + x[gi];
        lsum += r; lsq += r * r;
    }
#pragma unroll
    for (int off = 16; off > 0; off >>= 1) {
        lsum += __shfl_xor_sync(0xffffffffu, lsum, off);
        lsq  += __shfl_xor_sync(0xffffffffu, lsq,  off);
    }
    if (tx == 0) {
        atomicAdd(&g_stats[bb * 2 + 0], (double)lsum);
        atomicAdd(&g_stats[bb * 2 + 1], (double)lsq);
    }
}

__global__ void finalize_stats_kernel()
{
    int b = threadIdx.x;
    if (b < 8) {
        const double N = (double)Cn * HWn;
        double mu  = g_stats[2 * b + 0] / N;
        double var = g_stats[2 * b + 1] / N - mu * mu;
        g_mu[b]   = (float)mu;
        g_rstd[b] = (float)(1.0 / sqrt(var + 1e-5));
    }
}

// float4-vectorized: per-batch 2^21 floats = 2^19 float4s
__global__ void norm_kernel(const float4* __restrict__ attn,
                            const float4* __restrict__ x,
                            float4* __restrict__ out)
{
    int i = blockIdx.x * 256 + threadIdx.x;
    int bb = i >> 19;
    float mu = g_mu[bb], rs = g_rstd[bb];
    float4 a = attn[i], xv = x[i];
    float4 r;
    r.x = (a.x + xv.x - mu) * rs;
    r.y = (a.y + xv.y - mu) * rs;
    r.z = (a.z + xv.z - mu) * rs;
    r.w = (a.w + xv.w - mu) * rs;
    out[i] = r;
}

// ---------------- host launcher ----------------
extern "C" void kernel_launch(void* const* d_in, const int* in_sizes, int n_in,
                              void* d_out, int out_size)
{
    const float* x       = (const float*)d_in[0];
    const float* h_in_w  = (const float*)d_in[1];
    const float* h_in_b  = (const float*)d_in[2];
    const float* h_out_w = (const float*)d_in[3];
    const float* h_out_b = (const float*)d_in[4];
    const float* v_in_w  = (const float*)d_in[5];
    const float* v_in_b  = (const float*)d_in[6];
    const float* v_out_w = (const float*)d_in[7];
    const float* v_out_b = (const float*)d_in[8];
    const float* hfc_w   = (const float*)d_in[9];
    const float* hfc_b   = (const float*)d_in[10];
    const float* vfc_w   = (const float*)d_in[11];
    const float* vfc_b   = (const float*)d_in[12];

    float* out      = (float*)d_out;
    float* out_res  = out;                                   // result   [b,C,h,w]
    float* out_hax  = out + (size_t)NTOK * Cn;               // ha_x     [h,w,b,c]
    float* out_vax  = out + 2 * (size_t)NTOK * Cn;           // va_x     [h,w,b,c]
    float* out_attn = out + 3 * (size_t)NTOK * Cn;           // attn     [b,C,h,w]

    __half *p_qh_in, *p_kv_in, *p_xv_in, *p_qh, *p_kvh, *p_qkvv;
    __half *p_oh, *p_ov, *p_hax16, *p_vax16, *p_wt;
    float *p_ha, *p_va;
    cudaGetSymbolAddress((void**)&p_qh_in, g_qh_in);
    cudaGetSymbolAddress((void**)&p_kv_in, g_kv_in);
    cudaGetSymbolAddress((void**)&p_xv_in, g_xv_in);
    cudaGetSymbolAddress((void**)&p_qh,    g_qh);
    cudaGetSymbolAddress((void**)&p_kvh,   g_kvh);
    cudaGetSymbolAddress((void**)&p_qkvv,  g_qkvv);
    cudaGetSymbolAddress((void**)&p_oh,    g_oh);
    cudaGetSymbolAddress((void**)&p_ov,    g_ov);
    cudaGetSymbolAddress((void**)&p_hax16, g_hax16);
    cudaGetSymbolAddress((void**)&p_vax16, g_vax16);
    cudaGetSymbolAddress((void**)&p_wt,    g_wt);
    cudaGetSymbolAddress((void**)&p_ha,    g_ha);
    cudaGetSymbolAddress((void**)&p_va,    g_va);

    dim3 tb(32, 8);
    cudaFuncSetAttribute(gemm_f16, cudaFuncAttributeMaxDynamicSharedMemorySize, GSMEM);
    cudaFuncSetAttribute(attn_mma, cudaFuncAttributeMaxDynamicSharedMemorySize, ATT_SMEM);

    // idx 0: fused weight conversion (+ stats zero)
    conv_all_kernel<<<(2359296 + 255) / 256, 256>>>(h_in_w, v_in_w, h_out_w, v_out_w, hfc_w, vfc_w);

    // idx 1-2: transposes
    transpose_kernel<<<dim3(128, 16, 8), tb>>>(x, p_xv_in, 1);
    transpose_kernel<<<dim3(128, 16, 8), tb>>>(x, p_qh_in, 0);

    // idx 3: big v projection (profiled launch); fp16 logical out
    gemm_f16<<<dim3(12, 256), 256, GSMEM>>>(p_xv_in, p_wt + W_VIN,
        v_in_b, (float*)p_qkvv, 0, NTOK, 1536, 512, 1536, 0, -1);

    // idx 4: pool; idx 5-6: remaining input projections
    pool_kernel<<<(Bn * Cn * 256 + 255) / 256, 256>>>(x, p_kv_in);
    gemm_f16<<<dim3(8, 16), 256, GSMEM>>>(p_kv_in, p_wt + W_HIN + 512 * 512,
        h_in_b + 512, (float*)p_kvh, 0, NKV, 1024, 512, 1024, 0, -1);
    gemm_f16<<<dim3(4, 256), 256, GSMEM>>>(p_qh_in, p_wt + W_HIN,
        h_in_b, (float*)p_qh, 0, NTOK, 512, 512, 512, 0, -1);

    // attention (full fp16, register-P; outputs logical fp16)
    attn_mma<<<dim3(32, 8, 8),  256, ATT_SMEM>>>(p_qh, p_kvh, p_kvh + 512,
        p_oh, 8, 512, 1024, 512);
    attn_mma<<<dim3(2, 8, 128), 256, ATT_SMEM>>>(p_qkvv, p_qkvv + 512, p_qkvv + 1024,
        p_ov, 128, 1536, 1536, 512);

    // output projections: fp32 to d_out + logical fp16 copy for fc heads
    gemm_f16<<<dim3(4, 256), 256, GSMEM>>>(p_oh, p_wt + W_HOUT,
        h_out_b, out_hax, p_hax16, NTOK, 512, 512, 512, 0, -2);
    gemm_f16<<<dim3(4, 256), 256, GSMEM>>>(p_ov, p_wt + W_VOUT,
        v_out_b, out_vax, p_vax16, NTOK, 512, 512, 512, 1, -2);

    // fc heads (fp32 out)
    gemm_f16<<<dim3(3, 256), 256, GSMEM>>>(p_hax16, p_wt + W_HFC,
        hfc_b, p_ha, 0, NTOK, C1n, 512, C1n, 0, -2);
    gemm_f16<<<dim3(2, 256), 256, GSMEM>>>(p_vax16, p_wt + W_VFC,
        vfc_b, p_va, 0, NTOK, C2n, 512, C2n, 0, -2);

    // concat + residual stats + layernorm
    concat_stats_kernel<<<dim3(128, 16, 8), tb>>>(x, out_attn);
    finalize_stats_kernel<<<1, 32>>>();
    norm_kernel<<<NTOK * Cn / 4 / 256, 256>>>((const float4*)out_attn,
        (const float4*)x, (float4*)out_res);
}